// round 1
// baseline (speedup 1.0000x reference)
#include <cuda_runtime.h>
#include <math.h>
#include <stdint.h>

#define CIN 64
#define NGRP 100
#define HID 256
#define BB 4
#define HH 112
#define H2 224
#define QQ 50176
#define MTOT (BB*QQ)   // 200704

// ---------------- scratch (device globals; no allocation allowed) -------------
__device__ float g_h[(size_t)BB*CIN*HH*HH];          // 12.8 MB
__device__ float g_logits[(size_t)BB*NGRP*HH*HH];    // 20 MB
__device__ float g_wstat[49*4];
__device__ float g_ktw[49*196];
__device__ float g_gfeat[(size_t)BB*CIN*H2*H2];      // 51 MB  (NCHW)
__device__ float g_coef[(size_t)BB*H2*H2*HID];       // 205 MB (NHWC)
__device__ float g_freq[(size_t)BB*H2*H2*HID];       // 205 MB (NHWC)
__device__ float g_X0[(size_t)MTOT*HID];             // 205 MB
__device__ float g_X1[(size_t)MTOT*HID];             // 205 MB

// ---------------- conv3x3 64->64 @112, relu, NCHW out ------------------------
#define CONV_SMEM ((64*18*18 + 16*64*12)*4)

__global__ void conv112_relu(const float* __restrict__ in,
                             const float* __restrict__ w,
                             const float* __restrict__ bias) {
    extern __shared__ float sm[];
    float* ins = sm;               // 64*18*18
    float* ws  = sm + 64*18*18;    // 16*64*12
    int tile = blockIdx.x;         // 49 tiles of 16x16
    int co0  = blockIdx.y * 16;
    int b    = blockIdx.z;
    int ty0 = (tile / 7) * 16, tx0 = (tile % 7) * 16;
    int tid = threadIdx.x;

    const float* inb = in + (size_t)b * CIN * HH * HH;
    for (int i = tid; i < 64*18*18; i += 256) {
        int ci = i / 324; int r = (i % 324) / 18; int c = i % 18;
        int gy = ty0 + r - 1, gx = tx0 + c - 1;
        float v = 0.f;
        if (gy >= 0 && gy < HH && gx >= 0 && gx < HH) v = inb[(ci*HH + gy)*HH + gx];
        ins[i] = v;
    }
    for (int i = tid; i < 16*64*9; i += 256) {
        int co = i / 576; int rem = i % 576; int ci = rem / 9; int k = rem % 9;
        ws[(co*64 + ci)*12 + k] = w[(size_t)(co0 + co)*576 + rem];
    }
    __syncthreads();

    int ty = tid / 16, tx = tid % 16;
    float acc[16];
    #pragma unroll
    for (int co = 0; co < 16; co++) acc[co] = bias[co0 + co];

    for (int ci = 0; ci < 64; ci++) {
        float v[9];
        const float* ip = ins + ci*324 + ty*18 + tx;
        #pragma unroll
        for (int dy = 0; dy < 3; dy++)
            #pragma unroll
            for (int dx = 0; dx < 3; dx++)
                v[dy*3+dx] = ip[dy*18 + dx];
        const float* wp = ws + ci*12;
        #pragma unroll
        for (int co = 0; co < 16; co++) {
            const float* wc = wp + co*64*12;
            float4 w0 = *(const float4*)(wc);
            float4 w1 = *(const float4*)(wc + 4);
            float  w8 = wc[8];
            acc[co] += v[0]*w0.x + v[1]*w0.y + v[2]*w0.z + v[3]*w0.w
                     + v[4]*w1.x + v[5]*w1.y + v[6]*w1.z + v[7]*w1.w + v[8]*w8;
        }
    }
    int oy = ty0 + ty, ox = tx0 + tx;
    #pragma unroll
    for (int co = 0; co < 16; co++)
        g_h[(((size_t)b*64 + co0 + co)*HH + oy)*HH + ox] = fmaxf(acc[co], 0.f);
}

// ---------------- 1x1 conv 64->100 -------------------------------------------
__global__ void conv1x1_logits(const float* __restrict__ w2,
                               const float* __restrict__ b2) {
    __shared__ float ws[NGRP*64];
    int tid = threadIdx.x;
    for (int i = tid; i < NGRP*64; i += 256) ws[i] = w2[i];
    __syncthreads();
    int t = blockIdx.x * 256 + tid;         // 0..50175
    int b = t / (HH*HH); int pix = t % (HH*HH);
    const float* hp = g_h + (size_t)b*64*HH*HH + pix;
    float hv[64];
    #pragma unroll
    for (int ci = 0; ci < 64; ci++) hv[ci] = hp[(size_t)ci*HH*HH];
    float* lp = g_logits + (size_t)b*NGRP*HH*HH + pix;
    for (int g = 0; g < NGRP; g++) {
        float acc = b2[g];
        const float* wg = ws + g*64;
        #pragma unroll
        for (int ci = 0; ci < 64; ci += 4) {
            float4 wv = *(const float4*)(wg + ci);
            acc += hv[ci]*wv.x + hv[ci+1]*wv.y + hv[ci+2]*wv.z + hv[ci+3]*wv.w;
        }
        lp[(size_t)g*HH*HH] = acc;
    }
}

// ---------------- softmax + weighted stats ------------------------------------
__global__ void zero_stats() {
    int t = threadIdx.x;
    if (t < 196) g_wstat[t] = 0.f;
}

__global__ void softmax_stats(const float* __restrict__ sx, const float* __restrict__ sy,
                              const float* __restrict__ op, const float* __restrict__ rh) {
    __shared__ float sv[4*NGRP];
    __shared__ float accs[196];
    int tid = threadIdx.x;
    for (int i = tid; i < NGRP; i += 256) {
        sv[i] = sx[i]; sv[NGRP+i] = sy[i]; sv[2*NGRP+i] = op[i]; sv[3*NGRP+i] = rh[i];
    }
    for (int i = tid; i < 196; i += 256) accs[i] = 0.f;
    __syncthreads();
    int t = blockIdx.x * 256 + tid;
    int b = t / (HH*HH); int pix = t % (HH*HH);
    int y = pix / HH, x = pix % HH;
    const float* lp = g_logits + (size_t)b*NGRP*HH*HH + pix;
    float mx = -1e30f;
    for (int g = 0; g < NGRP; g++) mx = fmaxf(mx, lp[(size_t)g*HH*HH]);
    float s = 0.f, a0 = 0.f, a1 = 0.f, a2 = 0.f, a3 = 0.f;
    for (int g = 0; g < NGRP; g++) {
        float e = expf(lp[(size_t)g*HH*HH] - mx);
        s += e; a0 += e*sv[g]; a1 += e*sv[NGRP+g]; a2 += e*sv[2*NGRP+g]; a3 += e*sv[3*NGRP+g];
    }
    float inv = 1.f / s;
    int p = (y % 7)*7 + (x % 7);
    atomicAdd(&accs[p*4+0], a0*inv);
    atomicAdd(&accs[p*4+1], a1*inv);
    atomicAdd(&accs[p*4+2], a2*inv);
    atomicAdd(&accs[p*4+3], a3*inv);
    __syncthreads();
    for (int i = tid; i < 196; i += 256) atomicAdd(&g_wstat[i], accs[i]);
}

// ---------------- build translated gaussian kernels (x opacity) ---------------
__global__ void build_ktw() {
    __shared__ float kpad[49*196];
    __shared__ float wops[49];
    int tid = threadIdx.x;
    for (int i = tid; i < 49*196; i += 256) kpad[i] = 0.f;
    __syncthreads();
    if (tid < 49) {
        int p = tid;
        const float inv1024 = 1.f/1024.f;
        float wsx = g_wstat[p*4+0]*inv1024;
        float wsy = g_wstat[p*4+1]*inv1024;
        float wop = g_wstat[p*4+2]*inv1024;
        float wr  = g_wstat[p*4+3]*inv1024;
        wops[p] = wop;
        float c00 = wsx*wsx + 1e-5f;
        float c11 = wsy*wsy + 1e-5f;
        float c01 = wr*wsx*wsy;
        float det = c00*c11 - c01*c01;
        float i00 = c11/det, i11 = c00/det, i01 = -c01/det;
        float norm = 1.f/(2.f*3.14159265358979f*sqrtf(det));
        float kv[25]; float mx = 0.f;
        #pragma unroll
        for (int i = 0; i < 5; i++)
            #pragma unroll
            for (int j = 0; j < 5; j++) {
                float yv = -5.f + 2.5f*i;
                float xv = -5.f + 2.5f*j;
                float z = -0.5f*(i00*xv*xv + 2.f*i01*xv*yv + i11*yv*yv);
                float k = expf(z)*norm;
                kv[i*5+j] = k; mx = fmaxf(mx, k);
            }
        float im = 1.f/mx;
        #pragma unroll
        for (int i = 0; i < 5; i++)
            #pragma unroll
            for (int j = 0; j < 5; j++)
                kpad[p*196 + (i+4)*14 + (j+4)] = kv[i*5+j]*im;
    }
    __syncthreads();
    for (int idx = tid; idx < 49*196; idx += 256) {
        int p = idx/196, hw = idx%196, h = hw/14, w = hw%14;
        float txo = (0.5f - (float)(p/7)*(1.f/7.f))*2.f;
        float tyo = (0.5f - (float)(p%7)*(1.f/7.f))*2.f;
        float gxv = -1.f + (2.f/13.f)*w + txo;
        float gyv = -1.f + (2.f/13.f)*h + tyo;
        float px = (gxv + 1.f)*0.5f*13.f;
        float py = (gyv + 1.f)*0.5f*13.f;
        float x0f = floorf(px), y0f = floorf(py);
        int x0 = (int)x0f, y0 = (int)y0f;
        float wx = px - x0f, wy = py - y0f;
        float s00 = (y0   >= 0 && y0   < 14 && x0   >= 0 && x0   < 14) ? kpad[p*196 + y0*14 + x0]       : 0.f;
        float s01 = (y0   >= 0 && y0   < 14 && x0+1 >= 0 && x0+1 < 14) ? kpad[p*196 + y0*14 + x0+1]     : 0.f;
        float s10 = (y0+1 >= 0 && y0+1 < 14 && x0   >= 0 && x0   < 14) ? kpad[p*196 + (y0+1)*14 + x0]   : 0.f;
        float s11 = (y0+1 >= 0 && y0+1 < 14 && x0+1 >= 0 && x0+1 < 14) ? kpad[p*196 + (y0+1)*14 + x0+1] : 0.f;
        float kt = s00*(1.f-wy)*(1.f-wx) + s01*(1.f-wy)*wx + s10*wy*(1.f-wx) + s11*wy*wx;
        g_ktw[idx] = kt * wops[p];
    }
}

// ---------------- splat: feat patches -> gfeat (B,64,224,224) -----------------
#define SPLAT_SMEM ((49*196 + 64*49)*4)
__global__ void splat(const float* __restrict__ feat) {
    extern __shared__ float sm[];
    float* kts = sm;             // 9604
    float* fp  = sm + 49*196;    // 3136
    int bl = blockIdx.x;         // 0..1023
    int b = bl / 256; int l = bl % 256; int pr = l / 16, pc = l % 16;
    int tid = threadIdx.x;       // 196
    for (int i = tid; i < 49*196; i += 196) kts[i] = g_ktw[i];
    const float* fb = feat + (size_t)b*64*HH*HH;
    for (int i = tid; i < 64*49; i += 196) {
        int c = i/49, p = i%49;
        fp[i] = fb[((size_t)c*HH + pr*7 + p/7)*HH + pc*7 + p%7];
    }
    __syncthreads();
    int h = tid/14, w = tid%14;
    int oy = pr*14 + h, ox = pc*14 + w;
    float* outb = g_gfeat + (size_t)b*64*H2*H2;
    for (int c0 = 0; c0 < 64; c0 += 4) {
        float a0 = 0.f, a1 = 0.f, a2 = 0.f, a3 = 0.f;
        #pragma unroll
        for (int p = 0; p < 49; p++) {
            float kv = kts[p*196 + tid];
            a0 += fp[(c0+0)*49 + p]*kv;
            a1 += fp[(c0+1)*49 + p]*kv;
            a2 += fp[(c0+2)*49 + p]*kv;
            a3 += fp[(c0+3)*49 + p]*kv;
        }
        outb[((size_t)(c0+0)*H2 + oy)*H2 + ox] = __saturatef(a0);
        outb[((size_t)(c0+1)*H2 + oy)*H2 + ox] = __saturatef(a1);
        outb[((size_t)(c0+2)*H2 + oy)*H2 + ox] = __saturatef(a2);
        outb[((size_t)(c0+3)*H2 + oy)*H2 + ox] = __saturatef(a3);
    }
}

// ---------------- conv3x3 64->256 @224, NHWC out ------------------------------
__global__ void conv224(const float* __restrict__ w,
                        const float* __restrict__ bias, int sel) {
    extern __shared__ float sm[];
    float* ins = sm;
    float* ws  = sm + 64*18*18;
    int tile = blockIdx.x;       // 196 tiles of 16x16
    int co0  = blockIdx.y * 16;  // 16 groups
    int b    = blockIdx.z;
    int ty0 = (tile / 14) * 16, tx0 = (tile % 14) * 16;
    int tid = threadIdx.x;

    const float* inb = g_gfeat + (size_t)b*64*H2*H2;
    for (int i = tid; i < 64*18*18; i += 256) {
        int ci = i / 324; int r = (i % 324) / 18; int c = i % 18;
        int gy = ty0 + r - 1, gx = tx0 + c - 1;
        float v = 0.f;
        if (gy >= 0 && gy < H2 && gx >= 0 && gx < H2) v = inb[((size_t)ci*H2 + gy)*H2 + gx];
        ins[i] = v;
    }
    for (int i = tid; i < 16*64*9; i += 256) {
        int co = i / 576; int rem = i % 576; int ci = rem / 9; int k = rem % 9;
        ws[(co*64 + ci)*12 + k] = w[(size_t)(co0 + co)*576 + rem];
    }
    __syncthreads();

    int ty = tid/16, tx = tid%16;
    float acc[16];
    #pragma unroll
    for (int co = 0; co < 16; co++) acc[co] = bias[co0 + co];

    for (int ci = 0; ci < 64; ci++) {
        float v[9];
        const float* ip = ins + ci*324 + ty*18 + tx;
        #pragma unroll
        for (int dy = 0; dy < 3; dy++)
            #pragma unroll
            for (int dx = 0; dx < 3; dx++)
                v[dy*3+dx] = ip[dy*18 + dx];
        const float* wp = ws + ci*12;
        #pragma unroll
        for (int co = 0; co < 16; co++) {
            const float* wc = wp + co*64*12;
            float4 w0 = *(const float4*)(wc);
            float4 w1 = *(const float4*)(wc + 4);
            float  w8 = wc[8];
            acc[co] += v[0]*w0.x + v[1]*w0.y + v[2]*w0.z + v[3]*w0.w
                     + v[4]*w1.x + v[5]*w1.y + v[6]*w1.z + v[7]*w1.w + v[8]*w8;
        }
    }
    float* outp = sel ? g_freq : g_coef;
    int oy = ty0 + ty, ox = tx0 + tx;
    float* orow = outp + (((size_t)b*H2 + oy)*H2 + ox)*HID + co0;
    #pragma unroll
    for (int q = 0; q < 4; q++) {
        float4 o;
        o.x = acc[q*4+0]; o.y = acc[q*4+1]; o.z = acc[q*4+2]; o.w = acc[q*4+3];
        *(float4*)(orow + q*4) = o;
    }
}

// ---------------- gather + fourier basis -> X0 --------------------------------
__global__ void gather_basis(const float* __restrict__ coord,
                             const float* __restrict__ cell,
                             const float* __restrict__ phase_w) {
    int warp = threadIdx.x / 32, lane = threadIdx.x % 32;
    int m = blockIdx.x * 8 + warp;               // 0..200703
    int b = m / QQ; int q = m % QQ;
    float cy = coord[((size_t)b*QQ + q)*2 + 0];
    float cx = coord[((size_t)b*QQ + q)*2 + 1];
    int ix = (int)rintf(((cx + 1.f)*(float)H2 - 1.f)*0.5f);
    int iy = (int)rintf(((cy + 1.f)*(float)H2 - 1.f)*0.5f);
    bool ok = (ix >= 0 && ix < H2 && iy >= 0 && iy < H2);
    float* xr = g_X0 + (size_t)m*HID;
    if (!ok) {
        #pragma unroll
        for (int kk = 0; kk < 4; kk++) {
            int k = lane + kk*32;
            xr[k] = 0.f; xr[128 + k] = 0.f;
        }
        return;
    }
    float fcy = -1.f + 1.f/(float)H2 + (2.f/(float)H2)*(float)iy;
    float fcx = -1.f + 1.f/(float)H2 + (2.f/(float)H2)*(float)ix;
    float rely = (cy - fcy)*(float)H2;
    float relx = (cx - fcx)*(float)H2;
    float rc0 = cell[((size_t)b*QQ + q)*2 + 0]*(float)H2;
    float rc1 = cell[((size_t)b*QQ + q)*2 + 1]*(float)H2;
    size_t base = (((size_t)b*H2 + iy)*H2 + ix)*HID;
    const float*  cf = g_coef + base;
    const float2* fq = (const float2*)(g_freq + base);
    const float2* pw = (const float2*)phase_w;
    #pragma unroll
    for (int kk = 0; kk < 4; kk++) {
        int k = lane + kk*32;
        float2 f = fq[k];
        float2 p = pw[k];
        float s = f.x*rely + f.y*relx + rc0*p.x + rc1*p.y;
        xr[k]       = cf[k]       * cospif(s);
        xr[128 + k] = cf[128 + k] * sinpif(s);
    }
}

// ---------------- GEMM (M x 256) @ W^T (256 x 256) + bias + relu --------------
// layer 0: A=g_X0 -> C=g_X1 ;  layer 1: A=g_X1 -> C=g_X0
__global__ void gemm_relu(const float* __restrict__ Wt,
                          const float* __restrict__ bias, int layer) {
    __shared__ float a_s[16][64];
    __shared__ float b_s[16][64];
    const float* A = layer ? g_X1 : g_X0;
    float*       C = layer ? g_X0 : g_X1;
    int m0 = blockIdx.x * 64;
    int n0 = blockIdx.y * 64;
    int tid = threadIdx.x;
    int r0 = (tid/16)*4;
    int c0 = (tid%16)*4;
    int lr = tid/4;
    int lc = (tid%4)*4;
    float acc[4][4] = {};
    for (int k0 = 0; k0 < 256; k0 += 16) {
        float4 av = *(const float4*)&A [((size_t)(m0 + lr))*256 + k0 + lc];
        float4 bv = *(const float4*)&Wt[((size_t)(n0 + lr))*256 + k0 + lc];
        __syncthreads();
        a_s[lc+0][lr] = av.x; a_s[lc+1][lr] = av.y; a_s[lc+2][lr] = av.z; a_s[lc+3][lr] = av.w;
        b_s[lc+0][lr] = bv.x; b_s[lc+1][lr] = bv.y; b_s[lc+2][lr] = bv.z; b_s[lc+3][lr] = bv.w;
        __syncthreads();
        #pragma unroll
        for (int kk = 0; kk < 16; kk++) {
            float a[4];
            #pragma unroll
            for (int i = 0; i < 4; i++) a[i] = a_s[kk][r0 + i];
            float4 b4 = *(const float4*)&b_s[kk][c0];
            #pragma unroll
            for (int i = 0; i < 4; i++) {
                acc[i][0] += a[i]*b4.x; acc[i][1] += a[i]*b4.y;
                acc[i][2] += a[i]*b4.z; acc[i][3] += a[i]*b4.w;
            }
        }
    }
    float4 bb = *(const float4*)&bias[n0 + c0];
    #pragma unroll
    for (int i = 0; i < 4; i++) {
        float4 o;
        o.x = fmaxf(acc[i][0] + bb.x, 0.f);
        o.y = fmaxf(acc[i][1] + bb.y, 0.f);
        o.z = fmaxf(acc[i][2] + bb.z, 0.f);
        o.w = fmaxf(acc[i][3] + bb.w, 0.f);
        *(float4*)&C[((size_t)(m0 + r0 + i))*256 + n0 + c0] = o;
    }
}

// ---------------- final 256 -> 3 ----------------------------------------------
__global__ void final_layer(const float* __restrict__ w3,
                            const float* __restrict__ b3,
                            float* __restrict__ out) {
    __shared__ float w3s[3*256];
    int tid = threadIdx.x;
    for (int i = tid; i < 768; i += 256) w3s[i] = w3[i];
    __syncthreads();
    int warp = tid/32, lane = tid%32;
    int m = blockIdx.x * 8 + warp;
    const float* xr = g_X0 + (size_t)m*256;
    float a0 = 0.f, a1 = 0.f, a2 = 0.f;
    #pragma unroll
    for (int j = 0; j < 8; j++) {
        int k = lane + j*32;
        float v = xr[k];
        a0 += v*w3s[k]; a1 += v*w3s[256 + k]; a2 += v*w3s[512 + k];
    }
    #pragma unroll
    for (int off = 16; off; off >>= 1) {
        a0 += __shfl_down_sync(0xffffffffu, a0, off);
        a1 += __shfl_down_sync(0xffffffffu, a1, off);
        a2 += __shfl_down_sync(0xffffffffu, a2, off);
    }
    if (lane == 0) {
        out[(size_t)m*3 + 0] = a0 + b3[0];
        out[(size_t)m*3 + 1] = a1 + b3[1];
        out[(size_t)m*3 + 2] = a2 + b3[2];
    }
}

// ---------------- launch -------------------------------------------------------
extern "C" void kernel_launch(void* const* d_in, const int* in_sizes, int n_in,
                              void* d_out, int out_size) {
    const float* feat    = (const float*)d_in[0];
    const float* coord   = (const float*)d_in[1];
    const float* cell    = (const float*)d_in[2];
    const float* cls_w1  = (const float*)d_in[3];
    const float* cls_b1  = (const float*)d_in[4];
    const float* cls_w2  = (const float*)d_in[5];
    const float* cls_b2  = (const float*)d_in[6];
    const float* sigma_x = (const float*)d_in[7];
    const float* sigma_y = (const float*)d_in[8];
    const float* opacity = (const float*)d_in[9];
    const float* rho     = (const float*)d_in[10];
    const float* coef_w  = (const float*)d_in[11];
    const float* coef_b  = (const float*)d_in[12];
    const float* freq_w  = (const float*)d_in[13];
    const float* freq_b  = (const float*)d_in[14];
    const float* phase_w = (const float*)d_in[15];
    const float* mlp_w1  = (const float*)d_in[16];
    const float* mlp_b1  = (const float*)d_in[17];
    const float* mlp_w2  = (const float*)d_in[18];
    const float* mlp_b2  = (const float*)d_in[19];
    const float* mlp_w3  = (const float*)d_in[20];
    const float* mlp_b3  = (const float*)d_in[21];
    float* out = (float*)d_out;

    cudaFuncSetAttribute(conv112_relu, cudaFuncAttributeMaxDynamicSharedMemorySize, CONV_SMEM);
    cudaFuncSetAttribute(conv224,      cudaFuncAttributeMaxDynamicSharedMemorySize, CONV_SMEM);
    cudaFuncSetAttribute(splat,        cudaFuncAttributeMaxDynamicSharedMemorySize, SPLAT_SMEM);

    conv112_relu<<<dim3(49, 4, BB), 256, CONV_SMEM>>>(feat, cls_w1, cls_b1);
    conv1x1_logits<<<196, 256>>>(cls_w2, cls_b2);
    zero_stats<<<1, 256>>>();
    softmax_stats<<<196, 256>>>(sigma_x, sigma_y, opacity, rho);
    build_ktw<<<1, 256>>>();
    splat<<<1024, 196, SPLAT_SMEM>>>(feat);
    conv224<<<dim3(196, 16, BB), 256, CONV_SMEM>>>(coef_w, coef_b, 0);
    conv224<<<dim3(196, 16, BB), 256, CONV_SMEM>>>(freq_w, freq_b, 1);
    gather_basis<<<MTOT/8, 256>>>(coord, cell, phase_w);
    gemm_relu<<<dim3(MTOT/64, 4), 256>>>(mlp_w1, mlp_b1, 0);
    gemm_relu<<<dim3(MTOT/64, 4), 256>>>(mlp_w2, mlp_b2, 1);
    final_layer<<<MTOT/8, 256>>>(mlp_w3, mlp_b3, out);
}

// round 2
// speedup vs baseline: 1.4131x; 1.4131x over previous
#include <cuda_runtime.h>
#include <math.h>
#include <stdint.h>

#define CIN 64
#define NGRP 100
#define HID 256
#define BB 4
#define HH 112
#define H2 224
#define QQ 50176
#define MTOT (BB*QQ)   // 200704

typedef unsigned long long ull;

__device__ __forceinline__ ull pk2(float a, float b) {
    ull r; asm("mov.b64 %0,{%1,%2};" : "=l"(r) : "f"(a), "f"(b)); return r;
}
__device__ __forceinline__ void fma2(ull& d, ull a, ull b) {
    asm("fma.rn.f32x2 %0,%1,%2,%0;" : "+l"(d) : "l"(a), "l"(b));
}
__device__ __forceinline__ void upk2(ull v, float& a, float& b) {
    asm("mov.b64 {%0,%1},%2;" : "=f"(a), "=f"(b) : "l"(v));
}

// ---------------- scratch (device globals; no allocation allowed) -------------
__device__ float g_h[(size_t)BB*CIN*HH*HH];          // 12.8 MB
__device__ float g_logits[(size_t)BB*NGRP*HH*HH];    // 20 MB
__device__ float g_wstat[49*4];
__device__ float g_ktw[49*196];
__device__ float g_gfeat[(size_t)BB*CIN*H2*H2];      // 51 MB  (NCHW)
__device__ float g_coef[(size_t)BB*H2*H2*HID];       // 205 MB (NHWC)
__device__ float g_freq[(size_t)BB*H2*H2*HID];       // 205 MB (NHWC)
__device__ float g_X0[(size_t)MTOT*HID];             // 205 MB
__device__ float g_X1[(size_t)MTOT*HID];             // 205 MB

// smem: input tile 64*18*18 floats + packed weights 64*8*10 ull
#define CONVP_SMEM (64*18*18*4 + 64*8*10*8)   // 82944 + 40960 = 123904

// ---------------- conv3x3 64->64 @112, relu, NCHW out (packed f32x2) ----------
__global__ void conv112p(const float* __restrict__ in,
                         const float* __restrict__ w,
                         const float* __restrict__ bias) {
    extern __shared__ float sm[];
    float* ins = sm;                            // 64*18*18
    ull*   wsp = (ull*)(sm + 64*324);           // 64*8*10 packed pairs (stride 10)
    int tile = blockIdx.x;
    int co0  = blockIdx.y * 16;
    int b    = blockIdx.z;
    int ty0 = (tile / 7) * 16, tx0 = (tile % 7) * 16;
    int tid = threadIdx.x;

    const float* inb = in + (size_t)b * CIN * HH * HH;
    for (int i = tid; i < 64*18*18; i += 256) {
        int ci = i / 324; int r = (i % 324) / 18; int c = i % 18;
        int gy = ty0 + r - 1, gx = tx0 + c - 1;
        float v = 0.f;
        if (gy >= 0 && gy < HH && gx >= 0 && gx < HH) v = inb[(ci*HH + gy)*HH + gx];
        ins[i] = v;
    }
    float* wspf = (float*)wsp;
    for (int i = tid; i < 64*8*9*2; i += 256) {
        int half = i & 1; int e = i >> 1;
        int k = e % 9; int cop = (e/9) & 7; int ci = e/72;
        wspf[((ci*8 + cop)*10 + k)*2 + half] = w[(size_t)(co0 + cop*2 + half)*576 + ci*9 + k];
    }
    __syncthreads();

    int ty = tid / 16, tx = tid % 16;
    ull acc[8];
    #pragma unroll
    for (int cop = 0; cop < 8; cop++) acc[cop] = pk2(bias[co0+2*cop], bias[co0+2*cop+1]);

    for (int ci = 0; ci < 64; ci++) {
        const float* ip = ins + ci*324 + ty*18 + tx;
        ull vv[9];
        #pragma unroll
        for (int dy = 0; dy < 3; dy++)
            #pragma unroll
            for (int dx = 0; dx < 3; dx++) {
                float v = ip[dy*18 + dx];
                vv[dy*3+dx] = pk2(v, v);
            }
        const ull* wbase = wsp + ci*80;
        #pragma unroll
        for (int cop = 0; cop < 8; cop++) {
            const ulonglong2* wc2 = (const ulonglong2*)(wbase + cop*10);
            ulonglong2 p0 = wc2[0], p1 = wc2[1], p2 = wc2[2], p3 = wc2[3];
            ull p8 = (wbase + cop*10)[8];
            fma2(acc[cop], vv[0], p0.x); fma2(acc[cop], vv[1], p0.y);
            fma2(acc[cop], vv[2], p1.x); fma2(acc[cop], vv[3], p1.y);
            fma2(acc[cop], vv[4], p2.x); fma2(acc[cop], vv[5], p2.y);
            fma2(acc[cop], vv[6], p3.x); fma2(acc[cop], vv[7], p3.y);
            fma2(acc[cop], vv[8], p8);
        }
    }
    int oy = ty0 + ty, ox = tx0 + tx;
    #pragma unroll
    for (int cop = 0; cop < 8; cop++) {
        float lo, hi; upk2(acc[cop], lo, hi);
        g_h[(((size_t)b*64 + co0 + 2*cop    )*HH + oy)*HH + ox] = fmaxf(lo, 0.f);
        g_h[(((size_t)b*64 + co0 + 2*cop + 1)*HH + oy)*HH + ox] = fmaxf(hi, 0.f);
    }
}

// ---------------- 1x1 conv 64->100 -------------------------------------------
__global__ void conv1x1_logits(const float* __restrict__ w2,
                               const float* __restrict__ b2) {
    __shared__ float ws[NGRP*64];
    int tid = threadIdx.x;
    for (int i = tid; i < NGRP*64; i += 256) ws[i] = w2[i];
    __syncthreads();
    int t = blockIdx.x * 256 + tid;
    int b = t / (HH*HH); int pix = t % (HH*HH);
    const float* hp = g_h + (size_t)b*64*HH*HH + pix;
    float hv[64];
    #pragma unroll
    for (int ci = 0; ci < 64; ci++) hv[ci] = hp[(size_t)ci*HH*HH];
    float* lp = g_logits + (size_t)b*NGRP*HH*HH + pix;
    for (int g = 0; g < NGRP; g++) {
        float acc = b2[g];
        const float* wg = ws + g*64;
        #pragma unroll
        for (int ci = 0; ci < 64; ci += 4) {
            float4 wv = *(const float4*)(wg + ci);
            acc += hv[ci]*wv.x + hv[ci+1]*wv.y + hv[ci+2]*wv.z + hv[ci+3]*wv.w;
        }
        lp[(size_t)g*HH*HH] = acc;
    }
}

// ---------------- softmax + weighted stats ------------------------------------
__global__ void zero_stats() {
    int t = threadIdx.x;
    if (t < 196) g_wstat[t] = 0.f;
}

__global__ void softmax_stats(const float* __restrict__ sx, const float* __restrict__ sy,
                              const float* __restrict__ op, const float* __restrict__ rh) {
    __shared__ float sv[4*NGRP];
    __shared__ float accs[196];
    int tid = threadIdx.x;
    for (int i = tid; i < NGRP; i += 256) {
        sv[i] = sx[i]; sv[NGRP+i] = sy[i]; sv[2*NGRP+i] = op[i]; sv[3*NGRP+i] = rh[i];
    }
    for (int i = tid; i < 196; i += 256) accs[i] = 0.f;
    __syncthreads();
    int t = blockIdx.x * 256 + tid;
    int b = t / (HH*HH); int pix = t % (HH*HH);
    int y = pix / HH, x = pix % HH;
    const float* lp = g_logits + (size_t)b*NGRP*HH*HH + pix;
    float mx = -1e30f;
    for (int g = 0; g < NGRP; g++) mx = fmaxf(mx, lp[(size_t)g*HH*HH]);
    float s = 0.f, a0 = 0.f, a1 = 0.f, a2 = 0.f, a3 = 0.f;
    for (int g = 0; g < NGRP; g++) {
        float e = expf(lp[(size_t)g*HH*HH] - mx);
        s += e; a0 += e*sv[g]; a1 += e*sv[NGRP+g]; a2 += e*sv[2*NGRP+g]; a3 += e*sv[3*NGRP+g];
    }
    float inv = 1.f / s;
    int p = (y % 7)*7 + (x % 7);
    atomicAdd(&accs[p*4+0], a0*inv);
    atomicAdd(&accs[p*4+1], a1*inv);
    atomicAdd(&accs[p*4+2], a2*inv);
    atomicAdd(&accs[p*4+3], a3*inv);
    __syncthreads();
    for (int i = tid; i < 196; i += 256) atomicAdd(&g_wstat[i], accs[i]);
}

// ---------------- build translated gaussian kernels (x opacity) ---------------
__global__ void build_ktw() {
    __shared__ float kpad[49*196];
    __shared__ float wops[49];
    int tid = threadIdx.x;
    for (int i = tid; i < 49*196; i += 256) kpad[i] = 0.f;
    __syncthreads();
    if (tid < 49) {
        int p = tid;
        const float inv1024 = 1.f/1024.f;
        float wsx = g_wstat[p*4+0]*inv1024;
        float wsy = g_wstat[p*4+1]*inv1024;
        float wop = g_wstat[p*4+2]*inv1024;
        float wr  = g_wstat[p*4+3]*inv1024;
        wops[p] = wop;
        float c00 = wsx*wsx + 1e-5f;
        float c11 = wsy*wsy + 1e-5f;
        float c01 = wr*wsx*wsy;
        float det = c00*c11 - c01*c01;
        float i00 = c11/det, i11 = c00/det, i01 = -c01/det;
        float norm = 1.f/(2.f*3.14159265358979f*sqrtf(det));
        float kv[25]; float mx = 0.f;
        #pragma unroll
        for (int i = 0; i < 5; i++)
            #pragma unroll
            for (int j = 0; j < 5; j++) {
                float yv = -5.f + 2.5f*i;
                float xv = -5.f + 2.5f*j;
                float z = -0.5f*(i00*xv*xv + 2.f*i01*xv*yv + i11*yv*yv);
                float k = expf(z)*norm;
                kv[i*5+j] = k; mx = fmaxf(mx, k);
            }
        float im = 1.f/mx;
        #pragma unroll
        for (int i = 0; i < 5; i++)
            #pragma unroll
            for (int j = 0; j < 5; j++)
                kpad[p*196 + (i+4)*14 + (j+4)] = kv[i*5+j]*im;
    }
    __syncthreads();
    for (int idx = tid; idx < 49*196; idx += 256) {
        int p = idx/196, hw = idx%196, h = hw/14, w = hw%14;
        float txo = (0.5f - (float)(p/7)*(1.f/7.f))*2.f;
        float tyo = (0.5f - (float)(p%7)*(1.f/7.f))*2.f;
        float gxv = -1.f + (2.f/13.f)*w + txo;
        float gyv = -1.f + (2.f/13.f)*h + tyo;
        float px = (gxv + 1.f)*0.5f*13.f;
        float py = (gyv + 1.f)*0.5f*13.f;
        float x0f = floorf(px), y0f = floorf(py);
        int x0 = (int)x0f, y0 = (int)y0f;
        float wx = px - x0f, wy = py - y0f;
        float s00 = (y0   >= 0 && y0   < 14 && x0   >= 0 && x0   < 14) ? kpad[p*196 + y0*14 + x0]       : 0.f;
        float s01 = (y0   >= 0 && y0   < 14 && x0+1 >= 0 && x0+1 < 14) ? kpad[p*196 + y0*14 + x0+1]     : 0.f;
        float s10 = (y0+1 >= 0 && y0+1 < 14 && x0   >= 0 && x0   < 14) ? kpad[p*196 + (y0+1)*14 + x0]   : 0.f;
        float s11 = (y0+1 >= 0 && y0+1 < 14 && x0+1 >= 0 && x0+1 < 14) ? kpad[p*196 + (y0+1)*14 + x0+1] : 0.f;
        float kt = s00*(1.f-wy)*(1.f-wx) + s01*(1.f-wy)*wx + s10*wy*(1.f-wx) + s11*wy*wx;
        g_ktw[idx] = kt * wops[p];
    }
}

// ---------------- splat: feat patches -> gfeat (B,64,224,224) -----------------
#define SPLAT_SMEM ((49*196 + 64*49)*4)
__global__ void splat(const float* __restrict__ feat) {
    extern __shared__ float sm[];
    float* kts = sm;             // 9604
    float* fp  = sm + 49*196;    // 3136
    int bl = blockIdx.x;         // 0..1023
    int b = bl / 256; int l = bl % 256; int pr = l / 16, pc = l % 16;
    int tid = threadIdx.x;       // 196
    for (int i = tid; i < 49*196; i += 196) kts[i] = g_ktw[i];
    const float* fb = feat + (size_t)b*64*HH*HH;
    for (int i = tid; i < 64*49; i += 196) {
        int c = i/49, p = i%49;
        fp[i] = fb[((size_t)c*HH + pr*7 + p/7)*HH + pc*7 + p%7];
    }
    __syncthreads();
    int h = tid/14, w = tid%14;
    int oy = pr*14 + h, ox = pc*14 + w;
    float* outb = g_gfeat + (size_t)b*64*H2*H2;
    for (int c0 = 0; c0 < 64; c0 += 4) {
        float a0 = 0.f, a1 = 0.f, a2 = 0.f, a3 = 0.f;
        #pragma unroll
        for (int p = 0; p < 49; p++) {
            float kv = kts[p*196 + tid];
            a0 += fp[(c0+0)*49 + p]*kv;
            a1 += fp[(c0+1)*49 + p]*kv;
            a2 += fp[(c0+2)*49 + p]*kv;
            a3 += fp[(c0+3)*49 + p]*kv;
        }
        outb[((size_t)(c0+0)*H2 + oy)*H2 + ox] = __saturatef(a0);
        outb[((size_t)(c0+1)*H2 + oy)*H2 + ox] = __saturatef(a1);
        outb[((size_t)(c0+2)*H2 + oy)*H2 + ox] = __saturatef(a2);
        outb[((size_t)(c0+3)*H2 + oy)*H2 + ox] = __saturatef(a3);
    }
}

// ---------------- conv3x3 64->256 @224, NHWC out (packed f32x2) ---------------
__global__ void conv224p(const float* __restrict__ w,
                         const float* __restrict__ bias, int sel) {
    extern __shared__ float sm[];
    float* ins = sm;
    ull*   wsp = (ull*)(sm + 64*324);
    int tile = blockIdx.x;       // 196 tiles of 16x16
    int co0  = blockIdx.y * 16;  // 16 groups
    int b    = blockIdx.z;
    int ty0 = (tile / 14) * 16, tx0 = (tile % 14) * 16;
    int tid = threadIdx.x;

    const float* inb = g_gfeat + (size_t)b*64*H2*H2;
    for (int i = tid; i < 64*18*18; i += 256) {
        int ci = i / 324; int r = (i % 324) / 18; int c = i % 18;
        int gy = ty0 + r - 1, gx = tx0 + c - 1;
        float v = 0.f;
        if (gy >= 0 && gy < H2 && gx >= 0 && gx < H2) v = inb[((size_t)ci*H2 + gy)*H2 + gx];
        ins[i] = v;
    }
    float* wspf = (float*)wsp;
    for (int i = tid; i < 64*8*9*2; i += 256) {
        int half = i & 1; int e = i >> 1;
        int k = e % 9; int cop = (e/9) & 7; int ci = e/72;
        wspf[((ci*8 + cop)*10 + k)*2 + half] = w[(size_t)(co0 + cop*2 + half)*576 + ci*9 + k];
    }
    __syncthreads();

    int ty = tid/16, tx = tid%16;
    ull acc[8];
    #pragma unroll
    for (int cop = 0; cop < 8; cop++) acc[cop] = pk2(bias[co0+2*cop], bias[co0+2*cop+1]);

    for (int ci = 0; ci < 64; ci++) {
        const float* ip = ins + ci*324 + ty*18 + tx;
        ull vv[9];
        #pragma unroll
        for (int dy = 0; dy < 3; dy++)
            #pragma unroll
            for (int dx = 0; dx < 3; dx++) {
                float v = ip[dy*18 + dx];
                vv[dy*3+dx] = pk2(v, v);
            }
        const ull* wbase = wsp + ci*80;
        #pragma unroll
        for (int cop = 0; cop < 8; cop++) {
            const ulonglong2* wc2 = (const ulonglong2*)(wbase + cop*10);
            ulonglong2 p0 = wc2[0], p1 = wc2[1], p2 = wc2[2], p3 = wc2[3];
            ull p8 = (wbase + cop*10)[8];
            fma2(acc[cop], vv[0], p0.x); fma2(acc[cop], vv[1], p0.y);
            fma2(acc[cop], vv[2], p1.x); fma2(acc[cop], vv[3], p1.y);
            fma2(acc[cop], vv[4], p2.x); fma2(acc[cop], vv[5], p2.y);
            fma2(acc[cop], vv[6], p3.x); fma2(acc[cop], vv[7], p3.y);
            fma2(acc[cop], vv[8], p8);
        }
    }
    float* outp = sel ? g_freq : g_coef;
    int oy = ty0 + ty, ox = tx0 + tx;
    float* orow = outp + (((size_t)b*H2 + oy)*H2 + ox)*HID + co0;
    float o[16];
    #pragma unroll
    for (int cop = 0; cop < 8; cop++) upk2(acc[cop], o[2*cop], o[2*cop+1]);
    #pragma unroll
    for (int q = 0; q < 4; q++) {
        float4 ov;
        ov.x = o[q*4+0]; ov.y = o[q*4+1]; ov.z = o[q*4+2]; ov.w = o[q*4+3];
        *(float4*)(orow + q*4) = ov;
    }
}

// ---------------- gather + fourier basis -> X0 --------------------------------
__global__ void gather_basis(const float* __restrict__ coord,
                             const float* __restrict__ cell,
                             const float* __restrict__ phase_w) {
    int warp = threadIdx.x / 32, lane = threadIdx.x % 32;
    int m = blockIdx.x * 8 + warp;               // 0..200703
    int b = m / QQ; int q = m % QQ;
    float cy = coord[((size_t)b*QQ + q)*2 + 0];
    float cx = coord[((size_t)b*QQ + q)*2 + 1];
    int ix = (int)rintf(((cx + 1.f)*(float)H2 - 1.f)*0.5f);
    int iy = (int)rintf(((cy + 1.f)*(float)H2 - 1.f)*0.5f);
    bool ok = (ix >= 0 && ix < H2 && iy >= 0 && iy < H2);
    float* xr = g_X0 + (size_t)m*HID;
    if (!ok) {
        #pragma unroll
        for (int kk = 0; kk < 4; kk++) {
            int k = lane + kk*32;
            xr[k] = 0.f; xr[128 + k] = 0.f;
        }
        return;
    }
    float fcy = -1.f + 1.f/(float)H2 + (2.f/(float)H2)*(float)iy;
    float fcx = -1.f + 1.f/(float)H2 + (2.f/(float)H2)*(float)ix;
    float rely = (cy - fcy)*(float)H2;
    float relx = (cx - fcx)*(float)H2;
    float rc0 = cell[((size_t)b*QQ + q)*2 + 0]*(float)H2;
    float rc1 = cell[((size_t)b*QQ + q)*2 + 1]*(float)H2;
    size_t base = (((size_t)b*H2 + iy)*H2 + ix)*HID;
    const float*  cf = g_coef + base;
    const float2* fq = (const float2*)(g_freq + base);
    const float2* pw = (const float2*)phase_w;
    #pragma unroll
    for (int kk = 0; kk < 4; kk++) {
        int k = lane + kk*32;
        float2 f = fq[k];
        float2 p = pw[k];
        float s = f.x*rely + f.y*relx + rc0*p.x + rc1*p.y;
        xr[k]       = cf[k]       * cospif(s);
        xr[128 + k] = cf[128 + k] * sinpif(s);
    }
}

// ---------------- GEMM (M x 256) @ W^T (256 x 256) + bias + relu, packed ------
// layer 0: A=g_X0 -> C=g_X1 ;  layer 1: A=g_X1 -> C=g_X0
__global__ void gemm_relu_p(const float* __restrict__ Wt,
                            const float* __restrict__ bias, int layer) {
    __shared__ ull   a_su[16*128];    // prepacked (a,a) per element, k-major
    __shared__ float b_s[16][64];
    const float* A = layer ? g_X1 : g_X0;
    float*       C = layer ? g_X0 : g_X1;
    int m0 = blockIdx.x * 128;
    int n0 = blockIdx.y * 64;
    int tid = threadIdx.x;
    int r0 = (tid/16)*8;
    int c0 = (tid%16)*4;
    int lrA = tid >> 1, lcA = (tid & 1)*8;
    int lrB = tid >> 2, lcB = (tid & 3)*4;

    ull acc[8][2];
    ull bp0i = pk2(bias[n0+c0],   bias[n0+c0+1]);
    ull bp1i = pk2(bias[n0+c0+2], bias[n0+c0+3]);
    #pragma unroll
    for (int i = 0; i < 8; i++) { acc[i][0] = bp0i; acc[i][1] = bp1i; }

    for (int k0 = 0; k0 < 256; k0 += 16) {
        float4 av0 = *(const float4*)&A [((size_t)(m0 + lrA))*256 + k0 + lcA];
        float4 av1 = *(const float4*)&A [((size_t)(m0 + lrA))*256 + k0 + lcA + 4];
        float4 bv  = *(const float4*)&Wt[((size_t)(n0 + lrB))*256 + k0 + lcB];
        __syncthreads();
        a_su[(lcA+0)*128 + lrA] = pk2(av0.x, av0.x);
        a_su[(lcA+1)*128 + lrA] = pk2(av0.y, av0.y);
        a_su[(lcA+2)*128 + lrA] = pk2(av0.z, av0.z);
        a_su[(lcA+3)*128 + lrA] = pk2(av0.w, av0.w);
        a_su[(lcA+4)*128 + lrA] = pk2(av1.x, av1.x);
        a_su[(lcA+5)*128 + lrA] = pk2(av1.y, av1.y);
        a_su[(lcA+6)*128 + lrA] = pk2(av1.z, av1.z);
        a_su[(lcA+7)*128 + lrA] = pk2(av1.w, av1.w);
        b_s[lcB+0][lrB] = bv.x;
        b_s[lcB+1][lrB] = bv.y;
        b_s[lcB+2][lrB] = bv.z;
        b_s[lcB+3][lrB] = bv.w;
        __syncthreads();
        #pragma unroll
        for (int kk = 0; kk < 16; kk++) {
            const ulonglong2* ap = (const ulonglong2*)&a_su[kk*128 + r0];
            ulonglong2 a01 = ap[0], a23 = ap[1], a45 = ap[2], a67 = ap[3];
            ulonglong2 bb = *(const ulonglong2*)&b_s[kk][c0];
            fma2(acc[0][0], a01.x, bb.x); fma2(acc[0][1], a01.x, bb.y);
            fma2(acc[1][0], a01.y, bb.x); fma2(acc[1][1], a01.y, bb.y);
            fma2(acc[2][0], a23.x, bb.x); fma2(acc[2][1], a23.x, bb.y);
            fma2(acc[3][0], a23.y, bb.x); fma2(acc[3][1], a23.y, bb.y);
            fma2(acc[4][0], a45.x, bb.x); fma2(acc[4][1], a45.x, bb.y);
            fma2(acc[5][0], a45.y, bb.x); fma2(acc[5][1], a45.y, bb.y);
            fma2(acc[6][0], a67.x, bb.x); fma2(acc[6][1], a67.x, bb.y);
            fma2(acc[7][0], a67.y, bb.x); fma2(acc[7][1], a67.y, bb.y);
        }
    }
    #pragma unroll
    for (int i = 0; i < 8; i++) {
        float4 o;
        upk2(acc[i][0], o.x, o.y);
        upk2(acc[i][1], o.z, o.w);
        o.x = fmaxf(o.x, 0.f); o.y = fmaxf(o.y, 0.f);
        o.z = fmaxf(o.z, 0.f); o.w = fmaxf(o.w, 0.f);
        *(float4*)&C[((size_t)(m0 + r0 + i))*256 + n0 + c0] = o;
    }
}

// ---------------- final 256 -> 3 ----------------------------------------------
__global__ void final_layer(const float* __restrict__ w3,
                            const float* __restrict__ b3,
                            float* __restrict__ out) {
    __shared__ float w3s[3*256];
    int tid = threadIdx.x;
    for (int i = tid; i < 768; i += 256) w3s[i] = w3[i];
    __syncthreads();
    int warp = tid/32, lane = tid%32;
    int m = blockIdx.x * 8 + warp;
    const float* xr = g_X0 + (size_t)m*256;
    float a0 = 0.f, a1 = 0.f, a2 = 0.f;
    #pragma unroll
    for (int j = 0; j < 8; j++) {
        int k = lane + j*32;
        float v = xr[k];
        a0 += v*w3s[k]; a1 += v*w3s[256 + k]; a2 += v*w3s[512 + k];
    }
    #pragma unroll
    for (int off = 16; off; off >>= 1) {
        a0 += __shfl_down_sync(0xffffffffu, a0, off);
        a1 += __shfl_down_sync(0xffffffffu, a1, off);
        a2 += __shfl_down_sync(0xffffffffu, a2, off);
    }
    if (lane == 0) {
        out[(size_t)m*3 + 0] = a0 + b3[0];
        out[(size_t)m*3 + 1] = a1 + b3[1];
        out[(size_t)m*3 + 2] = a2 + b3[2];
    }
}

// ---------------- launch -------------------------------------------------------
extern "C" void kernel_launch(void* const* d_in, const int* in_sizes, int n_in,
                              void* d_out, int out_size) {
    const float* feat    = (const float*)d_in[0];
    const float* coord   = (const float*)d_in[1];
    const float* cell    = (const float*)d_in[2];
    const float* cls_w1  = (const float*)d_in[3];
    const float* cls_b1  = (const float*)d_in[4];
    const float* cls_w2  = (const float*)d_in[5];
    const float* cls_b2  = (const float*)d_in[6];
    const float* sigma_x = (const float*)d_in[7];
    const float* sigma_y = (const float*)d_in[8];
    const float* opacity = (const float*)d_in[9];
    const float* rho     = (const float*)d_in[10];
    const float* coef_w  = (const float*)d_in[11];
    const float* coef_b  = (const float*)d_in[12];
    const float* freq_w  = (const float*)d_in[13];
    const float* freq_b  = (const float*)d_in[14];
    const float* phase_w = (const float*)d_in[15];
    const float* mlp_w1  = (const float*)d_in[16];
    const float* mlp_b1  = (const float*)d_in[17];
    const float* mlp_w2  = (const float*)d_in[18];
    const float* mlp_b2  = (const float*)d_in[19];
    const float* mlp_w3  = (const float*)d_in[20];
    const float* mlp_b3  = (const float*)d_in[21];
    float* out = (float*)d_out;

    cudaFuncSetAttribute(conv112p, cudaFuncAttributeMaxDynamicSharedMemorySize, CONVP_SMEM);
    cudaFuncSetAttribute(conv224p, cudaFuncAttributeMaxDynamicSharedMemorySize, CONVP_SMEM);
    cudaFuncSetAttribute(splat,    cudaFuncAttributeMaxDynamicSharedMemorySize, SPLAT_SMEM);

    conv112p<<<dim3(49, 4, BB), 256, CONVP_SMEM>>>(feat, cls_w1, cls_b1);
    conv1x1_logits<<<196, 256>>>(cls_w2, cls_b2);
    zero_stats<<<1, 256>>>();
    softmax_stats<<<196, 256>>>(sigma_x, sigma_y, opacity, rho);
    build_ktw<<<1, 256>>>();
    splat<<<1024, 196, SPLAT_SMEM>>>(feat);
    conv224p<<<dim3(196, 16, BB), 256, CONVP_SMEM>>>(coef_w, coef_b, 0);
    conv224p<<<dim3(196, 16, BB), 256, CONVP_SMEM>>>(freq_w, freq_b, 1);
    gather_basis<<<MTOT/8, 256>>>(coord, cell, phase_w);
    gemm_relu_p<<<dim3(MTOT/128, 4), 256>>>(mlp_w1, mlp_b1, 0);
    gemm_relu_p<<<dim3(MTOT/128, 4), 256>>>(mlp_w2, mlp_b2, 1);
    final_layer<<<MTOT/8, 256>>>(mlp_w3, mlp_b3, out);
}

// round 3
// speedup vs baseline: 1.4322x; 1.0135x over previous
#include <cuda_runtime.h>
#include <math.h>
#include <stdint.h>

#define CIN 64
#define NGRP 100
#define HID 256
#define BB 4
#define HH 112
#define H2 224
#define QQ 50176
#define MTOT (BB*QQ)   // 200704

typedef unsigned long long ull;

__device__ __forceinline__ ull pk2(float a, float b) {
    ull r; asm("mov.b64 %0,{%1,%2};" : "=l"(r) : "f"(a), "f"(b)); return r;
}
__device__ __forceinline__ void fma2(ull& d, ull a, ull b) {
    asm("fma.rn.f32x2 %0,%1,%2,%0;" : "+l"(d) : "l"(a), "l"(b));
}
__device__ __forceinline__ void upk2(ull v, float& a, float& b) {
    asm("mov.b64 {%0,%1},%2;" : "=f"(a), "=f"(b) : "l"(v));
}
__device__ __forceinline__ void cpa16(void* dst, const void* src) {
    unsigned d = (unsigned)__cvta_generic_to_shared(dst);
    asm volatile("cp.async.cg.shared.global [%0], [%1], 16;" :: "r"(d), "l"(src));
}

// ---------------- scratch (device globals; no allocation allowed) -------------
__device__ float g_h[(size_t)BB*CIN*HH*HH];          // 12.8 MB
__device__ float g_logits[(size_t)BB*NGRP*HH*HH];    // 20 MB
__device__ float g_wstat[49*4];
__device__ float g_ktw[49*196];
__device__ float g_gfeat[(size_t)BB*CIN*H2*H2];      // 51 MB  (NCHW)
__device__ float g_coef[(size_t)BB*H2*H2*HID];       // 205 MB (NHWC)
__device__ float g_freq[(size_t)BB*H2*H2*HID];       // 205 MB (NHWC)
__device__ float g_X0[(size_t)MTOT*HID];             // 205 MB
__device__ float g_X1[(size_t)MTOT*HID];             // 205 MB
// packed conv224 weights: [sel][chunk32][ci64][cop4][k10] f32x2 pairs
__device__ __align__(16) ull g_wpack[2*32*64*4*10];  // 1.3 MB

// ---------------- conv3x3 64->64 @112, relu, NCHW out (packed f32x2) ----------
#define CONVP_SMEM (64*18*18*4 + 64*8*10*8)   // 123904

__global__ void conv112p(const float* __restrict__ in,
                         const float* __restrict__ w,
                         const float* __restrict__ bias) {
    extern __shared__ float sm[];
    float* ins = sm;                            // 64*18*18
    ull*   wsp = (ull*)(sm + 64*324);           // 64*8*10 packed pairs
    int tile = blockIdx.x;
    int co0  = blockIdx.y * 16;
    int b    = blockIdx.z;
    int ty0 = (tile / 7) * 16, tx0 = (tile % 7) * 16;
    int tid = threadIdx.x;

    const float* inb = in + (size_t)b * CIN * HH * HH;
    for (int i = tid; i < 64*18*18; i += 256) {
        int ci = i / 324; int r = (i % 324) / 18; int c = i % 18;
        int gy = ty0 + r - 1, gx = tx0 + c - 1;
        float v = 0.f;
        if (gy >= 0 && gy < HH && gx >= 0 && gx < HH) v = inb[(ci*HH + gy)*HH + gx];
        ins[i] = v;
    }
    float* wspf = (float*)wsp;
    for (int i = tid; i < 64*8*9*2; i += 256) {
        int half = i & 1; int e = i >> 1;
        int k = e % 9; int cop = (e/9) & 7; int ci = e/72;
        wspf[((ci*8 + cop)*10 + k)*2 + half] = w[(size_t)(co0 + cop*2 + half)*576 + ci*9 + k];
    }
    __syncthreads();

    int ty = tid / 16, tx = tid % 16;
    ull acc[8];
    #pragma unroll
    for (int cop = 0; cop < 8; cop++) acc[cop] = pk2(bias[co0+2*cop], bias[co0+2*cop+1]);

    for (int ci = 0; ci < 64; ci++) {
        const float* ip = ins + ci*324 + ty*18 + tx;
        ull vv[9];
        #pragma unroll
        for (int dy = 0; dy < 3; dy++)
            #pragma unroll
            for (int dx = 0; dx < 3; dx++) {
                float v = ip[dy*18 + dx];
                vv[dy*3+dx] = pk2(v, v);
            }
        const ull* wbase = wsp + ci*80;
        #pragma unroll
        for (int cop = 0; cop < 8; cop++) {
            const ulonglong2* wc2 = (const ulonglong2*)(wbase + cop*10);
            ulonglong2 p0 = wc2[0], p1 = wc2[1], p2 = wc2[2], p3 = wc2[3];
            ull p8 = (wbase + cop*10)[8];
            fma2(acc[cop], vv[0], p0.x); fma2(acc[cop], vv[1], p0.y);
            fma2(acc[cop], vv[2], p1.x); fma2(acc[cop], vv[3], p1.y);
            fma2(acc[cop], vv[4], p2.x); fma2(acc[cop], vv[5], p2.y);
            fma2(acc[cop], vv[6], p3.x); fma2(acc[cop], vv[7], p3.y);
            fma2(acc[cop], vv[8], p8);
        }
    }
    int oy = ty0 + ty, ox = tx0 + tx;
    #pragma unroll
    for (int cop = 0; cop < 8; cop++) {
        float lo, hi; upk2(acc[cop], lo, hi);
        g_h[(((size_t)b*64 + co0 + 2*cop    )*HH + oy)*HH + ox] = fmaxf(lo, 0.f);
        g_h[(((size_t)b*64 + co0 + 2*cop + 1)*HH + oy)*HH + ox] = fmaxf(hi, 0.f);
    }
}

// ---------------- 1x1 conv 64->100 -------------------------------------------
__global__ void conv1x1_logits(const float* __restrict__ w2,
                               const float* __restrict__ b2) {
    __shared__ float ws[NGRP*64];
    int tid = threadIdx.x;
    for (int i = tid; i < NGRP*64; i += 256) ws[i] = w2[i];
    __syncthreads();
    int t = blockIdx.x * 256 + tid;
    int b = t / (HH*HH); int pix = t % (HH*HH);
    const float* hp = g_h + (size_t)b*64*HH*HH + pix;
    float hv[64];
    #pragma unroll
    for (int ci = 0; ci < 64; ci++) hv[ci] = hp[(size_t)ci*HH*HH];
    float* lp = g_logits + (size_t)b*NGRP*HH*HH + pix;
    for (int g = 0; g < NGRP; g++) {
        float acc = b2[g];
        const float* wg = ws + g*64;
        #pragma unroll
        for (int ci = 0; ci < 64; ci += 4) {
            float4 wv = *(const float4*)(wg + ci);
            acc += hv[ci]*wv.x + hv[ci+1]*wv.y + hv[ci+2]*wv.z + hv[ci+3]*wv.w;
        }
        lp[(size_t)g*HH*HH] = acc;
    }
}

// ---------------- softmax + weighted stats ------------------------------------
__global__ void zero_stats() {
    int t = threadIdx.x;
    if (t < 196) g_wstat[t] = 0.f;
}

__global__ void softmax_stats(const float* __restrict__ sx, const float* __restrict__ sy,
                              const float* __restrict__ op, const float* __restrict__ rh) {
    __shared__ float sv[4*NGRP];
    __shared__ float accs[196];
    int tid = threadIdx.x;
    for (int i = tid; i < NGRP; i += 256) {
        sv[i] = sx[i]; sv[NGRP+i] = sy[i]; sv[2*NGRP+i] = op[i]; sv[3*NGRP+i] = rh[i];
    }
    for (int i = tid; i < 196; i += 256) accs[i] = 0.f;
    __syncthreads();
    int t = blockIdx.x * 256 + tid;
    int b = t / (HH*HH); int pix = t % (HH*HH);
    int y = pix / HH, x = pix % HH;
    const float* lp = g_logits + (size_t)b*NGRP*HH*HH + pix;
    float mx = -1e30f;
    for (int g = 0; g < NGRP; g++) mx = fmaxf(mx, lp[(size_t)g*HH*HH]);
    float s = 0.f, a0 = 0.f, a1 = 0.f, a2 = 0.f, a3 = 0.f;
    for (int g = 0; g < NGRP; g++) {
        float e = expf(lp[(size_t)g*HH*HH] - mx);
        s += e; a0 += e*sv[g]; a1 += e*sv[NGRP+g]; a2 += e*sv[2*NGRP+g]; a3 += e*sv[3*NGRP+g];
    }
    float inv = 1.f / s;
    int p = (y % 7)*7 + (x % 7);
    atomicAdd(&accs[p*4+0], a0*inv);
    atomicAdd(&accs[p*4+1], a1*inv);
    atomicAdd(&accs[p*4+2], a2*inv);
    atomicAdd(&accs[p*4+3], a3*inv);
    __syncthreads();
    for (int i = tid; i < 196; i += 256) atomicAdd(&g_wstat[i], accs[i]);
}

// ---------------- build translated gaussian kernels (x opacity) ---------------
__global__ void build_ktw() {
    __shared__ float kpad[49*196];
    __shared__ float wops[49];
    int tid = threadIdx.x;
    for (int i = tid; i < 49*196; i += 256) kpad[i] = 0.f;
    __syncthreads();
    if (tid < 49) {
        int p = tid;
        const float inv1024 = 1.f/1024.f;
        float wsx = g_wstat[p*4+0]*inv1024;
        float wsy = g_wstat[p*4+1]*inv1024;
        float wop = g_wstat[p*4+2]*inv1024;
        float wr  = g_wstat[p*4+3]*inv1024;
        wops[p] = wop;
        float c00 = wsx*wsx + 1e-5f;
        float c11 = wsy*wsy + 1e-5f;
        float c01 = wr*wsx*wsy;
        float det = c00*c11 - c01*c01;
        float i00 = c11/det, i11 = c00/det, i01 = -c01/det;
        float norm = 1.f/(2.f*3.14159265358979f*sqrtf(det));
        float kv[25]; float mx = 0.f;
        #pragma unroll
        for (int i = 0; i < 5; i++)
            #pragma unroll
            for (int j = 0; j < 5; j++) {
                float yv = -5.f + 2.5f*i;
                float xv = -5.f + 2.5f*j;
                float z = -0.5f*(i00*xv*xv + 2.f*i01*xv*yv + i11*yv*yv);
                float k = expf(z)*norm;
                kv[i*5+j] = k; mx = fmaxf(mx, k);
            }
        float im = 1.f/mx;
        #pragma unroll
        for (int i = 0; i < 5; i++)
            #pragma unroll
            for (int j = 0; j < 5; j++)
                kpad[p*196 + (i+4)*14 + (j+4)] = kv[i*5+j]*im;
    }
    __syncthreads();
    for (int idx = tid; idx < 49*196; idx += 256) {
        int p = idx/196, hw = idx%196, h = hw/14, w = hw%14;
        float txo = (0.5f - (float)(p/7)*(1.f/7.f))*2.f;
        float tyo = (0.5f - (float)(p%7)*(1.f/7.f))*2.f;
        float gxv = -1.f + (2.f/13.f)*w + txo;
        float gyv = -1.f + (2.f/13.f)*h + tyo;
        float px = (gxv + 1.f)*0.5f*13.f;
        float py = (gyv + 1.f)*0.5f*13.f;
        float x0f = floorf(px), y0f = floorf(py);
        int x0 = (int)x0f, y0 = (int)y0f;
        float wx = px - x0f, wy = py - y0f;
        float s00 = (y0   >= 0 && y0   < 14 && x0   >= 0 && x0   < 14) ? kpad[p*196 + y0*14 + x0]       : 0.f;
        float s01 = (y0   >= 0 && y0   < 14 && x0+1 >= 0 && x0+1 < 14) ? kpad[p*196 + y0*14 + x0+1]     : 0.f;
        float s10 = (y0+1 >= 0 && y0+1 < 14 && x0   >= 0 && x0   < 14) ? kpad[p*196 + (y0+1)*14 + x0]   : 0.f;
        float s11 = (y0+1 >= 0 && y0+1 < 14 && x0+1 >= 0 && x0+1 < 14) ? kpad[p*196 + (y0+1)*14 + x0+1] : 0.f;
        float kt = s00*(1.f-wy)*(1.f-wx) + s01*(1.f-wy)*wx + s10*wy*(1.f-wx) + s11*wy*wx;
        g_ktw[idx] = kt * wops[p];
    }
}

// ---------------- splat: feat patches -> gfeat (B,64,224,224) -----------------
#define SPLAT_SMEM ((49*196 + 64*49)*4)
__global__ void splat(const float* __restrict__ feat) {
    extern __shared__ float sm[];
    float* kts = sm;             // 9604
    float* fp  = sm + 49*196;    // 3136
    int bl = blockIdx.x;         // 0..1023
    int b = bl / 256; int l = bl % 256; int pr = l / 16, pc = l % 16;
    int tid = threadIdx.x;       // 196
    for (int i = tid; i < 49*196; i += 196) kts[i] = g_ktw[i];
    const float* fb = feat + (size_t)b*64*HH*HH;
    for (int i = tid; i < 64*49; i += 196) {
        int c = i/49, p = i%49;
        fp[i] = fb[((size_t)c*HH + pr*7 + p/7)*HH + pc*7 + p%7];
    }
    __syncthreads();
    int h = tid/14, w = tid%14;
    int oy = pr*14 + h, ox = pc*14 + w;
    float* outb = g_gfeat + (size_t)b*64*H2*H2;
    for (int c0 = 0; c0 < 64; c0 += 4) {
        float a0 = 0.f, a1 = 0.f, a2 = 0.f, a3 = 0.f;
        #pragma unroll
        for (int p = 0; p < 49; p++) {
            float kv = kts[p*196 + tid];
            a0 += fp[(c0+0)*49 + p]*kv;
            a1 += fp[(c0+1)*49 + p]*kv;
            a2 += fp[(c0+2)*49 + p]*kv;
            a3 += fp[(c0+3)*49 + p]*kv;
        }
        outb[((size_t)(c0+0)*H2 + oy)*H2 + ox] = __saturatef(a0);
        outb[((size_t)(c0+1)*H2 + oy)*H2 + ox] = __saturatef(a1);
        outb[((size_t)(c0+2)*H2 + oy)*H2 + ox] = __saturatef(a2);
        outb[((size_t)(c0+3)*H2 + oy)*H2 + ox] = __saturatef(a3);
    }
}

// ---------------- pack conv224 weights into f32x2 chunk layout ----------------
// g_wpack[sel][c(32)][ci(64)][cop(4)][k(10)] ; pair = (co=8c+2cop, co+1)
__global__ void pack_weights(const float* __restrict__ wc,
                             const float* __restrict__ wf) {
    int i = blockIdx.x*256 + threadIdx.x;   // 0..81919
    if (i >= 81920) return;
    int k = i % 10; int e = i/10; int cop = e & 3; e >>= 2; int ci = e & 63; int c = e >> 6;
    int co = c*8 + cop*2;
    float a0 = 0.f, b0 = 0.f, a1 = 0.f, b1 = 0.f;
    if (k < 9) {
        size_t idx0 = (size_t)co*576 + ci*9 + k;
        size_t idx1 = (size_t)(co+1)*576 + ci*9 + k;
        a0 = wc[idx0]; b0 = wc[idx1];
        a1 = wf[idx0]; b1 = wf[idx1];
    }
    g_wpack[i]         = pk2(a0, b0);
    g_wpack[81920 + i] = pk2(a1, b1);
}

// ---------------- conv3x3 64->256 @224, NHWC out, resident-input --------------
// tile 32 rows x 16 cols, 512 threads, all 256 co in 32 chunks of 8,
// weights cp.async double-buffered.
#define C224_SMEM (64*612*4 + 2*2560*8)   // 156672 + 40960 = 197632
__global__ void conv224w(const float* __restrict__ bias, int sel) {
    extern __shared__ float sm[];
    float* ins = sm;                       // [ci][34][18]
    ull*  wbuf = (ull*)(sm + 64*612);      // 2 x 2560
    int bt = blockIdx.x;                   // 0..97
    int b  = blockIdx.y;
    int row0 = (bt/14)*32, col0 = (bt%14)*16;
    int tid = threadIdx.x;                 // 512

    const ull* wsrc = g_wpack + (sel ? 81920 : 0);
    // prefetch chunk 0
    for (int i = tid; i < 1280; i += 512)
        cpa16(wbuf + i*2, wsrc + i*2);
    asm volatile("cp.async.commit_group;" ::: "memory");

    const float* inb = g_gfeat + (size_t)b*64*H2*H2;
    for (int i = tid; i < 64*612; i += 512) {
        int ci = i/612; int rr = (i%612)/18; int cc = i%18;
        int gy = row0 + rr - 1, gx = col0 + cc - 1;
        float v = 0.f;
        if (gy >= 0 && gy < H2 && gx >= 0 && gx < H2)
            v = inb[(size_t)ci*(H2*H2) + gy*H2 + gx];
        ins[i] = v;
    }

    int ty = tid >> 4, tx = tid & 15;      // ty 0..31, tx 0..15
    float* outbase = (sel ? g_freq : g_coef)
                   + (((size_t)b*H2 + row0 + ty)*H2 + col0 + tx)*HID;

    for (int c = 0; c < 32; c++) {
        if (c + 1 < 32) {
            const ull* src = wsrc + (c+1)*2560;
            ull* dst = wbuf + ((c+1)&1)*2560;
            for (int i = tid; i < 1280; i += 512)
                cpa16(dst + i*2, src + i*2);
        }
        asm volatile("cp.async.commit_group;" ::: "memory");
        asm volatile("cp.async.wait_group 1;" ::: "memory");
        __syncthreads();

        const ull* wb = wbuf + (c&1)*2560;
        ull acc0 = pk2(bias[c*8+0], bias[c*8+1]);
        ull acc1 = pk2(bias[c*8+2], bias[c*8+3]);
        ull acc2 = pk2(bias[c*8+4], bias[c*8+5]);
        ull acc3 = pk2(bias[c*8+6], bias[c*8+7]);

        for (int ci = 0; ci < 64; ci++) {
            const float* ip = ins + ci*612 + ty*18 + tx;
            ull vv[9];
            #pragma unroll
            for (int dy = 0; dy < 3; dy++)
                #pragma unroll
                for (int dx = 0; dx < 3; dx++) {
                    float v = ip[dy*18 + dx];
                    vv[dy*3+dx] = pk2(v, v);
                }
            const ull* wci = wb + ci*40;
            #pragma unroll
            for (int cop = 0; cop < 4; cop++) {
                const ulonglong2* wc2 = (const ulonglong2*)(wci + cop*10);
                ulonglong2 p0 = wc2[0], p1 = wc2[1], p2 = wc2[2], p3 = wc2[3];
                ull p8 = (wci + cop*10)[8];
                ull* ac = (cop == 0) ? &acc0 : (cop == 1) ? &acc1 : (cop == 2) ? &acc2 : &acc3;
                fma2(*ac, vv[0], p0.x); fma2(*ac, vv[1], p0.y);
                fma2(*ac, vv[2], p1.x); fma2(*ac, vv[3], p1.y);
                fma2(*ac, vv[4], p2.x); fma2(*ac, vv[5], p2.y);
                fma2(*ac, vv[6], p3.x); fma2(*ac, vv[7], p3.y);
                fma2(*ac, vv[8], p8);
            }
        }
        float o[8];
        upk2(acc0, o[0], o[1]); upk2(acc1, o[2], o[3]);
        upk2(acc2, o[4], o[5]); upk2(acc3, o[6], o[7]);
        float* op = outbase + c*8;
        *(float4*)(op)     = make_float4(o[0], o[1], o[2], o[3]);
        *(float4*)(op + 4) = make_float4(o[4], o[5], o[6], o[7]);
        __syncthreads();
    }
}

// ---------------- gather + fourier basis -> X0 --------------------------------
__global__ void gather_basis(const float* __restrict__ coord,
                             const float* __restrict__ cell,
                             const float* __restrict__ phase_w) {
    int warp = threadIdx.x / 32, lane = threadIdx.x % 32;
    int m = blockIdx.x * 8 + warp;               // 0..200703
    int b = m / QQ; int q = m % QQ;
    float cy = coord[((size_t)b*QQ + q)*2 + 0];
    float cx = coord[((size_t)b*QQ + q)*2 + 1];
    int ix = (int)rintf(((cx + 1.f)*(float)H2 - 1.f)*0.5f);
    int iy = (int)rintf(((cy + 1.f)*(float)H2 - 1.f)*0.5f);
    bool ok = (ix >= 0 && ix < H2 && iy >= 0 && iy < H2);
    float* xr = g_X0 + (size_t)m*HID;
    if (!ok) {
        #pragma unroll
        for (int kk = 0; kk < 4; kk++) {
            int k = lane + kk*32;
            xr[k] = 0.f; xr[128 + k] = 0.f;
        }
        return;
    }
    float fcy = -1.f + 1.f/(float)H2 + (2.f/(float)H2)*(float)iy;
    float fcx = -1.f + 1.f/(float)H2 + (2.f/(float)H2)*(float)ix;
    float rely = (cy - fcy)*(float)H2;
    float relx = (cx - fcx)*(float)H2;
    float rc0 = cell[((size_t)b*QQ + q)*2 + 0]*(float)H2;
    float rc1 = cell[((size_t)b*QQ + q)*2 + 1]*(float)H2;
    size_t base = (((size_t)b*H2 + iy)*H2 + ix)*HID;
    const float*  cf = g_coef + base;
    const float2* fq = (const float2*)(g_freq + base);
    const float2* pw = (const float2*)phase_w;
    #pragma unroll
    for (int kk = 0; kk < 4; kk++) {
        int k = lane + kk*32;
        float2 f = fq[k];
        float2 p = pw[k];
        float s = f.x*rely + f.y*relx + rc0*p.x + rc1*p.y;
        xr[k]       = cf[k]       * cospif(s);
        xr[128 + k] = cf[128 + k] * sinpif(s);
    }
}

// ---------------- GEMM (M x 256) @ W^T (256 x 256) + bias + relu, packed ------
__global__ void gemm_relu_p(const float* __restrict__ Wt,
                            const float* __restrict__ bias, int layer) {
    __shared__ ull   a_su[16*128];
    __shared__ float b_s[16][64];
    const float* A = layer ? g_X1 : g_X0;
    float*       C = layer ? g_X0 : g_X1;
    int m0 = blockIdx.x * 128;
    int n0 = blockIdx.y * 64;
    int tid = threadIdx.x;
    int r0 = (tid/16)*8;
    int c0 = (tid%16)*4;
    int lrA = tid >> 1, lcA = (tid & 1)*8;
    int lrB = tid >> 2, lcB = (tid & 3)*4;

    ull acc[8][2];
    ull bp0i = pk2(bias[n0+c0],   bias[n0+c0+1]);
    ull bp1i = pk2(bias[n0+c0+2], bias[n0+c0+3]);
    #pragma unroll
    for (int i = 0; i < 8; i++) { acc[i][0] = bp0i; acc[i][1] = bp1i; }

    for (int k0 = 0; k0 < 256; k0 += 16) {
        float4 av0 = *(const float4*)&A [((size_t)(m0 + lrA))*256 + k0 + lcA];
        float4 av1 = *(const float4*)&A [((size_t)(m0 + lrA))*256 + k0 + lcA + 4];
        float4 bv  = *(const float4*)&Wt[((size_t)(n0 + lrB))*256 + k0 + lcB];
        __syncthreads();
        a_su[(lcA+0)*128 + lrA] = pk2(av0.x, av0.x);
        a_su[(lcA+1)*128 + lrA] = pk2(av0.y, av0.y);
        a_su[(lcA+2)*128 + lrA] = pk2(av0.z, av0.z);
        a_su[(lcA+3)*128 + lrA] = pk2(av0.w, av0.w);
        a_su[(lcA+4)*128 + lrA] = pk2(av1.x, av1.x);
        a_su[(lcA+5)*128 + lrA] = pk2(av1.y, av1.y);
        a_su[(lcA+6)*128 + lrA] = pk2(av1.z, av1.z);
        a_su[(lcA+7)*128 + lrA] = pk2(av1.w, av1.w);
        b_s[lcB+0][lrB] = bv.x;
        b_s[lcB+1][lrB] = bv.y;
        b_s[lcB+2][lrB] = bv.z;
        b_s[lcB+3][lrB] = bv.w;
        __syncthreads();
        #pragma unroll
        for (int kk = 0; kk < 16; kk++) {
            const ulonglong2* ap = (const ulonglong2*)&a_su[kk*128 + r0];
            ulonglong2 a01 = ap[0], a23 = ap[1], a45 = ap[2], a67 = ap[3];
            ulonglong2 bb = *(const ulonglong2*)&b_s[kk][c0];
            fma2(acc[0][0], a01.x, bb.x); fma2(acc[0][1], a01.x, bb.y);
            fma2(acc[1][0], a01.y, bb.x); fma2(acc[1][1], a01.y, bb.y);
            fma2(acc[2][0], a23.x, bb.x); fma2(acc[2][1], a23.x, bb.y);
            fma2(acc[3][0], a23.y, bb.x); fma2(acc[3][1], a23.y, bb.y);
            fma2(acc[4][0], a45.x, bb.x); fma2(acc[4][1], a45.x, bb.y);
            fma2(acc[5][0], a45.y, bb.x); fma2(acc[5][1], a45.y, bb.y);
            fma2(acc[6][0], a67.x, bb.x); fma2(acc[6][1], a67.x, bb.y);
            fma2(acc[7][0], a67.y, bb.x); fma2(acc[7][1], a67.y, bb.y);
        }
    }
    #pragma unroll
    for (int i = 0; i < 8; i++) {
        float4 o;
        upk2(acc[i][0], o.x, o.y);
        upk2(acc[i][1], o.z, o.w);
        o.x = fmaxf(o.x, 0.f); o.y = fmaxf(o.y, 0.f);
        o.z = fmaxf(o.z, 0.f); o.w = fmaxf(o.w, 0.f);
        *(float4*)&C[((size_t)(m0 + r0 + i))*256 + n0 + c0] = o;
    }
}

// ---------------- final 256 -> 3 ----------------------------------------------
__global__ void final_layer(const float* __restrict__ w3,
                            const float* __restrict__ b3,
                            float* __restrict__ out) {
    __shared__ float w3s[3*256];
    int tid = threadIdx.x;
    for (int i = tid; i < 768; i += 256) w3s[i] = w3[i];
    __syncthreads();
    int warp = tid/32, lane = tid%32;
    int m = blockIdx.x * 8 + warp;
    const float* xr = g_X0 + (size_t)m*256;
    float a0 = 0.f, a1 = 0.f, a2 = 0.f;
    #pragma unroll
    for (int j = 0; j < 8; j++) {
        int k = lane + j*32;
        float v = xr[k];
        a0 += v*w3s[k]; a1 += v*w3s[256 + k]; a2 += v*w3s[512 + k];
    }
    #pragma unroll
    for (int off = 16; off; off >>= 1) {
        a0 += __shfl_down_sync(0xffffffffu, a0, off);
        a1 += __shfl_down_sync(0xffffffffu, a1, off);
        a2 += __shfl_down_sync(0xffffffffu, a2, off);
    }
    if (lane == 0) {
        out[(size_t)m*3 + 0] = a0 + b3[0];
        out[(size_t)m*3 + 1] = a1 + b3[1];
        out[(size_t)m*3 + 2] = a2 + b3[2];
    }
}

// ---------------- launch -------------------------------------------------------
extern "C" void kernel_launch(void* const* d_in, const int* in_sizes, int n_in,
                              void* d_out, int out_size) {
    const float* feat    = (const float*)d_in[0];
    const float* coord   = (const float*)d_in[1];
    const float* cell    = (const float*)d_in[2];
    const float* cls_w1  = (const float*)d_in[3];
    const float* cls_b1  = (const float*)d_in[4];
    const float* cls_w2  = (const float*)d_in[5];
    const float* cls_b2  = (const float*)d_in[6];
    const float* sigma_x = (const float*)d_in[7];
    const float* sigma_y = (const float*)d_in[8];
    const float* opacity = (const float*)d_in[9];
    const float* rho     = (const float*)d_in[10];
    const float* coef_w  = (const float*)d_in[11];
    const float* coef_b  = (const float*)d_in[12];
    const float* freq_w  = (const float*)d_in[13];
    const float* freq_b  = (const float*)d_in[14];
    const float* phase_w = (const float*)d_in[15];
    const float* mlp_w1  = (const float*)d_in[16];
    const float* mlp_b1  = (const float*)d_in[17];
    const float* mlp_w2  = (const float*)d_in[18];
    const float* mlp_b2  = (const float*)d_in[19];
    const float* mlp_w3  = (const float*)d_in[20];
    const float* mlp_b3  = (const float*)d_in[21];
    float* out = (float*)d_out;

    cudaFuncSetAttribute(conv112p, cudaFuncAttributeMaxDynamicSharedMemorySize, CONVP_SMEM);
    cudaFuncSetAttribute(conv224w, cudaFuncAttributeMaxDynamicSharedMemorySize, C224_SMEM);
    cudaFuncSetAttribute(splat,    cudaFuncAttributeMaxDynamicSharedMemorySize, SPLAT_SMEM);

    conv112p<<<dim3(49, 4, BB), 256, CONVP_SMEM>>>(feat, cls_w1, cls_b1);
    conv1x1_logits<<<196, 256>>>(cls_w2, cls_b2);
    zero_stats<<<1, 256>>>();
    softmax_stats<<<196, 256>>>(sigma_x, sigma_y, opacity, rho);
    build_ktw<<<1, 256>>>();
    splat<<<1024, 196, SPLAT_SMEM>>>(feat);
    pack_weights<<<320, 256>>>(coef_w, freq_w);
    conv224w<<<dim3(98, BB), 512, C224_SMEM>>>(coef_b, 0);
    conv224w<<<dim3(98, BB), 512, C224_SMEM>>>(freq_b, 1);
    gather_basis<<<MTOT/8, 256>>>(coord, cell, phase_w);
    gemm_relu_p<<<dim3(MTOT/128, 4), 256>>>(mlp_w1, mlp_b1, 0);
    gemm_relu_p<<<dim3(MTOT/128, 4), 256>>>(mlp_w2, mlp_b2, 1);
    final_layer<<<MTOT/8, 256>>>(mlp_w3, mlp_b3, out);
}

// round 6
// speedup vs baseline: 1.5853x; 1.1069x over previous
#include <cuda_runtime.h>
#include <cuda_bf16.h>
#include <math.h>
#include <stdint.h>

#define CIN 64
#define NGRP 100
#define HID 256
#define BB 4
#define HH 112
#define H2 224
#define QQ 50176
#define MTOT (BB*QQ)   // 200704

typedef unsigned long long ull;

__device__ __forceinline__ ull pk2(float a, float b) {
    ull r; asm("mov.b64 %0,{%1,%2};" : "=l"(r) : "f"(a), "f"(b)); return r;
}
__device__ __forceinline__ void fma2(ull& d, ull a, ull b) {
    asm("fma.rn.f32x2 %0,%1,%2,%0;" : "+l"(d) : "l"(a), "l"(b));
}
__device__ __forceinline__ void upk2(ull v, float& a, float& b) {
    asm("mov.b64 {%0,%1},%2;" : "=f"(a), "=f"(b) : "l"(v));
}
__device__ __forceinline__ void cpa16(void* dst, const void* src) {
    unsigned d = (unsigned)__cvta_generic_to_shared(dst);
    asm volatile("cp.async.cg.shared.global [%0], [%1], 16;" :: "r"(d), "l"(src));
}
__device__ __forceinline__ uint32_t lds32(uint32_t a) {
    uint32_t v; asm volatile("ld.shared.b32 %0,[%1];" : "=r"(v) : "r"(a)); return v;
}
__device__ __forceinline__ void mma16816(float* c, uint32_t a0, uint32_t a1, uint32_t a2, uint32_t a3,
                                         uint32_t b0, uint32_t b1) {
    asm volatile("mma.sync.aligned.m16n8k16.row.col.f32.bf16.bf16.f32 "
        "{%0,%1,%2,%3},{%4,%5,%6,%7},{%8,%9},{%0,%1,%2,%3};"
        : "+f"(c[0]), "+f"(c[1]), "+f"(c[2]), "+f"(c[3])
        : "r"(a0), "r"(a1), "r"(a2), "r"(a3), "r"(b0), "r"(b1));
}

// ---------------- scratch -----------------------------------------------------
__device__ float g_h[(size_t)BB*CIN*HH*HH];
__device__ float g_logits[(size_t)BB*NGRP*HH*HH];
__device__ float g_wstat[49*4];
__device__ int   g_ctr;
__device__ float g_ktw[49*196];
__device__ float g_gfeat[(size_t)BB*CIN*H2*H2];
__device__ float g_coef[(size_t)BB*H2*H2*HID];
__device__ float g_freq[(size_t)BB*H2*H2*HID];
__device__ float g_X0[(size_t)MTOT*HID];
__device__ __nv_bfloat16 g_X0h[(size_t)MTOT*HID];
__device__ __nv_bfloat16 g_X0l[(size_t)MTOT*HID];
__device__ __nv_bfloat16 g_X1h[(size_t)MTOT*HID];
__device__ __nv_bfloat16 g_X1l[(size_t)MTOT*HID];
__device__ __align__(16) ull g_wpack[2*32*64*4*10];
__device__ __align__(16) __nv_bfloat16 g_Wh[2][65536];   // mlp weights hi [layer][n*256+k]
__device__ __align__(16) __nv_bfloat16 g_Wl[2][65536];   // mlp weights lo

// ---------------- conv3x3 64->64 @112, relu, NCHW out (packed f32x2) ----------
#define CONVP_SMEM (64*18*18*4 + 64*8*10*8)

__global__ void conv112p(const float* __restrict__ in,
                         const float* __restrict__ w,
                         const float* __restrict__ bias) {
    extern __shared__ float sm[];
    float* ins = sm;
    ull*   wsp = (ull*)(sm + 64*324);
    int tile = blockIdx.x;
    int co0  = blockIdx.y * 16;
    int b    = blockIdx.z;
    int ty0 = (tile / 7) * 16, tx0 = (tile % 7) * 16;
    int tid = threadIdx.x;

    const float* inb = in + (size_t)b * CIN * HH * HH;
    for (int i = tid; i < 64*18*18; i += 256) {
        int ci = i / 324; int r = (i % 324) / 18; int c = i % 18;
        int gy = ty0 + r - 1, gx = tx0 + c - 1;
        float v = 0.f;
        if (gy >= 0 && gy < HH && gx >= 0 && gx < HH) v = inb[(ci*HH + gy)*HH + gx];
        ins[i] = v;
    }
    float* wspf = (float*)wsp;
    for (int i = tid; i < 64*8*9*2; i += 256) {
        int half = i & 1; int e = i >> 1;
        int k = e % 9; int cop = (e/9) & 7; int ci = e/72;
        wspf[((ci*8 + cop)*10 + k)*2 + half] = w[(size_t)(co0 + cop*2 + half)*576 + ci*9 + k];
    }
    __syncthreads();

    int ty = tid / 16, tx = tid % 16;
    ull acc[8];
    #pragma unroll
    for (int cop = 0; cop < 8; cop++) acc[cop] = pk2(bias[co0+2*cop], bias[co0+2*cop+1]);

    for (int ci = 0; ci < 64; ci++) {
        const float* ip = ins + ci*324 + ty*18 + tx;
        ull vv[9];
        #pragma unroll
        for (int dy = 0; dy < 3; dy++)
            #pragma unroll
            for (int dx = 0; dx < 3; dx++) {
                float v = ip[dy*18 + dx];
                vv[dy*3+dx] = pk2(v, v);
            }
        const ull* wbase = wsp + ci*80;
        #pragma unroll
        for (int cop = 0; cop < 8; cop++) {
            const ulonglong2* wc2 = (const ulonglong2*)(wbase + cop*10);
            ulonglong2 p0 = wc2[0], p1 = wc2[1], p2 = wc2[2], p3 = wc2[3];
            ull p8 = (wbase + cop*10)[8];
            fma2(acc[cop], vv[0], p0.x); fma2(acc[cop], vv[1], p0.y);
            fma2(acc[cop], vv[2], p1.x); fma2(acc[cop], vv[3], p1.y);
            fma2(acc[cop], vv[4], p2.x); fma2(acc[cop], vv[5], p2.y);
            fma2(acc[cop], vv[6], p3.x); fma2(acc[cop], vv[7], p3.y);
            fma2(acc[cop], vv[8], p8);
        }
    }
    int oy = ty0 + ty, ox = tx0 + tx;
    #pragma unroll
    for (int cop = 0; cop < 8; cop++) {
        float lo, hi; upk2(acc[cop], lo, hi);
        g_h[(((size_t)b*64 + co0 + 2*cop    )*HH + oy)*HH + ox] = fmaxf(lo, 0.f);
        g_h[(((size_t)b*64 + co0 + 2*cop + 1)*HH + oy)*HH + ox] = fmaxf(hi, 0.f);
    }
}

// ------- 1x1 conv 64->100 (+ zero stats + pack conv224 weights) ---------------
__global__ void conv1x1_logits(const float* __restrict__ w2,
                               const float* __restrict__ b2,
                               const float* __restrict__ wc,
                               const float* __restrict__ wf) {
    __shared__ float ws[NGRP*64];
    int tid = threadIdx.x;
    if (blockIdx.x == 0 && tid < 196) g_wstat[tid] = 0.f;
    for (int i = blockIdx.x*256 + tid; i < 81920; i += 196*256) {
        int k = i % 10; int e = i/10; int cop = e & 3; e >>= 2; int ci = e & 63; int c = e >> 6;
        int co = c*8 + cop*2;
        float a0 = 0.f, b0 = 0.f, a1 = 0.f, b1 = 0.f;
        if (k < 9) {
            size_t idx0 = (size_t)co*576 + ci*9 + k;
            size_t idx1 = (size_t)(co+1)*576 + ci*9 + k;
            a0 = wc[idx0]; b0 = wc[idx1];
            a1 = wf[idx0]; b1 = wf[idx1];
        }
        g_wpack[i]         = pk2(a0, b0);
        g_wpack[81920 + i] = pk2(a1, b1);
    }
    for (int i = tid; i < NGRP*64; i += 256) ws[i] = w2[i];
    __syncthreads();
    int t = blockIdx.x * 256 + tid;
    int b = t / (HH*HH); int pix = t % (HH*HH);
    const float* hp = g_h + (size_t)b*64*HH*HH + pix;
    float hv[64];
    #pragma unroll
    for (int ci = 0; ci < 64; ci++) hv[ci] = hp[(size_t)ci*HH*HH];
    float* lp = g_logits + (size_t)b*NGRP*HH*HH + pix;
    for (int g = 0; g < NGRP; g++) {
        float acc = b2[g];
        const float* wg = ws + g*64;
        #pragma unroll
        for (int ci = 0; ci < 64; ci += 4) {
            float4 wv = *(const float4*)(wg + ci);
            acc += hv[ci]*wv.x + hv[ci+1]*wv.y + hv[ci+2]*wv.z + hv[ci+3]*wv.w;
        }
        lp[(size_t)g*HH*HH] = acc;
    }
}

// ---------------- softmax + stats + (last block) build ktw --------------------
__global__ void softmax_stats(const float* __restrict__ sx, const float* __restrict__ sy,
                              const float* __restrict__ op, const float* __restrict__ rh) {
    __shared__ float sv[4*NGRP];
    __shared__ float accs[196];
    __shared__ float kpad[49*196];
    __shared__ float wops[49];
    __shared__ int lastb;
    int tid = threadIdx.x;
    for (int i = tid; i < NGRP; i += 256) {
        sv[i] = sx[i]; sv[NGRP+i] = sy[i]; sv[2*NGRP+i] = op[i]; sv[3*NGRP+i] = rh[i];
    }
    for (int i = tid; i < 196; i += 256) accs[i] = 0.f;
    __syncthreads();
    int t = blockIdx.x * 256 + tid;
    int b = t / (HH*HH); int pix = t % (HH*HH);
    int y = pix / HH, x = pix % HH;
    const float* lp = g_logits + (size_t)b*NGRP*HH*HH + pix;
    float mx = -1e30f;
    for (int g = 0; g < NGRP; g++) mx = fmaxf(mx, lp[(size_t)g*HH*HH]);
    float s = 0.f, a0 = 0.f, a1 = 0.f, a2 = 0.f, a3 = 0.f;
    for (int g = 0; g < NGRP; g++) {
        float e = expf(lp[(size_t)g*HH*HH] - mx);
        s += e; a0 += e*sv[g]; a1 += e*sv[NGRP+g]; a2 += e*sv[2*NGRP+g]; a3 += e*sv[3*NGRP+g];
    }
    float inv = 1.f / s;
    int p = (y % 7)*7 + (x % 7);
    atomicAdd(&accs[p*4+0], a0*inv);
    atomicAdd(&accs[p*4+1], a1*inv);
    atomicAdd(&accs[p*4+2], a2*inv);
    atomicAdd(&accs[p*4+3], a3*inv);
    __syncthreads();
    for (int i = tid; i < 196; i += 256) atomicAdd(&g_wstat[i], accs[i]);

    __threadfence();
    if (tid == 0) lastb = (atomicAdd(&g_ctr, 1) == (int)gridDim.x - 1);
    __syncthreads();
    if (!lastb) return;
    if (tid == 0) g_ctr = 0;

    for (int i = tid; i < 49*196; i += 256) kpad[i] = 0.f;
    __syncthreads();
    if (tid < 49) {
        int p2 = tid;
        const float inv1024 = 1.f/1024.f;
        float wsx = g_wstat[p2*4+0]*inv1024;
        float wsy = g_wstat[p2*4+1]*inv1024;
        float wop = g_wstat[p2*4+2]*inv1024;
        float wr  = g_wstat[p2*4+3]*inv1024;
        wops[p2] = wop;
        float c00 = wsx*wsx + 1e-5f;
        float c11 = wsy*wsy + 1e-5f;
        float c01 = wr*wsx*wsy;
        float det = c00*c11 - c01*c01;
        float i00 = c11/det, i11 = c00/det, i01 = -c01/det;
        float norm = 1.f/(2.f*3.14159265358979f*sqrtf(det));
        float kv[25]; float kmx = 0.f;
        #pragma unroll
        for (int i = 0; i < 5; i++)
            #pragma unroll
            for (int j = 0; j < 5; j++) {
                float yv = -5.f + 2.5f*i;
                float xv = -5.f + 2.5f*j;
                float z = -0.5f*(i00*xv*xv + 2.f*i01*xv*yv + i11*yv*yv);
                float k = expf(z)*norm;
                kv[i*5+j] = k; kmx = fmaxf(kmx, k);
            }
        float im = 1.f/kmx;
        #pragma unroll
        for (int i = 0; i < 5; i++)
            #pragma unroll
            for (int j = 0; j < 5; j++)
                kpad[p2*196 + (i+4)*14 + (j+4)] = kv[i*5+j]*im;
    }
    __syncthreads();
    for (int idx = tid; idx < 49*196; idx += 256) {
        int p2 = idx/196, hw = idx%196, h = hw/14, w = hw%14;
        float txo = (0.5f - (float)(p2/7)*(1.f/7.f))*2.f;
        float tyo = (0.5f - (float)(p2%7)*(1.f/7.f))*2.f;
        float gxv = -1.f + (2.f/13.f)*w + txo;
        float gyv = -1.f + (2.f/13.f)*h + tyo;
        float px = (gxv + 1.f)*0.5f*13.f;
        float py = (gyv + 1.f)*0.5f*13.f;
        float x0f = floorf(px), y0f = floorf(py);
        int x0 = (int)x0f, y0 = (int)y0f;
        float wx = px - x0f, wy = py - y0f;
        float s00 = (y0   >= 0 && y0   < 14 && x0   >= 0 && x0   < 14) ? kpad[p2*196 + y0*14 + x0]       : 0.f;
        float s01 = (y0   >= 0 && y0   < 14 && x0+1 >= 0 && x0+1 < 14) ? kpad[p2*196 + y0*14 + x0+1]     : 0.f;
        float s10 = (y0+1 >= 0 && y0+1 < 14 && x0   >= 0 && x0   < 14) ? kpad[p2*196 + (y0+1)*14 + x0]   : 0.f;
        float s11 = (y0+1 >= 0 && y0+1 < 14 && x0+1 >= 0 && x0+1 < 14) ? kpad[p2*196 + (y0+1)*14 + x0+1] : 0.f;
        float kt = s00*(1.f-wy)*(1.f-wx) + s01*(1.f-wy)*wx + s10*wy*(1.f-wx) + s11*wy*wx;
        g_ktw[idx] = kt * wops[p2];
    }
}

// ---------------- splat -------------------------------------------------------
#define SPLAT_SMEM ((49*196 + 64*49)*4)
__global__ void splat(const float* __restrict__ feat) {
    extern __shared__ float sm[];
    float* kts = sm;
    float* fp  = sm + 49*196;
    int bl = blockIdx.x;
    int b = bl / 256; int l = bl % 256; int pr = l / 16, pc = l % 16;
    int tid = threadIdx.x;
    for (int i = tid; i < 49*196; i += 196) kts[i] = g_ktw[i];
    const float* fb = feat + (size_t)b*64*HH*HH;
    for (int i = tid; i < 64*49; i += 196) {
        int c = i/49, p = i%49;
        fp[i] = fb[((size_t)c*HH + pr*7 + p/7)*HH + pc*7 + p%7];
    }
    __syncthreads();
    int h = tid/14, w = tid%14;
    int oy = pr*14 + h, ox = pc*14 + w;
    float* outb = g_gfeat + (size_t)b*64*H2*H2;
    for (int c0 = 0; c0 < 64; c0 += 4) {
        float a0 = 0.f, a1 = 0.f, a2 = 0.f, a3 = 0.f;
        #pragma unroll
        for (int p = 0; p < 49; p++) {
            float kv = kts[p*196 + tid];
            a0 += fp[(c0+0)*49 + p]*kv;
            a1 += fp[(c0+1)*49 + p]*kv;
            a2 += fp[(c0+2)*49 + p]*kv;
            a3 += fp[(c0+3)*49 + p]*kv;
        }
        outb[((size_t)(c0+0)*H2 + oy)*H2 + ox] = __saturatef(a0);
        outb[((size_t)(c0+1)*H2 + oy)*H2 + ox] = __saturatef(a1);
        outb[((size_t)(c0+2)*H2 + oy)*H2 + ox] = __saturatef(a2);
        outb[((size_t)(c0+3)*H2 + oy)*H2 + ox] = __saturatef(a3);
    }
}

// ---------------- conv3x3 64->256 @224, NHWC out, resident-input --------------
#define C224_SMEM (64*612*4 + 2*2560*8)
__global__ void conv224w(const float* __restrict__ bias, int sel) {
    extern __shared__ float sm[];
    float* ins = sm;
    ull*  wbuf = (ull*)(sm + 64*612);
    int bt = blockIdx.x;
    int b  = blockIdx.y;
    int row0 = (bt/14)*32, col0 = (bt%14)*16;
    int tid = threadIdx.x;

    const ull* wsrc = g_wpack + (sel ? 81920 : 0);
    for (int i = tid; i < 1280; i += 512)
        cpa16(wbuf + i*2, wsrc + i*2);
    asm volatile("cp.async.commit_group;" ::: "memory");

    const float* inb = g_gfeat + (size_t)b*64*H2*H2;
    for (int i = tid; i < 64*612; i += 512) {
        int ci = i/612; int rr = (i%612)/18; int cc = i%18;
        int gy = row0 + rr - 1, gx = col0 + cc - 1;
        float v = 0.f;
        if (gy >= 0 && gy < H2 && gx >= 0 && gx < H2)
            v = inb[(size_t)ci*(H2*H2) + gy*H2 + gx];
        ins[i] = v;
    }

    int ty = tid >> 4, tx = tid & 15;
    float* outbase = (sel ? g_freq : g_coef)
                   + (((size_t)b*H2 + row0 + ty)*H2 + col0 + tx)*HID;

    for (int c = 0; c < 32; c++) {
        if (c + 1 < 32) {
            const ull* src = wsrc + (c+1)*2560;
            ull* dst = wbuf + ((c+1)&1)*2560;
            for (int i = tid; i < 1280; i += 512)
                cpa16(dst + i*2, src + i*2);
        }
        asm volatile("cp.async.commit_group;" ::: "memory");
        asm volatile("cp.async.wait_group 1;" ::: "memory");
        __syncthreads();

        const ull* wb = wbuf + (c&1)*2560;
        ull acc0 = pk2(bias[c*8+0], bias[c*8+1]);
        ull acc1 = pk2(bias[c*8+2], bias[c*8+3]);
        ull acc2 = pk2(bias[c*8+4], bias[c*8+5]);
        ull acc3 = pk2(bias[c*8+6], bias[c*8+7]);

        for (int ci = 0; ci < 64; ci++) {
            const float* ip = ins + ci*612 + ty*18 + tx;
            ull vv[9];
            #pragma unroll
            for (int dy = 0; dy < 3; dy++)
                #pragma unroll
                for (int dx = 0; dx < 3; dx++) {
                    float v = ip[dy*18 + dx];
                    vv[dy*3+dx] = pk2(v, v);
                }
            const ull* wci = wb + ci*40;
            #pragma unroll
            for (int cop = 0; cop < 4; cop++) {
                const ulonglong2* wc2 = (const ulonglong2*)(wci + cop*10);
                ulonglong2 p0 = wc2[0], p1 = wc2[1], p2 = wc2[2], p3 = wc2[3];
                ull p8 = (wci + cop*10)[8];
                ull* ac = (cop == 0) ? &acc0 : (cop == 1) ? &acc1 : (cop == 2) ? &acc2 : &acc3;
                fma2(*ac, vv[0], p0.x); fma2(*ac, vv[1], p0.y);
                fma2(*ac, vv[2], p1.x); fma2(*ac, vv[3], p1.y);
                fma2(*ac, vv[4], p2.x); fma2(*ac, vv[5], p2.y);
                fma2(*ac, vv[6], p3.x); fma2(*ac, vv[7], p3.y);
                fma2(*ac, vv[8], p8);
            }
        }
        float o[8];
        upk2(acc0, o[0], o[1]); upk2(acc1, o[2], o[3]);
        upk2(acc2, o[4], o[5]); upk2(acc3, o[6], o[7]);
        float* op = outbase + c*8;
        *(float4*)(op)     = make_float4(o[0], o[1], o[2], o[3]);
        *(float4*)(op + 4) = make_float4(o[4], o[5], o[6], o[7]);
        __syncthreads();
    }
}

// ---------------- pack MLP weights (bf16 hi/lo, row-major) --------------------
__global__ void pack_mlp(const float* __restrict__ w1, const float* __restrict__ w2) {
    int i = blockIdx.x*256 + threadIdx.x;   // 0..131071
    int l = i >> 16; int e = i & 65535;
    const float* W = l ? w2 : w1;
    float v = W[e];
    __nv_bfloat16 h = __float2bfloat16(v);
    g_Wh[l][e] = h;
    g_Wl[l][e] = __float2bfloat16(v - __bfloat162float(h));
}

// ---------------- gather + fourier basis -> X0 hi/lo bf16 ---------------------
__global__ void gather_basis(const float* __restrict__ coord,
                             const float* __restrict__ cell,
                             const float* __restrict__ phase_w) {
    int warp = threadIdx.x / 32, lane = threadIdx.x % 32;
    int m = blockIdx.x * 8 + warp;
    int b = m / QQ; int q = m % QQ;
    float cy = coord[((size_t)b*QQ + q)*2 + 0];
    float cx = coord[((size_t)b*QQ + q)*2 + 1];
    int ix = (int)rintf(((cx + 1.f)*(float)H2 - 1.f)*0.5f);
    int iy = (int)rintf(((cy + 1.f)*(float)H2 - 1.f)*0.5f);
    bool ok = (ix >= 0 && ix < H2 && iy >= 0 && iy < H2);
    __nv_bfloat16* xh = g_X0h + (size_t)m*HID;
    __nv_bfloat16* xl = g_X0l + (size_t)m*HID;
    if (!ok) {
        __nv_bfloat16 z = __float2bfloat16(0.f);
        #pragma unroll
        for (int kk = 0; kk < 4; kk++) {
            int k = lane + kk*32;
            xh[k] = z; xh[128+k] = z; xl[k] = z; xl[128+k] = z;
        }
        return;
    }
    float fcy = -1.f + 1.f/(float)H2 + (2.f/(float)H2)*(float)iy;
    float fcx = -1.f + 1.f/(float)H2 + (2.f/(float)H2)*(float)ix;
    float rely = (cy - fcy)*(float)H2;
    float relx = (cx - fcx)*(float)H2;
    float rc0 = cell[((size_t)b*QQ + q)*2 + 0]*(float)H2;
    float rc1 = cell[((size_t)b*QQ + q)*2 + 1]*(float)H2;
    size_t base = (((size_t)b*H2 + iy)*H2 + ix)*HID;
    const float*  cf = g_coef + base;
    const float2* fq = (const float2*)(g_freq + base);
    const float2* pw = (const float2*)phase_w;
    #pragma unroll
    for (int kk = 0; kk < 4; kk++) {
        int k = lane + kk*32;
        float2 f = fq[k];
        float2 p = pw[k];
        float s = f.x*rely + f.y*relx + rc0*p.x + rc1*p.y;
        float v0 = cf[k]       * cospif(s);
        float v1 = cf[128 + k] * sinpif(s);
        __nv_bfloat16 h0 = __float2bfloat16(v0);
        __nv_bfloat16 h1 = __float2bfloat16(v1);
        xh[k]     = h0; xl[k]     = __float2bfloat16(v0 - __bfloat162float(h0));
        xh[128+k] = h1; xl[128+k] = __float2bfloat16(v1 - __bfloat162float(h1));
    }
}

// ---------------- mma.sync bf16 GEMM (3-pass split) + bias + relu -------------
// CTA: M=128, N=128 (grid.y=2). B (weights) smem-resident hi+lo (128 KB).
// A streamed in k-chunks of 64, double-buffered cp.async (2x32 KB).
#define GM_BB 0
#define GM_AB 131072
#define GM_SMEM 196608

__global__ void __launch_bounds__(256, 1) gemm_mma(const float* __restrict__ bias, int layer) {
    extern __shared__ __align__(16) char smc[];
    __shared__ float sbias[128];
    uint32_t sb;
    asm("{ .reg .u64 t; cvta.to.shared.u64 t, %1; cvt.u32.u64 %0, t; }" : "=r"(sb) : "l"(smc));
    int tid = threadIdx.x, wid = tid >> 5, lane = tid & 31;
    int grp = lane >> 2, t4 = lane & 3;
    int m0 = blockIdx.x * 128;
    int n0 = blockIdx.y * 128;
    int wm = wid >> 1, wn = wid & 1;          // warp tile 32M x 64N
    int mb = wm * 32, nb = wn * 64;

    const __nv_bfloat16* Ah = layer ? g_X1h : g_X0h;
    const __nv_bfloat16* Al = layer ? g_X1l : g_X0l;
    const __nv_bfloat16* Wh = g_Wh[layer];
    const __nv_bfloat16* Wl = g_Wl[layer];

    // B: [hi|lo][n(128)][k 512B], swizzle ((j*16) ^ ((n&7)<<4))
    for (int i = tid; i < 8192; i += 256) {
        int half = i >> 12; int rem = i & 4095; int n = rem >> 5; int j = rem & 31;
        const __nv_bfloat16* src = (half ? Wl : Wh) + (size_t)(n0 + n)*256 + j*8;
        cpa16(smc + GM_BB + half*65536 + n*512 + ((j*16) ^ ((n&7)<<4)), src);
    }
    // A chunk 0: [buf][hi|lo][m(128)][k 128B], swizzle ((j*16) ^ ((m&7)<<4))
    for (int i = tid; i < 2048; i += 256) {
        int half = i >> 10; int rem = i & 1023; int m = rem >> 3; int j = rem & 7;
        const __nv_bfloat16* src = (half ? Al : Ah) + (size_t)(m0 + m)*256 + j*8;
        cpa16(smc + GM_AB + half*16384 + m*128 + ((j*16) ^ ((m&7)<<4)), src);
    }
    asm volatile("cp.async.commit_group;" ::: "memory");
    if (tid < 128) sbias[tid] = bias[n0 + tid];

    float acc[2][8][4];
    #pragma unroll
    for (int t = 0; t < 2; t++)
        #pragma unroll
        for (int u = 0; u < 8; u++)
            #pragma unroll
            for (int j = 0; j < 4; j++) acc[t][u][j] = 0.f;

    uint32_t swz = (uint32_t)(grp << 4);
    uint32_t t4x4 = (uint32_t)(t4 * 4);
    uint32_t bB = sb + GM_BB;

    for (int c = 0; c < 4; c++) {
        if (c < 3) {
            int cn = c + 1;
            char* dstb = smc + GM_AB + (cn & 1)*32768;
            for (int i = tid; i < 2048; i += 256) {
                int half = i >> 10; int rem = i & 1023; int m = rem >> 3; int j = rem & 7;
                const __nv_bfloat16* src = (half ? Al : Ah) + (size_t)(m0 + m)*256 + cn*64 + j*8;
                cpa16(dstb + half*16384 + m*128 + ((j*16) ^ ((m&7)<<4)), src);
            }
            asm volatile("cp.async.commit_group;" ::: "memory");
            asm volatile("cp.async.wait_group 1;" ::: "memory");
        } else {
            asm volatile("cp.async.wait_group 0;" ::: "memory");
        }
        __syncthreads();

        uint32_t bA = sb + GM_AB + (c & 1)*32768;
        #pragma unroll
        for (int ks = 0; ks < 4; ks++) {
            uint32_t ko  = (((uint32_t)(ks*32)) ^ swz) + t4x4;
            uint32_t koh = (((uint32_t)(ks*32+16)) ^ swz) + t4x4;
            uint32_t ahf[2][4], alf[2][4], bhf[8][2], blf[8][2];
            #pragma unroll
            for (int t = 0; t < 2; t++) {
                uint32_t ra = bA + (uint32_t)((mb + t*16 + grp)*128);
                ahf[t][0] = lds32(ra + ko);
                ahf[t][1] = lds32(ra + 1024 + ko);
                ahf[t][2] = lds32(ra + koh);
                ahf[t][3] = lds32(ra + 1024 + koh);
                alf[t][0] = lds32(ra + 16384 + ko);
                alf[t][1] = lds32(ra + 16384 + 1024 + ko);
                alf[t][2] = lds32(ra + 16384 + koh);
                alf[t][3] = lds32(ra + 16384 + 1024 + koh);
            }
            uint32_t kob  = (((uint32_t)(c*128 + ks*32)) ^ swz) + t4x4;
            uint32_t kobh = (((uint32_t)(c*128 + ks*32+16)) ^ swz) + t4x4;
            #pragma unroll
            for (int u = 0; u < 8; u++) {
                uint32_t rb = bB + (uint32_t)((nb + u*8 + grp)*512);
                bhf[u][0] = lds32(rb + kob);
                bhf[u][1] = lds32(rb + kobh);
                blf[u][0] = lds32(rb + 65536 + kob);
                blf[u][1] = lds32(rb + 65536 + kobh);
            }
            #pragma unroll
            for (int t = 0; t < 2; t++)
                #pragma unroll
                for (int u = 0; u < 8; u++)
                    mma16816(acc[t][u], ahf[t][0], ahf[t][1], ahf[t][2], ahf[t][3], bhf[u][0], bhf[u][1]);
            #pragma unroll
            for (int t = 0; t < 2; t++)
                #pragma unroll
                for (int u = 0; u < 8; u++)
                    mma16816(acc[t][u], ahf[t][0], ahf[t][1], ahf[t][2], ahf[t][3], blf[u][0], blf[u][1]);
            #pragma unroll
            for (int t = 0; t < 2; t++)
                #pragma unroll
                for (int u = 0; u < 8; u++)
                    mma16816(acc[t][u], alf[t][0], alf[t][1], alf[t][2], alf[t][3], bhf[u][0], bhf[u][1]);
        }
        __syncthreads();
    }

    // epilogue
    #pragma unroll
    for (int t = 0; t < 2; t++) {
        int r0 = m0 + mb + t*16 + grp;
        int r1 = r0 + 8;
        #pragma unroll
        for (int u = 0; u < 8; u++) {
            int cb = nb + u*8 + t4*2;
            float b0v = sbias[cb], b1v = sbias[cb+1];
            float v00 = fmaxf(acc[t][u][0] + b0v, 0.f);
            float v01 = fmaxf(acc[t][u][1] + b1v, 0.f);
            float v10 = fmaxf(acc[t][u][2] + b0v, 0.f);
            float v11 = fmaxf(acc[t][u][3] + b1v, 0.f);
            int gcol = n0 + cb;
            if (layer == 0) {
                __nv_bfloat162 h0 = __float22bfloat162_rn(make_float2(v00, v01));
                __nv_bfloat162 h1 = __float22bfloat162_rn(make_float2(v10, v11));
                __nv_bfloat162 l0, l1;
                l0.x = __float2bfloat16(v00 - __bfloat162float(h0.x));
                l0.y = __float2bfloat16(v01 - __bfloat162float(h0.y));
                l1.x = __float2bfloat16(v10 - __bfloat162float(h1.x));
                l1.y = __float2bfloat16(v11 - __bfloat162float(h1.y));
                *(__nv_bfloat162*)&g_X1h[(size_t)r0*256 + gcol] = h0;
                *(__nv_bfloat162*)&g_X1h[(size_t)r1*256 + gcol] = h1;
                *(__nv_bfloat162*)&g_X1l[(size_t)r0*256 + gcol] = l0;
                *(__nv_bfloat162*)&g_X1l[(size_t)r1*256 + gcol] = l1;
            } else {
                *(float2*)&g_X0[(size_t)r0*256 + gcol] = make_float2(v00, v01);
                *(float2*)&g_X0[(size_t)r1*256 + gcol] = make_float2(v10, v11);
            }
        }
    }
}

// ---------------- final 256 -> 3 ----------------------------------------------
__global__ void final_layer(const float* __restrict__ w3,
                            const float* __restrict__ b3,
                            float* __restrict__ out) {
    __shared__ float w3s[3*256];
    int tid = threadIdx.x;
    for (int i = tid; i < 768; i += 256) w3s[i] = w3[i];
    __syncthreads();
    int warp = tid/32, lane = tid%32;
    int m = blockIdx.x * 8 + warp;
    const float* xr = g_X0 + (size_t)m*256;
    float a0 = 0.f, a1 = 0.f, a2 = 0.f;
    #pragma unroll
    for (int j = 0; j < 8; j++) {
        int k = lane + j*32;
        float v = xr[k];
        a0 += v*w3s[k]; a1 += v*w3s[256 + k]; a2 += v*w3s[512 + k];
    }
    #pragma unroll
    for (int off = 16; off; off >>= 1) {
        a0 += __shfl_down_sync(0xffffffffu, a0, off);
        a1 += __shfl_down_sync(0xffffffffu, a1, off);
        a2 += __shfl_down_sync(0xffffffffu, a2, off);
    }
    if (lane == 0) {
        out[(size_t)m*3 + 0] = a0 + b3[0];
        out[(size_t)m*3 + 1] = a1 + b3[1];
        out[(size_t)m*3 + 2] = a2 + b3[2];
    }
}

// ---------------- launch -------------------------------------------------------
extern "C" void kernel_launch(void* const* d_in, const int* in_sizes, int n_in,
                              void* d_out, int out_size) {
    const float* feat    = (const float*)d_in[0];
    const float* coord   = (const float*)d_in[1];
    const float* cell    = (const float*)d_in[2];
    const float* cls_w1  = (const float*)d_in[3];
    const float* cls_b1  = (const float*)d_in[4];
    const float* cls_w2  = (const float*)d_in[5];
    const float* cls_b2  = (const float*)d_in[6];
    const float* sigma_x = (const float*)d_in[7];
    const float* sigma_y = (const float*)d_in[8];
    const float* opacity = (const float*)d_in[9];
    const float* rho     = (const float*)d_in[10];
    const float* coef_w  = (const float*)d_in[11];
    const float* coef_b  = (const float*)d_in[12];
    const float* freq_w  = (const float*)d_in[13];
    const float* freq_b  = (const float*)d_in[14];
    const float* phase_w = (const float*)d_in[15];
    const float* mlp_w1  = (const float*)d_in[16];
    const float* mlp_b1  = (const float*)d_in[17];
    const float* mlp_w2  = (const float*)d_in[18];
    const float* mlp_b2  = (const float*)d_in[19];
    const float* mlp_w3  = (const float*)d_in[20];
    const float* mlp_b3  = (const float*)d_in[21];
    float* out = (float*)d_out;

    cudaFuncSetAttribute(conv112p, cudaFuncAttributeMaxDynamicSharedMemorySize, CONVP_SMEM);
    cudaFuncSetAttribute(conv224w, cudaFuncAttributeMaxDynamicSharedMemorySize, C224_SMEM);
    cudaFuncSetAttribute(splat,    cudaFuncAttributeMaxDynamicSharedMemorySize, SPLAT_SMEM);
    cudaFuncSetAttribute(gemm_mma, cudaFuncAttributeMaxDynamicSharedMemorySize, GM_SMEM);

    conv112p<<<dim3(49, 4, BB), 256, CONVP_SMEM>>>(feat, cls_w1, cls_b1);          // #1
    conv1x1_logits<<<196, 256>>>(cls_w2, cls_b2, coef_w, freq_w);                  // #2
    softmax_stats<<<196, 256>>>(sigma_x, sigma_y, opacity, rho);                   // #3
    splat<<<1024, 196, SPLAT_SMEM>>>(feat);                                        // #4
    conv224w<<<dim3(98, BB), 512, C224_SMEM>>>(coef_b, 0);                         // #5
    conv224w<<<dim3(98, BB), 512, C224_SMEM>>>(freq_b, 1);                         // #6
    pack_mlp<<<512, 256>>>(mlp_w1, mlp_w2);                                        // #7
    gather_basis<<<MTOT/8, 256>>>(coord, cell, phase_w);                           // #8
    gemm_mma<<<dim3(MTOT/128, 2), 256, GM_SMEM>>>(mlp_b1, 0);                      // #9
    gemm_mma<<<dim3(MTOT/128, 2), 256, GM_SMEM>>>(mlp_b2, 1);                      // #10
    final_layer<<<MTOT/8, 256>>>(mlp_w3, mlp_b3, out);                             // #11
}

// round 7
// speedup vs baseline: 5.7690x; 3.6390x over previous
#include <cuda_runtime.h>
#include <cuda_bf16.h>
#include <math.h>
#include <stdint.h>

#define CIN 64
#define NGRP 100
#define HID 256
#define BB 4
#define HH 112
#define H2 224
#define QQ 50176
#define MTOT (BB*QQ)   // 200704

typedef unsigned long long ull;

__device__ __forceinline__ ull pk2(float a, float b) {
    ull r; asm("mov.b64 %0,{%1,%2};" : "=l"(r) : "f"(a), "f"(b)); return r;
}
__device__ __forceinline__ void fma2(ull& d, ull a, ull b) {
    asm("fma.rn.f32x2 %0,%1,%2,%0;" : "+l"(d) : "l"(a), "l"(b));
}
__device__ __forceinline__ void upk2(ull v, float& a, float& b) {
    asm("mov.b64 {%0,%1},%2;" : "=f"(a), "=f"(b) : "l"(v));
}
__device__ __forceinline__ void cpa16(void* dst, const void* src) {
    unsigned d = (unsigned)__cvta_generic_to_shared(dst);
    asm volatile("cp.async.cg.shared.global [%0], [%1], 16;" :: "r"(d), "l"(src));
}
__device__ __forceinline__ void cpa16z(void* dst, const void* src, int sz) {
    unsigned d = (unsigned)__cvta_generic_to_shared(dst);
    asm volatile("cp.async.cg.shared.global [%0], [%1], 16, %2;" :: "r"(d), "l"(src), "r"(sz));
}
__device__ __forceinline__ uint32_t lds32(uint32_t a) {
    uint32_t v; asm volatile("ld.shared.b32 %0,[%1];" : "=r"(v) : "r"(a)); return v;
}
__device__ __forceinline__ void mma16816(float* c, uint32_t a0, uint32_t a1, uint32_t a2, uint32_t a3,
                                         uint32_t b0, uint32_t b1) {
    asm volatile("mma.sync.aligned.m16n8k16.row.col.f32.bf16.bf16.f32 "
        "{%0,%1,%2,%3},{%4,%5,%6,%7},{%8,%9},{%0,%1,%2,%3};"
        : "+f"(c[0]), "+f"(c[1]), "+f"(c[2]), "+f"(c[3])
        : "r"(a0), "r"(a1), "r"(a2), "r"(a3), "r"(b0), "r"(b1));
}

// ---------------- scratch -----------------------------------------------------
__device__ float g_h[(size_t)BB*CIN*HH*HH];
__device__ float g_logits[(size_t)BB*NGRP*HH*HH];
__device__ float g_wstat[49*4];
__device__ int   g_ctr;
__device__ float g_ktw[49*196];
__device__ __align__(16) __nv_bfloat16 g_gfh[(size_t)BB*H2*H2*64];  // NHWC hi
__device__ __align__(16) __nv_bfloat16 g_gfl[(size_t)BB*H2*H2*64];  // NHWC lo
__device__ float g_coef[(size_t)BB*H2*H2*HID];
__device__ float g_freq[(size_t)BB*H2*H2*HID];
__device__ float g_X0[(size_t)MTOT*HID];
__device__ __nv_bfloat16 g_X0h[(size_t)MTOT*HID];
__device__ __nv_bfloat16 g_X0l[(size_t)MTOT*HID];
__device__ __nv_bfloat16 g_X1h[(size_t)MTOT*HID];
__device__ __nv_bfloat16 g_X1l[(size_t)MTOT*HID];
__device__ __align__(16) unsigned char g_cw[(size_t)2*2*9*32768];   // conv224 bf16 hi/lo swizzled
__device__ __align__(16) __nv_bfloat16 g_Wh[2][65536];
__device__ __align__(16) __nv_bfloat16 g_Wl[2][65536];

// ---------------- conv3x3 64->64 @112, relu, NCHW out (packed f32x2) ----------
#define CONVP_SMEM (64*18*18*4 + 64*8*10*8)

__global__ void conv112p(const float* __restrict__ in,
                         const float* __restrict__ w,
                         const float* __restrict__ bias) {
    extern __shared__ float sm[];
    float* ins = sm;
    ull*   wsp = (ull*)(sm + 64*324);
    int tile = blockIdx.x;
    int co0  = blockIdx.y * 16;
    int b    = blockIdx.z;
    int ty0 = (tile / 7) * 16, tx0 = (tile % 7) * 16;
    int tid = threadIdx.x;

    const float* inb = in + (size_t)b * CIN * HH * HH;
    for (int i = tid; i < 64*18*18; i += 256) {
        int ci = i / 324; int r = (i % 324) / 18; int c = i % 18;
        int gy = ty0 + r - 1, gx = tx0 + c - 1;
        float v = 0.f;
        if (gy >= 0 && gy < HH && gx >= 0 && gx < HH) v = inb[(ci*HH + gy)*HH + gx];
        ins[i] = v;
    }
    float* wspf = (float*)wsp;
    for (int i = tid; i < 64*8*9*2; i += 256) {
        int half = i & 1; int e = i >> 1;
        int k = e % 9; int cop = (e/9) & 7; int ci = e/72;
        wspf[((ci*8 + cop)*10 + k)*2 + half] = w[(size_t)(co0 + cop*2 + half)*576 + ci*9 + k];
    }
    __syncthreads();

    int ty = tid / 16, tx = tid % 16;
    ull acc[8];
    #pragma unroll
    for (int cop = 0; cop < 8; cop++) acc[cop] = pk2(bias[co0+2*cop], bias[co0+2*cop+1]);

    for (int ci = 0; ci < 64; ci++) {
        const float* ip = ins + ci*324 + ty*18 + tx;
        ull vv[9];
        #pragma unroll
        for (int dy = 0; dy < 3; dy++)
            #pragma unroll
            for (int dx = 0; dx < 3; dx++) {
                float v = ip[dy*18 + dx];
                vv[dy*3+dx] = pk2(v, v);
            }
        const ull* wbase = wsp + ci*80;
        #pragma unroll
        for (int cop = 0; cop < 8; cop++) {
            const ulonglong2* wc2 = (const ulonglong2*)(wbase + cop*10);
            ulonglong2 p0 = wc2[0], p1 = wc2[1], p2 = wc2[2], p3 = wc2[3];
            ull p8 = (wbase + cop*10)[8];
            fma2(acc[cop], vv[0], p0.x); fma2(acc[cop], vv[1], p0.y);
            fma2(acc[cop], vv[2], p1.x); fma2(acc[cop], vv[3], p1.y);
            fma2(acc[cop], vv[4], p2.x); fma2(acc[cop], vv[5], p2.y);
            fma2(acc[cop], vv[6], p3.x); fma2(acc[cop], vv[7], p3.y);
            fma2(acc[cop], vv[8], p8);
        }
    }
    int oy = ty0 + ty, ox = tx0 + tx;
    #pragma unroll
    for (int cop = 0; cop < 8; cop++) {
        float lo, hi; upk2(acc[cop], lo, hi);
        g_h[(((size_t)b*64 + co0 + 2*cop    )*HH + oy)*HH + ox] = fmaxf(lo, 0.f);
        g_h[(((size_t)b*64 + co0 + 2*cop + 1)*HH + oy)*HH + ox] = fmaxf(hi, 0.f);
    }
}

// ------- pack conv224 weights: bf16 hi/lo, per-tap [co128][ci64] swizzled -----
__global__ void pack_cw(const float* __restrict__ wc, const float* __restrict__ wf) {
    int i = blockIdx.x*256 + threadIdx.x;   // 0..294911
    if (i >= 294912) return;
    int ci = i & 63; int t = i >> 6;
    int co = t & 127; t >>= 7;
    int dydx = t % 9; t /= 9;
    int half = t & 1; int sel = t >> 1;
    const float* W = sel ? wf : wc;
    float v = W[(size_t)(half*128 + co)*576 + ci*9 + dydx];
    __nv_bfloat16 h = __float2bfloat16(v);
    __nv_bfloat16 l = __float2bfloat16(v - __bfloat162float(h));
    size_t base = ((size_t)((sel*2 + half)*9 + dydx))*32768;
    uint32_t off = (uint32_t)co*128 + (((uint32_t)(ci>>3)*16) ^ (((uint32_t)co&7)<<4)) + (ci&7)*2;
    *(__nv_bfloat16*)(g_cw + base + off)         = h;
    *(__nv_bfloat16*)(g_cw + base + 16384 + off) = l;
}

// ------- 1x1 conv 64->100 (+ zero stats) --------------------------------------
__global__ void conv1x1_logits(const float* __restrict__ w2,
                               const float* __restrict__ b2) {
    __shared__ float ws[NGRP*64];
    int tid = threadIdx.x;
    if (blockIdx.x == 0 && tid < 196) g_wstat[tid] = 0.f;
    for (int i = tid; i < NGRP*64; i += 256) ws[i] = w2[i];
    __syncthreads();
    int t = blockIdx.x * 256 + tid;
    int b = t / (HH*HH); int pix = t % (HH*HH);
    const float* hp = g_h + (size_t)b*64*HH*HH + pix;
    float hv[64];
    #pragma unroll
    for (int ci = 0; ci < 64; ci++) hv[ci] = hp[(size_t)ci*HH*HH];
    float* lp = g_logits + (size_t)b*NGRP*HH*HH + pix;
    for (int g = 0; g < NGRP; g++) {
        float acc = b2[g];
        const float* wg = ws + g*64;
        #pragma unroll
        for (int ci = 0; ci < 64; ci += 4) {
            float4 wv = *(const float4*)(wg + ci);
            acc += hv[ci]*wv.x + hv[ci+1]*wv.y + hv[ci+2]*wv.z + hv[ci+3]*wv.w;
        }
        lp[(size_t)g*HH*HH] = acc;
    }
}

// ---------------- softmax + stats + (last block) build ktw --------------------
__global__ void softmax_stats(const float* __restrict__ sx, const float* __restrict__ sy,
                              const float* __restrict__ op, const float* __restrict__ rh) {
    __shared__ float sv[4*NGRP];
    __shared__ float accs[196];
    __shared__ float kpad[49*196];
    __shared__ float wops[49];
    __shared__ int lastb;
    int tid = threadIdx.x;
    for (int i = tid; i < NGRP; i += 256) {
        sv[i] = sx[i]; sv[NGRP+i] = sy[i]; sv[2*NGRP+i] = op[i]; sv[3*NGRP+i] = rh[i];
    }
    for (int i = tid; i < 196; i += 256) accs[i] = 0.f;
    __syncthreads();
    int t = blockIdx.x * 256 + tid;
    int b = t / (HH*HH); int pix = t % (HH*HH);
    int y = pix / HH, x = pix % HH;
    const float* lp = g_logits + (size_t)b*NGRP*HH*HH + pix;
    float mx = -1e30f;
    for (int g = 0; g < NGRP; g++) mx = fmaxf(mx, lp[(size_t)g*HH*HH]);
    float s = 0.f, a0 = 0.f, a1 = 0.f, a2 = 0.f, a3 = 0.f;
    for (int g = 0; g < NGRP; g++) {
        float e = expf(lp[(size_t)g*HH*HH] - mx);
        s += e; a0 += e*sv[g]; a1 += e*sv[NGRP+g]; a2 += e*sv[2*NGRP+g]; a3 += e*sv[3*NGRP+g];
    }
    float inv = 1.f / s;
    int p = (y % 7)*7 + (x % 7);
    atomicAdd(&accs[p*4+0], a0*inv);
    atomicAdd(&accs[p*4+1], a1*inv);
    atomicAdd(&accs[p*4+2], a2*inv);
    atomicAdd(&accs[p*4+3], a3*inv);
    __syncthreads();
    for (int i = tid; i < 196; i += 256) atomicAdd(&g_wstat[i], accs[i]);

    __threadfence();
    if (tid == 0) lastb = (atomicAdd(&g_ctr, 1) == (int)gridDim.x - 1);
    __syncthreads();
    if (!lastb) return;
    if (tid == 0) g_ctr = 0;

    for (int i = tid; i < 49*196; i += 256) kpad[i] = 0.f;
    __syncthreads();
    if (tid < 49) {
        int p2 = tid;
        const float inv1024 = 1.f/1024.f;
        float wsx = g_wstat[p2*4+0]*inv1024;
        float wsy = g_wstat[p2*4+1]*inv1024;
        float wop = g_wstat[p2*4+2]*inv1024;
        float wr  = g_wstat[p2*4+3]*inv1024;
        wops[p2] = wop;
        float c00 = wsx*wsx + 1e-5f;
        float c11 = wsy*wsy + 1e-5f;
        float c01 = wr*wsx*wsy;
        float det = c00*c11 - c01*c01;
        float i00 = c11/det, i11 = c00/det, i01 = -c01/det;
        float norm = 1.f/(2.f*3.14159265358979f*sqrtf(det));
        float kv[25]; float kmx = 0.f;
        #pragma unroll
        for (int i = 0; i < 5; i++)
            #pragma unroll
            for (int j = 0; j < 5; j++) {
                float yv = -5.f + 2.5f*i;
                float xv = -5.f + 2.5f*j;
                float z = -0.5f*(i00*xv*xv + 2.f*i01*xv*yv + i11*yv*yv);
                float k = expf(z)*norm;
                kv[i*5+j] = k; kmx = fmaxf(kmx, k);
            }
        float im = 1.f/kmx;
        #pragma unroll
        for (int i = 0; i < 5; i++)
            #pragma unroll
            for (int j = 0; j < 5; j++)
                kpad[p2*196 + (i+4)*14 + (j+4)] = kv[i*5+j]*im;
    }
    __syncthreads();
    for (int idx = tid; idx < 49*196; idx += 256) {
        int p2 = idx/196, hw = idx%196, h = hw/14, w = hw%14;
        float txo = (0.5f - (float)(p2/7)*(1.f/7.f))*2.f;
        float tyo = (0.5f - (float)(p2%7)*(1.f/7.f))*2.f;
        float gxv = -1.f + (2.f/13.f)*w + txo;
        float gyv = -1.f + (2.f/13.f)*h + tyo;
        float px = (gxv + 1.f)*0.5f*13.f;
        float py = (gyv + 1.f)*0.5f*13.f;
        float x0f = floorf(px), y0f = floorf(py);
        int x0 = (int)x0f, y0 = (int)y0f;
        float wx = px - x0f, wy = py - y0f;
        float s00 = (y0   >= 0 && y0   < 14 && x0   >= 0 && x0   < 14) ? kpad[p2*196 + y0*14 + x0]       : 0.f;
        float s01 = (y0   >= 0 && y0   < 14 && x0+1 >= 0 && x0+1 < 14) ? kpad[p2*196 + y0*14 + x0+1]     : 0.f;
        float s10 = (y0+1 >= 0 && y0+1 < 14 && x0   >= 0 && x0   < 14) ? kpad[p2*196 + (y0+1)*14 + x0]   : 0.f;
        float s11 = (y0+1 >= 0 && y0+1 < 14 && x0+1 >= 0 && x0+1 < 14) ? kpad[p2*196 + (y0+1)*14 + x0+1] : 0.f;
        float kt = s00*(1.f-wy)*(1.f-wx) + s01*(1.f-wy)*wx + s10*wy*(1.f-wx) + s11*wy*wx;
        g_ktw[idx] = kt * wops[p2];
    }
}

// ---------------- splat -> NHWC bf16 hi/lo ------------------------------------
#define SPLAT_SMEM ((49*196 + 64*49)*4)
__global__ void splat(const float* __restrict__ feat) {
    extern __shared__ float sm[];
    float* kts = sm;
    float* fp  = sm + 49*196;
    int bl = blockIdx.x;
    int b = bl / 256; int l = bl % 256; int pr = l / 16, pc = l % 16;
    int tid = threadIdx.x;
    for (int i = tid; i < 49*196; i += 196) kts[i] = g_ktw[i];
    const float* fb = feat + (size_t)b*64*HH*HH;
    for (int i = tid; i < 64*49; i += 196) {
        int c = i/49, p = i%49;
        fp[i] = fb[((size_t)c*HH + pr*7 + p/7)*HH + pc*7 + p%7];
    }
    __syncthreads();
    int h = tid/14, w = tid%14;
    int oy = pr*14 + h, ox = pc*14 + w;
    size_t pixb = ((size_t)b*H2 + oy)*H2 + ox;
    __nv_bfloat16* gh = g_gfh + pixb*64;
    __nv_bfloat16* gl = g_gfl + pixb*64;
    for (int c0 = 0; c0 < 64; c0 += 4) {
        float a0 = 0.f, a1 = 0.f, a2 = 0.f, a3 = 0.f;
        #pragma unroll
        for (int p = 0; p < 49; p++) {
            float kv = kts[p*196 + tid];
            a0 += fp[(c0+0)*49 + p]*kv;
            a1 += fp[(c0+1)*49 + p]*kv;
            a2 += fp[(c0+2)*49 + p]*kv;
            a3 += fp[(c0+3)*49 + p]*kv;
        }
        a0 = __saturatef(a0); a1 = __saturatef(a1);
        a2 = __saturatef(a2); a3 = __saturatef(a3);
        __nv_bfloat16 h0 = __float2bfloat16(a0), h1 = __float2bfloat16(a1);
        __nv_bfloat16 h2 = __float2bfloat16(a2), h3 = __float2bfloat16(a3);
        *(__nv_bfloat162*)(gh + c0)     = __halves2bfloat162(h0, h1);
        *(__nv_bfloat162*)(gh + c0 + 2) = __halves2bfloat162(h2, h3);
        *(__nv_bfloat162*)(gl + c0)     = __halves2bfloat162(
            __float2bfloat16(a0 - __bfloat162float(h0)),
            __float2bfloat16(a1 - __bfloat162float(h1)));
        *(__nv_bfloat162*)(gl + c0 + 2) = __halves2bfloat162(
            __float2bfloat16(a2 - __bfloat162float(h2)),
            __float2bfloat16(a3 - __bfloat162float(h3)));
    }
}

// ---------------- conv3x3 64->256 @224 via mma.sync (9 shift-GEMMs) -----------
// CTA: 16x16 pixels (M=256) x 128 co. 512 threads / 16 warps (warp 32M x 64N).
// A: halo 18x18 x 64ci bf16 hi+lo resident (83KB). W: per-tap 32KB double-buffered.
#define CM_ALO   41472
#define CM_WBASE 82944
#define CM_WBUF  32768
#define CM_SMEM  148480

__global__ void __launch_bounds__(512, 1) conv224m(const float* __restrict__ bias, int sel) {
    extern __shared__ __align__(16) char smc[];
    __shared__ float sbias[128];
    uint32_t sb;
    asm("{ .reg .u64 t; cvta.to.shared.u64 t, %1; cvt.u32.u64 %0, t; }" : "=r"(sb) : "l"(smc));
    int tid = threadIdx.x, wid = tid >> 5, lane = tid & 31;
    int grp = lane >> 2, t4 = lane & 3;
    int bt = blockIdx.x, cohalf = blockIdx.y, b = blockIdx.z;
    int row0 = (bt/14)*16, col0 = (bt%14)*16;
    int wm = wid >> 1, wn = wid & 1;
    int nb = wn*64;

    const __nv_bfloat16* gh = g_gfh + (size_t)b*H2*H2*64;
    const __nv_bfloat16* gl = g_gfl + (size_t)b*H2*H2*64;
    const unsigned char* wsrc = g_cw + (size_t)(sel*2 + cohalf)*9*32768;

    // weight tap 0
    for (int i = tid; i < 2048; i += 512)
        cpa16(smc + CM_WBASE + i*16, wsrc + i*16);
    // A tile (hi then lo), swizzled 16B chunks, zero-fill OOB halo
    for (int i = tid; i < 5184; i += 512) {
        int hlf = i >= 2592; int e = hlf ? i - 2592 : i;
        int pos = e >> 3, j = e & 7;
        int r = pos / 18, c = pos - r*18;
        int gy = row0 + r - 1, gx = col0 + c - 1;
        int ok = (gy >= 0 && gy < H2 && gx >= 0 && gx < H2);
        const __nv_bfloat16* src = (hlf ? gl : gh) + ((size_t)(ok ? gy : 0)*H2 + (ok ? gx : 0))*64 + j*8;
        cpa16z(smc + (hlf ? CM_ALO : 0) + (r*18 + c)*128 + (((uint32_t)j*16) ^ (((uint32_t)c&7)<<4)),
               src, ok ? 16 : 0);
    }
    asm volatile("cp.async.commit_group;" ::: "memory");
    if (tid < 128) sbias[tid] = bias[cohalf*128 + tid];

    float acc[2][8][4];
    #pragma unroll
    for (int t = 0; t < 2; t++)
        #pragma unroll
        for (int u = 0; u < 8; u++)
            #pragma unroll
            for (int j = 0; j < 4; j++) acc[t][u][j] = 0.f;

    uint32_t swzb = (uint32_t)(grp << 4);
    uint32_t t4x4 = (uint32_t)(t4*4);

    for (int dydx = 0; dydx < 9; dydx++) {
        if (dydx < 8) {
            const unsigned char* src = wsrc + (size_t)(dydx+1)*32768;
            char* dst = smc + CM_WBASE + ((dydx+1)&1)*CM_WBUF;
            for (int i = tid; i < 2048; i += 512)
                cpa16(dst + i*16, src + i*16);
            asm volatile("cp.async.commit_group;" ::: "memory");
            asm volatile("cp.async.wait_group 1;" ::: "memory");
        } else {
            asm volatile("cp.async.wait_group 0;" ::: "memory");
        }
        __syncthreads();

        int dy = dydx/3, dx = dydx - dy*3;
        uint32_t wb = sb + CM_WBASE + (uint32_t)((dydx&1)*CM_WBUF);
        uint32_t swza = (uint32_t)(((grp + dx) & 7) << 4);
        uint32_t aRow0 = sb + (uint32_t)(((wm*2 + dy)*18 + grp + dx)*128);
        uint32_t aRow1 = aRow0 + 18*128;

        #pragma unroll
        for (int ks = 0; ks < 4; ks++) {
            uint32_t kA0 = (((uint32_t)(ks*32)) ^ swza) + t4x4;
            uint32_t kA1 = (((uint32_t)(ks*32 + 16)) ^ swza) + t4x4;
            uint32_t ah[2][4], al[2][4];
            ah[0][0] = lds32(aRow0 + kA0);        ah[0][1] = lds32(aRow0 + 1024 + kA0);
            ah[0][2] = lds32(aRow0 + kA1);        ah[0][3] = lds32(aRow0 + 1024 + kA1);
            al[0][0] = lds32(aRow0 + CM_ALO + kA0); al[0][1] = lds32(aRow0 + CM_ALO + 1024 + kA0);
            al[0][2] = lds32(aRow0 + CM_ALO + kA1); al[0][3] = lds32(aRow0 + CM_ALO + 1024 + kA1);
            ah[1][0] = lds32(aRow1 + kA0);        ah[1][1] = lds32(aRow1 + 1024 + kA0);
            ah[1][2] = lds32(aRow1 + kA1);        ah[1][3] = lds32(aRow1 + 1024 + kA1);
            al[1][0] = lds32(aRow1 + CM_ALO + kA0); al[1][1] = lds32(aRow1 + CM_ALO + 1024 + kA0);
            al[1][2] = lds32(aRow1 + CM_ALO + kA1); al[1][3] = lds32(aRow1 + CM_ALO + 1024 + kA1);
            uint32_t kB0 = (((uint32_t)(ks*32)) ^ swzb) + t4x4;
            uint32_t kB1 = (((uint32_t)(ks*32 + 16)) ^ swzb) + t4x4;
            #pragma unroll
            for (int u = 0; u < 8; u++) {
                uint32_t rb = wb + (uint32_t)((nb + u*8 + grp)*128);
                uint32_t bh0 = lds32(rb + kB0), bh1 = lds32(rb + kB1);
                uint32_t bl0 = lds32(rb + 16384 + kB0), bl1 = lds32(rb + 16384 + kB1);
                mma16816(acc[0][u], ah[0][0], ah[0][1], ah[0][2], ah[0][3], bh0, bh1);
                mma16816(acc[1][u], ah[1][0], ah[1][1], ah[1][2], ah[1][3], bh0, bh1);
                mma16816(acc[0][u], ah[0][0], ah[0][1], ah[0][2], ah[0][3], bl0, bl1);
                mma16816(acc[1][u], ah[1][0], ah[1][1], ah[1][2], ah[1][3], bl0, bl1);
                mma16816(acc[0][u], al[0][0], al[0][1], al[0][2], al[0][3], bh0, bh1);
                mma16816(acc[1][u], al[1][0], al[1][1], al[1][2], al[1][3], bh0, bh1);
            }
        }
        __syncthreads();
    }

    // epilogue: bias (no relu), fp32 NHWC
    float* outp = sel ? g_freq : g_coef;
    #pragma unroll
    for (int t = 0; t < 2; t++) {
        int gy = row0 + wm*2 + t;
        #pragma unroll
        for (int u = 0; u < 8; u++) {
            int cidx = nb + u*8 + t4*2;
            float b0 = sbias[cidx], b1 = sbias[cidx+1];
            size_t o0 = (((size_t)b*H2 + gy)*H2 + col0 + grp)*256 + cohalf*128 + cidx;
            size_t o1 = o0 + (size_t)8*256;
            *(float2*)&outp[o0] = make_float2(acc[t][u][0] + b0, acc[t][u][1] + b1);
            *(float2*)&outp[o1] = make_float2(acc[t][u][2] + b0, acc[t][u][3] + b1);
        }
    }
}

// ---------------- pack MLP weights (bf16 hi/lo, row-major) --------------------
__global__ void pack_mlp(const float* __restrict__ w1, const float* __restrict__ w2) {
    int i = blockIdx.x*256 + threadIdx.x;
    int l = i >> 16; int e = i & 65535;
    const float* W = l ? w2 : w1;
    float v = W[e];
    __nv_bfloat16 h = __float2bfloat16(v);
    g_Wh[l][e] = h;
    g_Wl[l][e] = __float2bfloat16(v - __bfloat162float(h));
}

// ---------------- gather + fourier basis -> X0 hi/lo bf16 ---------------------
__global__ void gather_basis(const float* __restrict__ coord,
                             const float* __restrict__ cell,
                             const float* __restrict__ phase_w) {
    int warp = threadIdx.x / 32, lane = threadIdx.x % 32;
    int m = blockIdx.x * 8 + warp;
    int b = m / QQ; int q = m % QQ;
    float cy = coord[((size_t)b*QQ + q)*2 + 0];
    float cx = coord[((size_t)b*QQ + q)*2 + 1];
    int ix = (int)rintf(((cx + 1.f)*(float)H2 - 1.f)*0.5f);
    int iy = (int)rintf(((cy + 1.f)*(float)H2 - 1.f)*0.5f);
    bool ok = (ix >= 0 && ix < H2 && iy >= 0 && iy < H2);
    __nv_bfloat16* xh = g_X0h + (size_t)m*HID;
    __nv_bfloat16* xl = g_X0l + (size_t)m*HID;
    if (!ok) {
        __nv_bfloat16 z = __float2bfloat16(0.f);
        #pragma unroll
        for (int kk = 0; kk < 4; kk++) {
            int k = lane + kk*32;
            xh[k] = z; xh[128+k] = z; xl[k] = z; xl[128+k] = z;
        }
        return;
    }
    float fcy = -1.f + 1.f/(float)H2 + (2.f/(float)H2)*(float)iy;
    float fcx = -1.f + 1.f/(float)H2 + (2.f/(float)H2)*(float)ix;
    float rely = (cy - fcy)*(float)H2;
    float relx = (cx - fcx)*(float)H2;
    float rc0 = cell[((size_t)b*QQ + q)*2 + 0]*(float)H2;
    float rc1 = cell[((size_t)b*QQ + q)*2 + 1]*(float)H2;
    size_t base = (((size_t)b*H2 + iy)*H2 + ix)*HID;
    const float*  cf = g_coef + base;
    const float2* fq = (const float2*)(g_freq + base);
    const float2* pw = (const float2*)phase_w;
    #pragma unroll
    for (int kk = 0; kk < 4; kk++) {
        int k = lane + kk*32;
        float2 f = fq[k];
        float2 p = pw[k];
        float s = f.x*rely + f.y*relx + rc0*p.x + rc1*p.y;
        float v0 = cf[k]       * cospif(s);
        float v1 = cf[128 + k] * sinpif(s);
        __nv_bfloat16 h0 = __float2bfloat16(v0);
        __nv_bfloat16 h1 = __float2bfloat16(v1);
        xh[k]     = h0; xl[k]     = __float2bfloat16(v0 - __bfloat162float(h0));
        xh[128+k] = h1; xl[128+k] = __float2bfloat16(v1 - __bfloat162float(h1));
    }
}

// ---------------- mma.sync bf16 GEMM (3-pass split) + bias + relu -------------
#define GM_BB 0
#define GM_AB 131072
#define GM_SMEM 196608

__global__ void __launch_bounds__(256, 1) gemm_mma(const float* __restrict__ bias, int layer) {
    extern __shared__ __align__(16) char smc[];
    __shared__ float sbias[128];
    uint32_t sb;
    asm("{ .reg .u64 t; cvta.to.shared.u64 t, %1; cvt.u32.u64 %0, t; }" : "=r"(sb) : "l"(smc));
    int tid = threadIdx.x, wid = tid >> 5, lane = tid & 31;
    int grp = lane >> 2, t4 = lane & 3;
    int m0 = blockIdx.x * 128;
    int n0 = blockIdx.y * 128;
    int wm = wid >> 1, wn = wid & 1;
    int mb = wm * 32, nb = wn * 64;

    const __nv_bfloat16* Ah = layer ? g_X1h : g_X0h;
    const __nv_bfloat16* Al = layer ? g_X1l : g_X0l;
    const __nv_bfloat16* Wh = g_Wh[layer];
    const __nv_bfloat16* Wl = g_Wl[layer];

    for (int i = tid; i < 8192; i += 256) {
        int half = i >> 12; int rem = i & 4095; int n = rem >> 5; int j = rem & 31;
        const __nv_bfloat16* src = (half ? Wl : Wh) + (size_t)(n0 + n)*256 + j*8;
        cpa16(smc + GM_BB + half*65536 + n*512 + ((j*16) ^ ((n&7)<<4)), src);
    }
    for (int i = tid; i < 2048; i += 256) {
        int half = i >> 10; int rem = i & 1023; int m = rem >> 3; int j = rem & 7;
        const __nv_bfloat16* src = (half ? Al : Ah) + (size_t)(m0 + m)*256 + j*8;
        cpa16(smc + GM_AB + half*16384 + m*128 + ((j*16) ^ ((m&7)<<4)), src);
    }
    asm volatile("cp.async.commit_group;" ::: "memory");
    if (tid < 128) sbias[tid] = bias[n0 + tid];

    float acc[2][8][4];
    #pragma unroll
    for (int t = 0; t < 2; t++)
        #pragma unroll
        for (int u = 0; u < 8; u++)
            #pragma unroll
            for (int j = 0; j < 4; j++) acc[t][u][j] = 0.f;

    uint32_t swz = (uint32_t)(grp << 4);
    uint32_t t4x4 = (uint32_t)(t4 * 4);
    uint32_t bB = sb + GM_BB;

    for (int c = 0; c < 4; c++) {
        if (c < 3) {
            int cn = c + 1;
            char* dstb = smc + GM_AB + (cn & 1)*32768;
            for (int i = tid; i < 2048; i += 256) {
                int half = i >> 10; int rem = i & 1023; int m = rem >> 3; int j = rem & 7;
                const __nv_bfloat16* src = (half ? Al : Ah) + (size_t)(m0 + m)*256 + cn*64 + j*8;
                cpa16(dstb + half*16384 + m*128 + ((j*16) ^ ((m&7)<<4)), src);
            }
            asm volatile("cp.async.commit_group;" ::: "memory");
            asm volatile("cp.async.wait_group 1;" ::: "memory");
        } else {
            asm volatile("cp.async.wait_group 0;" ::: "memory");
        }
        __syncthreads();

        uint32_t bA = sb + GM_AB + (c & 1)*32768;
        #pragma unroll
        for (int ks = 0; ks < 4; ks++) {
            uint32_t ko  = (((uint32_t)(ks*32)) ^ swz) + t4x4;
            uint32_t koh = (((uint32_t)(ks*32+16)) ^ swz) + t4x4;
            uint32_t ahf[2][4], alf[2][4], bhf[8][2], blf[8][2];
            #pragma unroll
            for (int t = 0; t < 2; t++) {
                uint32_t ra = bA + (uint32_t)((mb + t*16 + grp)*128);
                ahf[t][0] = lds32(ra + ko);
                ahf[t][1] = lds32(ra + 1024 + ko);
                ahf[t][2] = lds32(ra + koh);
                ahf[t][3] = lds32(ra + 1024 + koh);
                alf[t][0] = lds32(ra + 16384 + ko);
                alf[t][1] = lds32(ra + 16384 + 1024 + ko);
                alf[t][2] = lds32(ra + 16384 + koh);
                alf[t][3] = lds32(ra + 16384 + 1024 + koh);
            }
            uint32_t kob  = (((uint32_t)(c*128 + ks*32)) ^ swz) + t4x4;
            uint32_t kobh = (((uint32_t)(c*128 + ks*32+16)) ^ swz) + t4x4;
            #pragma unroll
            for (int u = 0; u < 8; u++) {
                uint32_t rb = bB + (uint32_t)((nb + u*8 + grp)*512);
                bhf[u][0] = lds32(rb + kob);
                bhf[u][1] = lds32(rb + kobh);
                blf[u][0] = lds32(rb + 65536 + kob);
                blf[u][1] = lds32(rb + 65536 + kobh);
            }
            #pragma unroll
            for (int t = 0; t < 2; t++)
                #pragma unroll
                for (int u = 0; u < 8; u++)
                    mma16816(acc[t][u], ahf[t][0], ahf[t][1], ahf[t][2], ahf[t][3], bhf[u][0], bhf[u][1]);
            #pragma unroll
            for (int t = 0; t < 2; t++)
                #pragma unroll
                for (int u = 0; u < 8; u++)
                    mma16816(acc[t][u], ahf[t][0], ahf[t][1], ahf[t][2], ahf[t][3], blf[u][0], blf[u][1]);
            #pragma unroll
            for (int t = 0; t < 2; t++)
                #pragma unroll
                for (int u = 0; u < 8; u++)
                    mma16816(acc[t][u], alf[t][0], alf[t][1], alf[t][2], alf[t][3], bhf[u][0], bhf[u][1]);
        }
        __syncthreads();
    }

    #pragma unroll
    for (int t = 0; t < 2; t++) {
        int r0 = m0 + mb + t*16 + grp;
        int r1 = r0 + 8;
        #pragma unroll
        for (int u = 0; u < 8; u++) {
            int cb = nb + u*8 + t4*2;
            float b0v = sbias[cb], b1v = sbias[cb+1];
            float v00 = fmaxf(acc[t][u][0] + b0v, 0.f);
            float v01 = fmaxf(acc[t][u][1] + b1v, 0.f);
            float v10 = fmaxf(acc[t][u][2] + b0v, 0.f);
            float v11 = fmaxf(acc[t][u][3] + b1v, 0.f);
            int gcol = n0 + cb;
            if (layer == 0) {
                __nv_bfloat162 h0 = __float22bfloat162_rn(make_float2(v00, v01));
                __nv_bfloat162 h1 = __float22bfloat162_rn(make_float2(v10, v11));
                __nv_bfloat162 l0, l1;
                l0.x = __float2bfloat16(v00 - __bfloat162float(h0.x));
                l0.y = __float2bfloat16(v01 - __bfloat162float(h0.y));
                l1.x = __float2bfloat16(v10 - __bfloat162float(h1.x));
                l1.y = __float2bfloat16(v11 - __bfloat162float(h1.y));
                *(__nv_bfloat162*)&g_X1h[(size_t)r0*256 + gcol] = h0;
                *(__nv_bfloat162*)&g_X1h[(size_t)r1*256 + gcol] = h1;
                *(__nv_bfloat162*)&g_X1l[(size_t)r0*256 + gcol] = l0;
                *(__nv_bfloat162*)&g_X1l[(size_t)r1*256 + gcol] = l1;
            } else {
                *(float2*)&g_X0[(size_t)r0*256 + gcol] = make_float2(v00, v01);
                *(float2*)&g_X0[(size_t)r1*256 + gcol] = make_float2(v10, v11);
            }
        }
    }
}

// ---------------- final 256 -> 3 ----------------------------------------------
__global__ void final_layer(const float* __restrict__ w3,
                            const float* __restrict__ b3,
                            float* __restrict__ out) {
    __shared__ float w3s[3*256];
    int tid = threadIdx.x;
    for (int i = tid; i < 768; i += 256) w3s[i] = w3[i];
    __syncthreads();
    int warp = tid/32, lane = tid%32;
    int m = blockIdx.x * 8 + warp;
    const float* xr = g_X0 + (size_t)m*256;
    float a0 = 0.f, a1 = 0.f, a2 = 0.f;
    #pragma unroll
    for (int j = 0; j < 8; j++) {
        int k = lane + j*32;
        float v = xr[k];
        a0 += v*w3s[k]; a1 += v*w3s[256 + k]; a2 += v*w3s[512 + k];
    }
    #pragma unroll
    for (int off = 16; off; off >>= 1) {
        a0 += __shfl_down_sync(0xffffffffu, a0, off);
        a1 += __shfl_down_sync(0xffffffffu, a1, off);
        a2 += __shfl_down_sync(0xffffffffu, a2, off);
    }
    if (lane == 0) {
        out[(size_t)m*3 + 0] = a0 + b3[0];
        out[(size_t)m*3 + 1] = a1 + b3[1];
        out[(size_t)m*3 + 2] = a2 + b3[2];
    }
}

// ---------------- launch -------------------------------------------------------
extern "C" void kernel_launch(void* const* d_in, const int* in_sizes, int n_in,
                              void* d_out, int out_size) {
    const float* feat    = (const float*)d_in[0];
    const float* coord   = (const float*)d_in[1];
    const float* cell    = (const float*)d_in[2];
    const float* cls_w1  = (const float*)d_in[3];
    const float* cls_b1  = (const float*)d_in[4];
    const float* cls_w2  = (const float*)d_in[5];
    const float* cls_b2  = (const float*)d_in[6];
    const float* sigma_x = (const float*)d_in[7];
    const float* sigma_y = (const float*)d_in[8];
    const float* opacity = (const float*)d_in[9];
    const float* rho     = (const float*)d_in[10];
    const float* coef_w  = (const float*)d_in[11];
    const float* coef_b  = (const float*)d_in[12];
    const float* freq_w  = (const float*)d_in[13];
    const float* freq_b  = (const float*)d_in[14];
    const float* phase_w = (const float*)d_in[15];
    const float* mlp_w1  = (const float*)d_in[16];
    const float* mlp_b1  = (const float*)d_in[17];
    const float* mlp_w2  = (const float*)d_in[18];
    const float* mlp_b2  = (const float*)d_in[19];
    const float* mlp_w3  = (const float*)d_in[20];
    const float* mlp_b3  = (const float*)d_in[21];
    float* out = (float*)d_out;

    cudaFuncSetAttribute(conv112p, cudaFuncAttributeMaxDynamicSharedMemorySize, CONVP_SMEM);
    cudaFuncSetAttribute(splat,    cudaFuncAttributeMaxDynamicSharedMemorySize, SPLAT_SMEM);
    cudaFuncSetAttribute(conv224m, cudaFuncAttributeMaxDynamicSharedMemorySize, CM_SMEM);
    cudaFuncSetAttribute(gemm_mma, cudaFuncAttributeMaxDynamicSharedMemorySize, GM_SMEM);

    conv112p<<<dim3(49, 4, BB), 256, CONVP_SMEM>>>(feat, cls_w1, cls_b1);
    conv1x1_logits<<<196, 256>>>(cls_w2, cls_b2);
    softmax_stats<<<196, 256>>>(sigma_x, sigma_y, opacity, rho);
    splat<<<1024, 196, SPLAT_SMEM>>>(feat);
    pack_cw<<<1152, 256>>>(coef_w, freq_w);
    conv224m<<<dim3(196, 2, BB), 512, CM_SMEM>>>(coef_b, 0);
    conv224m<<<dim3(196, 2, BB), 512, CM_SMEM>>>(freq_b, 1);
    pack_mlp<<<512, 256>>>(mlp_w1, mlp_w2);
    gather_basis<<<MTOT/8, 256>>>(coord, cell, phase_w);
    gemm_mma<<<dim3(MTOT/128, 2), 256, GM_SMEM>>>(mlp_b1, 0);
    gemm_mma<<<dim3(MTOT/128, 2), 256, GM_SMEM>>>(mlp_b2, 1);
    final_layer<<<MTOT/8, 256>>>(mlp_w3, mlp_b3, out);
}

// round 8
// speedup vs baseline: 6.0587x; 1.0502x over previous
#include <cuda_runtime.h>
#include <cuda_bf16.h>
#include <math.h>
#include <stdint.h>

#define CIN 64
#define NGRP 100
#define HID 256
#define BB 4
#define HH 112
#define H2 224
#define QQ 50176
#define MTOT (BB*QQ)   // 200704

typedef unsigned long long ull;

__device__ __forceinline__ ull pk2(float a, float b) {
    ull r; asm("mov.b64 %0,{%1,%2};" : "=l"(r) : "f"(a), "f"(b)); return r;
}
__device__ __forceinline__ void fma2(ull& d, ull a, ull b) {
    asm("fma.rn.f32x2 %0,%1,%2,%0;" : "+l"(d) : "l"(a), "l"(b));
}
__device__ __forceinline__ void upk2(ull v, float& a, float& b) {
    asm("mov.b64 {%0,%1},%2;" : "=f"(a), "=f"(b) : "l"(v));
}
__device__ __forceinline__ void cpa16(void* dst, const void* src) {
    unsigned d = (unsigned)__cvta_generic_to_shared(dst);
    asm volatile("cp.async.cg.shared.global [%0], [%1], 16;" :: "r"(d), "l"(src));
}
__device__ __forceinline__ void cpa16z(void* dst, const void* src, int sz) {
    unsigned d = (unsigned)__cvta_generic_to_shared(dst);
    asm volatile("cp.async.cg.shared.global [%0], [%1], 16, %2;" :: "r"(d), "l"(src), "r"(sz));
}
__device__ __forceinline__ uint32_t lds32(uint32_t a) {
    uint32_t v; asm volatile("ld.shared.b32 %0,[%1];" : "=r"(v) : "r"(a)); return v;
}
__device__ __forceinline__ void mma16816(float* c, uint32_t a0, uint32_t a1, uint32_t a2, uint32_t a3,
                                         uint32_t b0, uint32_t b1) {
    asm volatile("mma.sync.aligned.m16n8k16.row.col.f32.bf16.bf16.f32 "
        "{%0,%1,%2,%3},{%4,%5,%6,%7},{%8,%9},{%0,%1,%2,%3};"
        : "+f"(c[0]), "+f"(c[1]), "+f"(c[2]), "+f"(c[3])
        : "r"(a0), "r"(a1), "r"(a2), "r"(a3), "r"(b0), "r"(b1));
}

// ---------------- scratch -----------------------------------------------------
__device__ float g_h[(size_t)BB*CIN*HH*HH];
__device__ float g_logits[(size_t)BB*NGRP*HH*HH];
__device__ float g_wstat[49*4];
__device__ int   g_ctr;
__device__ float g_ktw[49*196];
__device__ __align__(16) __nv_bfloat16 g_gfh[(size_t)BB*H2*H2*64];  // NHWC hi
__device__ __align__(16) __nv_bfloat16 g_gfl[(size_t)BB*H2*H2*64];  // NHWC lo
__device__ float g_coef[(size_t)BB*H2*H2*HID];
__device__ float g_freq[(size_t)BB*H2*H2*HID];
__device__ __nv_bfloat16 g_X0h[(size_t)MTOT*HID];
__device__ __nv_bfloat16 g_X0l[(size_t)MTOT*HID];
__device__ __nv_bfloat16 g_X1h[(size_t)MTOT*HID];
__device__ __nv_bfloat16 g_X1l[(size_t)MTOT*HID];
__device__ __align__(16) unsigned char g_cw[(size_t)2*2*9*32768];   // conv224 bf16 hi/lo swizzled
__device__ __align__(16) __nv_bfloat16 g_Wh[2][65536];
__device__ __align__(16) __nv_bfloat16 g_Wl[2][65536];

// ---------------- conv3x3 64->64 @112, relu, NCHW out (packed f32x2) ----------
#define CONVP_SMEM (64*18*18*4 + 64*8*10*8)

__global__ void conv112p(const float* __restrict__ in,
                         const float* __restrict__ w,
                         const float* __restrict__ bias) {
    extern __shared__ float sm[];
    float* ins = sm;
    ull*   wsp = (ull*)(sm + 64*324);
    int tile = blockIdx.x;
    int co0  = blockIdx.y * 16;
    int b    = blockIdx.z;
    int ty0 = (tile / 7) * 16, tx0 = (tile % 7) * 16;
    int tid = threadIdx.x;

    const float* inb = in + (size_t)b * CIN * HH * HH;
    for (int i = tid; i < 64*18*18; i += 256) {
        int ci = i / 324; int r = (i % 324) / 18; int c = i % 18;
        int gy = ty0 + r - 1, gx = tx0 + c - 1;
        float v = 0.f;
        if (gy >= 0 && gy < HH && gx >= 0 && gx < HH) v = inb[(ci*HH + gy)*HH + gx];
        ins[i] = v;
    }
    float* wspf = (float*)wsp;
    for (int i = tid; i < 64*8*9*2; i += 256) {
        int half = i & 1; int e = i >> 1;
        int k = e % 9; int cop = (e/9) & 7; int ci = e/72;
        wspf[((ci*8 + cop)*10 + k)*2 + half] = w[(size_t)(co0 + cop*2 + half)*576 + ci*9 + k];
    }
    __syncthreads();

    int ty = tid / 16, tx = tid % 16;
    ull acc[8];
    #pragma unroll
    for (int cop = 0; cop < 8; cop++) acc[cop] = pk2(bias[co0+2*cop], bias[co0+2*cop+1]);

    for (int ci = 0; ci < 64; ci++) {
        const float* ip = ins + ci*324 + ty*18 + tx;
        ull vv[9];
        #pragma unroll
        for (int dy = 0; dy < 3; dy++)
            #pragma unroll
            for (int dx = 0; dx < 3; dx++) {
                float v = ip[dy*18 + dx];
                vv[dy*3+dx] = pk2(v, v);
            }
        const ull* wbase = wsp + ci*80;
        #pragma unroll
        for (int cop = 0; cop < 8; cop++) {
            const ulonglong2* wc2 = (const ulonglong2*)(wbase + cop*10);
            ulonglong2 p0 = wc2[0], p1 = wc2[1], p2 = wc2[2], p3 = wc2[3];
            ull p8 = (wbase + cop*10)[8];
            fma2(acc[cop], vv[0], p0.x); fma2(acc[cop], vv[1], p0.y);
            fma2(acc[cop], vv[2], p1.x); fma2(acc[cop], vv[3], p1.y);
            fma2(acc[cop], vv[4], p2.x); fma2(acc[cop], vv[5], p2.y);
            fma2(acc[cop], vv[6], p3.x); fma2(acc[cop], vv[7], p3.y);
            fma2(acc[cop], vv[8], p8);
        }
    }
    int oy = ty0 + ty, ox = tx0 + tx;
    #pragma unroll
    for (int cop = 0; cop < 8; cop++) {
        float lo, hi; upk2(acc[cop], lo, hi);
        g_h[(((size_t)b*64 + co0 + 2*cop    )*HH + oy)*HH + ox] = fmaxf(lo, 0.f);
        g_h[(((size_t)b*64 + co0 + 2*cop + 1)*HH + oy)*HH + ox] = fmaxf(hi, 0.f);
    }
}

// ------- pack conv224 weights: bf16 hi/lo, per-tap [co128][ci64] swizzled -----
__global__ void pack_cw(const float* __restrict__ wc, const float* __restrict__ wf) {
    int i = blockIdx.x*256 + threadIdx.x;
    if (i >= 294912) return;
    int ci = i & 63; int t = i >> 6;
    int co = t & 127; t >>= 7;
    int dydx = t % 9; t /= 9;
    int half = t & 1; int sel = t >> 1;
    const float* W = sel ? wf : wc;
    float v = W[(size_t)(half*128 + co)*576 + ci*9 + dydx];
    __nv_bfloat16 h = __float2bfloat16(v);
    __nv_bfloat16 l = __float2bfloat16(v - __bfloat162float(h));
    size_t base = ((size_t)((sel*2 + half)*9 + dydx))*32768;
    uint32_t off = (uint32_t)co*128 + (((uint32_t)(ci>>3)*16) ^ (((uint32_t)co&7)<<4)) + (ci&7)*2;
    *(__nv_bfloat16*)(g_cw + base + off)         = h;
    *(__nv_bfloat16*)(g_cw + base + 16384 + off) = l;
}

// ------- 1x1 conv 64->100 (+ zero stats) --------------------------------------
__global__ void conv1x1_logits(const float* __restrict__ w2,
                               const float* __restrict__ b2) {
    __shared__ float ws[NGRP*64];
    int tid = threadIdx.x;
    if (blockIdx.x == 0 && tid < 196) g_wstat[tid] = 0.f;
    for (int i = tid; i < NGRP*64; i += 256) ws[i] = w2[i];
    __syncthreads();
    int t = blockIdx.x * 256 + tid;
    int b = t / (HH*HH); int pix = t % (HH*HH);
    const float* hp = g_h + (size_t)b*64*HH*HH + pix;
    float hv[64];
    #pragma unroll
    for (int ci = 0; ci < 64; ci++) hv[ci] = hp[(size_t)ci*HH*HH];
    float* lp = g_logits + (size_t)b*NGRP*HH*HH + pix;
    for (int g = 0; g < NGRP; g++) {
        float acc = b2[g];
        const float* wg = ws + g*64;
        #pragma unroll
        for (int ci = 0; ci < 64; ci += 4) {
            float4 wv = *(const float4*)(wg + ci);
            acc += hv[ci]*wv.x + hv[ci+1]*wv.y + hv[ci+2]*wv.z + hv[ci+3]*wv.w;
        }
        lp[(size_t)g*HH*HH] = acc;
    }
}

// ---------------- softmax + stats + (last block) build ktw --------------------
__global__ void softmax_stats(const float* __restrict__ sx, const float* __restrict__ sy,
                              const float* __restrict__ op, const float* __restrict__ rh) {
    __shared__ float sv[4*NGRP];
    __shared__ float accs[196];
    __shared__ float kpad[49*196];
    __shared__ float wops[49];
    __shared__ int lastb;
    int tid = threadIdx.x;
    for (int i = tid; i < NGRP; i += 256) {
        sv[i] = sx[i]; sv[NGRP+i] = sy[i]; sv[2*NGRP+i] = op[i]; sv[3*NGRP+i] = rh[i];
    }
    for (int i = tid; i < 196; i += 256) accs[i] = 0.f;
    __syncthreads();
    int t = blockIdx.x * 256 + tid;
    int b = t / (HH*HH); int pix = t % (HH*HH);
    int y = pix / HH, x = pix % HH;
    const float* lp = g_logits + (size_t)b*NGRP*HH*HH + pix;
    float mx = -1e30f;
    for (int g = 0; g < NGRP; g++) mx = fmaxf(mx, lp[(size_t)g*HH*HH]);
    float s = 0.f, a0 = 0.f, a1 = 0.f, a2 = 0.f, a3 = 0.f;
    for (int g = 0; g < NGRP; g++) {
        float e = expf(lp[(size_t)g*HH*HH] - mx);
        s += e; a0 += e*sv[g]; a1 += e*sv[NGRP+g]; a2 += e*sv[2*NGRP+g]; a3 += e*sv[3*NGRP+g];
    }
    float inv = 1.f / s;
    int p = (y % 7)*7 + (x % 7);
    atomicAdd(&accs[p*4+0], a0*inv);
    atomicAdd(&accs[p*4+1], a1*inv);
    atomicAdd(&accs[p*4+2], a2*inv);
    atomicAdd(&accs[p*4+3], a3*inv);
    __syncthreads();
    for (int i = tid; i < 196; i += 256) atomicAdd(&g_wstat[i], accs[i]);

    __threadfence();
    if (tid == 0) lastb = (atomicAdd(&g_ctr, 1) == (int)gridDim.x - 1);
    __syncthreads();
    if (!lastb) return;
    if (tid == 0) g_ctr = 0;

    for (int i = tid; i < 49*196; i += 256) kpad[i] = 0.f;
    __syncthreads();
    if (tid < 49) {
        int p2 = tid;
        const float inv1024 = 1.f/1024.f;
        float wsx = g_wstat[p2*4+0]*inv1024;
        float wsy = g_wstat[p2*4+1]*inv1024;
        float wop = g_wstat[p2*4+2]*inv1024;
        float wr  = g_wstat[p2*4+3]*inv1024;
        wops[p2] = wop;
        float c00 = wsx*wsx + 1e-5f;
        float c11 = wsy*wsy + 1e-5f;
        float c01 = wr*wsx*wsy;
        float det = c00*c11 - c01*c01;
        float i00 = c11/det, i11 = c00/det, i01 = -c01/det;
        float norm = 1.f/(2.f*3.14159265358979f*sqrtf(det));
        float kv[25]; float kmx = 0.f;
        #pragma unroll
        for (int i = 0; i < 5; i++)
            #pragma unroll
            for (int j = 0; j < 5; j++) {
                float yv = -5.f + 2.5f*i;
                float xv = -5.f + 2.5f*j;
                float z = -0.5f*(i00*xv*xv + 2.f*i01*xv*yv + i11*yv*yv);
                float k = expf(z)*norm;
                kv[i*5+j] = k; kmx = fmaxf(kmx, k);
            }
        float im = 1.f/kmx;
        #pragma unroll
        for (int i = 0; i < 5; i++)
            #pragma unroll
            for (int j = 0; j < 5; j++)
                kpad[p2*196 + (i+4)*14 + (j+4)] = kv[i*5+j]*im;
    }
    __syncthreads();
    for (int idx = tid; idx < 49*196; idx += 256) {
        int p2 = idx/196, hw = idx%196, h = hw/14, w = hw%14;
        float txo = (0.5f - (float)(p2/7)*(1.f/7.f))*2.f;
        float tyo = (0.5f - (float)(p2%7)*(1.f/7.f))*2.f;
        float gxv = -1.f + (2.f/13.f)*w + txo;
        float gyv = -1.f + (2.f/13.f)*h + tyo;
        float px = (gxv + 1.f)*0.5f*13.f;
        float py = (gyv + 1.f)*0.5f*13.f;
        float x0f = floorf(px), y0f = floorf(py);
        int x0 = (int)x0f, y0 = (int)y0f;
        float wx = px - x0f, wy = py - y0f;
        float s00 = (y0   >= 0 && y0   < 14 && x0   >= 0 && x0   < 14) ? kpad[p2*196 + y0*14 + x0]       : 0.f;
        float s01 = (y0   >= 0 && y0   < 14 && x0+1 >= 0 && x0+1 < 14) ? kpad[p2*196 + y0*14 + x0+1]     : 0.f;
        float s10 = (y0+1 >= 0 && y0+1 < 14 && x0   >= 0 && x0   < 14) ? kpad[p2*196 + (y0+1)*14 + x0]   : 0.f;
        float s11 = (y0+1 >= 0 && y0+1 < 14 && x0+1 >= 0 && x0+1 < 14) ? kpad[p2*196 + (y0+1)*14 + x0+1] : 0.f;
        float kt = s00*(1.f-wy)*(1.f-wx) + s01*(1.f-wy)*wx + s10*wy*(1.f-wx) + s11*wy*wx;
        g_ktw[idx] = kt * wops[p2];
    }
}

// ---------------- splat -> NHWC bf16 hi/lo (392 threads, kv in regs) ----------
#define SPLAT_SMEM ((49*196 + 64*49)*4)
__global__ void splat(const float* __restrict__ feat) {
    extern __shared__ float sm[];
    float* kts = sm;
    float* fp  = sm + 49*196;
    int bl = blockIdx.x;
    int b = bl / 256; int l = bl % 256; int pr = l / 16, pc = l % 16;
    int tid = threadIdx.x;   // 392
    for (int i = tid; i < 49*196; i += 392) kts[i] = g_ktw[i];
    const float* fb = feat + (size_t)b*64*HH*HH;
    for (int i = tid; i < 64*49; i += 392) {
        int c = i/49, p = i%49;
        fp[i] = fb[((size_t)c*HH + pr*7 + p/7)*HH + pc*7 + p%7];
    }
    __syncthreads();
    int half = tid / 196;
    int pix  = tid % 196;
    int h = pix/14, w = pix%14;
    float kv[49];
    #pragma unroll
    for (int p = 0; p < 49; p++) kv[p] = kts[p*196 + pix];
    int oy = pr*14 + h, ox = pc*14 + w;
    size_t pixb = ((size_t)b*H2 + oy)*H2 + ox;
    __nv_bfloat16* gh = g_gfh + pixb*64;
    __nv_bfloat16* gl = g_gfl + pixb*64;
    for (int c0 = half*32; c0 < half*32 + 32; c0 += 4) {
        float a0 = 0.f, a1 = 0.f, a2 = 0.f, a3 = 0.f;
        #pragma unroll
        for (int p = 0; p < 49; p++) {
            float k = kv[p];
            a0 += fp[(c0+0)*49 + p]*k;
            a1 += fp[(c0+1)*49 + p]*k;
            a2 += fp[(c0+2)*49 + p]*k;
            a3 += fp[(c0+3)*49 + p]*k;
        }
        a0 = __saturatef(a0); a1 = __saturatef(a1);
        a2 = __saturatef(a2); a3 = __saturatef(a3);
        __nv_bfloat16 h0 = __float2bfloat16(a0), h1 = __float2bfloat16(a1);
        __nv_bfloat16 h2 = __float2bfloat16(a2), h3 = __float2bfloat16(a3);
        *(__nv_bfloat162*)(gh + c0)     = __halves2bfloat162(h0, h1);
        *(__nv_bfloat162*)(gh + c0 + 2) = __halves2bfloat162(h2, h3);
        *(__nv_bfloat162*)(gl + c0)     = __halves2bfloat162(
            __float2bfloat16(a0 - __bfloat162float(h0)),
            __float2bfloat16(a1 - __bfloat162float(h1)));
        *(__nv_bfloat162*)(gl + c0 + 2) = __halves2bfloat162(
            __float2bfloat16(a2 - __bfloat162float(h2)),
            __float2bfloat16(a3 - __bfloat162float(h3)));
    }
}

// ---------------- conv3x3 64->256 @224 via mma.sync (merged sel) --------------
#define CM_ALO   41472
#define CM_WBASE 82944
#define CM_WBUF  32768
#define CM_SMEM  148480

__global__ void __launch_bounds__(512, 1) conv224m(const float* __restrict__ bias_c,
                                                   const float* __restrict__ bias_f) {
    extern __shared__ __align__(16) char smc[];
    __shared__ float sbias[128];
    uint32_t sb;
    asm("{ .reg .u64 t; cvta.to.shared.u64 t, %1; cvt.u32.u64 %0, t; }" : "=r"(sb) : "l"(smc));
    int tid = threadIdx.x, wid = tid >> 5, lane = tid & 31;
    int grp = lane >> 2, t4 = lane & 3;
    int bt = blockIdx.x, cohalf = blockIdx.y;
    int sel = blockIdx.z & 1, b = blockIdx.z >> 1;
    int row0 = (bt/14)*16, col0 = (bt%14)*16;
    int wm = wid >> 1, wn = wid & 1;
    int nb = wn*64;

    const __nv_bfloat16* gh = g_gfh + (size_t)b*H2*H2*64;
    const __nv_bfloat16* gl = g_gfl + (size_t)b*H2*H2*64;
    const unsigned char* wsrc = g_cw + (size_t)(sel*2 + cohalf)*9*32768;
    const float* bias = sel ? bias_f : bias_c;

    for (int i = tid; i < 2048; i += 512)
        cpa16(smc + CM_WBASE + i*16, wsrc + i*16);
    for (int i = tid; i < 5184; i += 512) {
        int hlf = i >= 2592; int e = hlf ? i - 2592 : i;
        int pos = e >> 3, j = e & 7;
        int r = pos / 18, c = pos - r*18;
        int gy = row0 + r - 1, gx = col0 + c - 1;
        int ok = (gy >= 0 && gy < H2 && gx >= 0 && gx < H2);
        const __nv_bfloat16* src = (hlf ? gl : gh) + ((size_t)(ok ? gy : 0)*H2 + (ok ? gx : 0))*64 + j*8;
        cpa16z(smc + (hlf ? CM_ALO : 0) + (r*18 + c)*128 + (((uint32_t)j*16) ^ (((uint32_t)c&7)<<4)),
               src, ok ? 16 : 0);
    }
    asm volatile("cp.async.commit_group;" ::: "memory");
    if (tid < 128) sbias[tid] = bias[cohalf*128 + tid];

    float acc[2][8][4];
    #pragma unroll
    for (int t = 0; t < 2; t++)
        #pragma unroll
        for (int u = 0; u < 8; u++)
            #pragma unroll
            for (int j = 0; j < 4; j++) acc[t][u][j] = 0.f;

    uint32_t swzb = (uint32_t)(grp << 4);
    uint32_t t4x4 = (uint32_t)(t4*4);

    for (int dydx = 0; dydx < 9; dydx++) {
        if (dydx < 8) {
            const unsigned char* src = wsrc + (size_t)(dydx+1)*32768;
            char* dst = smc + CM_WBASE + ((dydx+1)&1)*CM_WBUF;
            for (int i = tid; i < 2048; i += 512)
                cpa16(dst + i*16, src + i*16);
            asm volatile("cp.async.commit_group;" ::: "memory");
            asm volatile("cp.async.wait_group 1;" ::: "memory");
        } else {
            asm volatile("cp.async.wait_group 0;" ::: "memory");
        }
        __syncthreads();

        int dy = dydx/3, dx = dydx - dy*3;
        uint32_t wb = sb + CM_WBASE + (uint32_t)((dydx&1)*CM_WBUF);
        uint32_t swza = (uint32_t)(((grp + dx) & 7) << 4);
        uint32_t aRow0 = sb + (uint32_t)(((wm*2 + dy)*18 + grp + dx)*128);
        uint32_t aRow1 = aRow0 + 18*128;

        #pragma unroll
        for (int ks = 0; ks < 4; ks++) {
            uint32_t kA0 = (((uint32_t)(ks*32)) ^ swza) + t4x4;
            uint32_t kA1 = (((uint32_t)(ks*32 + 16)) ^ swza) + t4x4;
            uint32_t ah[2][4], al[2][4];
            ah[0][0] = lds32(aRow0 + kA0);        ah[0][1] = lds32(aRow0 + 1024 + kA0);
            ah[0][2] = lds32(aRow0 + kA1);        ah[0][3] = lds32(aRow0 + 1024 + kA1);
            al[0][0] = lds32(aRow0 + CM_ALO + kA0); al[0][1] = lds32(aRow0 + CM_ALO + 1024 + kA0);
            al[0][2] = lds32(aRow0 + CM_ALO + kA1); al[0][3] = lds32(aRow0 + CM_ALO + 1024 + kA1);
            ah[1][0] = lds32(aRow1 + kA0);        ah[1][1] = lds32(aRow1 + 1024 + kA0);
            ah[1][2] = lds32(aRow1 + kA1);        ah[1][3] = lds32(aRow1 + 1024 + kA1);
            al[1][0] = lds32(aRow1 + CM_ALO + kA0); al[1][1] = lds32(aRow1 + CM_ALO + 1024 + kA0);
            al[1][2] = lds32(aRow1 + CM_ALO + kA1); al[1][3] = lds32(aRow1 + CM_ALO + 1024 + kA1);
            uint32_t kB0 = (((uint32_t)(ks*32)) ^ swzb) + t4x4;
            uint32_t kB1 = (((uint32_t)(ks*32 + 16)) ^ swzb) + t4x4;
            #pragma unroll
            for (int u = 0; u < 8; u++) {
                uint32_t rb = wb + (uint32_t)((nb + u*8 + grp)*128);
                uint32_t bh0 = lds32(rb + kB0), bh1 = lds32(rb + kB1);
                uint32_t bl0 = lds32(rb + 16384 + kB0), bl1 = lds32(rb + 16384 + kB1);
                mma16816(acc[0][u], ah[0][0], ah[0][1], ah[0][2], ah[0][3], bh0, bh1);
                mma16816(acc[1][u], ah[1][0], ah[1][1], ah[1][2], ah[1][3], bh0, bh1);
                mma16816(acc[0][u], ah[0][0], ah[0][1], ah[0][2], ah[0][3], bl0, bl1);
                mma16816(acc[1][u], ah[1][0], ah[1][1], ah[1][2], ah[1][3], bl0, bl1);
                mma16816(acc[0][u], al[0][0], al[0][1], al[0][2], al[0][3], bh0, bh1);
                mma16816(acc[1][u], al[1][0], al[1][1], al[1][2], al[1][3], bh0, bh1);
            }
        }
        __syncthreads();
    }

    float* outp = sel ? g_freq : g_coef;
    #pragma unroll
    for (int t = 0; t < 2; t++) {
        int gy = row0 + wm*2 + t;
        #pragma unroll
        for (int u = 0; u < 8; u++) {
            int cidx = nb + u*8 + t4*2;
            float b0 = sbias[cidx], b1 = sbias[cidx+1];
            size_t o0 = (((size_t)b*H2 + gy)*H2 + col0 + grp)*256 + cohalf*128 + cidx;
            size_t o1 = o0 + (size_t)8*256;
            *(float2*)&outp[o0] = make_float2(acc[t][u][0] + b0, acc[t][u][1] + b1);
            *(float2*)&outp[o1] = make_float2(acc[t][u][2] + b0, acc[t][u][3] + b1);
        }
    }
}

// ---------------- pack MLP weights (bf16 hi/lo, row-major) --------------------
__global__ void pack_mlp(const float* __restrict__ w1, const float* __restrict__ w2) {
    int i = blockIdx.x*256 + threadIdx.x;
    int l = i >> 16; int e = i & 65535;
    const float* W = l ? w2 : w1;
    float v = W[e];
    __nv_bfloat16 h = __float2bfloat16(v);
    g_Wh[l][e] = h;
    g_Wl[l][e] = __float2bfloat16(v - __bfloat162float(h));
}

// ---------------- gather + fourier basis -> X0 hi/lo bf16 (+ zero out) --------
__global__ void gather_basis(const float* __restrict__ coord,
                             const float* __restrict__ cell,
                             const float* __restrict__ phase_w,
                             float* __restrict__ outz) {
    int gid = blockIdx.x*256 + threadIdx.x;
    if (gid < MTOT*3) outz[gid] = 0.f;
    int warp = threadIdx.x / 32, lane = threadIdx.x % 32;
    int m = blockIdx.x * 8 + warp;
    int b = m / QQ; int q = m % QQ;
    float cy = coord[((size_t)b*QQ + q)*2 + 0];
    float cx = coord[((size_t)b*QQ + q)*2 + 1];
    int ix = (int)rintf(((cx + 1.f)*(float)H2 - 1.f)*0.5f);
    int iy = (int)rintf(((cy + 1.f)*(float)H2 - 1.f)*0.5f);
    bool ok = (ix >= 0 && ix < H2 && iy >= 0 && iy < H2);
    __nv_bfloat16* xh = g_X0h + (size_t)m*HID;
    __nv_bfloat16* xl = g_X0l + (size_t)m*HID;
    if (!ok) {
        __nv_bfloat16 z = __float2bfloat16(0.f);
        #pragma unroll
        for (int kk = 0; kk < 4; kk++) {
            int k = lane + kk*32;
            xh[k] = z; xh[128+k] = z; xl[k] = z; xl[128+k] = z;
        }
        return;
    }
    float fcy = -1.f + 1.f/(float)H2 + (2.f/(float)H2)*(float)iy;
    float fcx = -1.f + 1.f/(float)H2 + (2.f/(float)H2)*(float)ix;
    float rely = (cy - fcy)*(float)H2;
    float relx = (cx - fcx)*(float)H2;
    float rc0 = cell[((size_t)b*QQ + q)*2 + 0]*(float)H2;
    float rc1 = cell[((size_t)b*QQ + q)*2 + 1]*(float)H2;
    size_t base = (((size_t)b*H2 + iy)*H2 + ix)*HID;
    const float*  cf = g_coef + base;
    const float2* fq = (const float2*)(g_freq + base);
    const float2* pw = (const float2*)phase_w;
    const float PI = 3.14159265358979f;
    #pragma unroll
    for (int kk = 0; kk < 4; kk++) {
        int k = lane + kk*32;
        float2 f = fq[k];
        float2 p = pw[k];
        float s = (f.x*rely + f.y*relx + rc0*p.x + rc1*p.y) * PI;
        float v0 = cf[k]       * __cosf(s);
        float v1 = cf[128 + k] * __sinf(s);
        __nv_bfloat16 h0 = __float2bfloat16(v0);
        __nv_bfloat16 h1 = __float2bfloat16(v1);
        xh[k]     = h0; xl[k]     = __float2bfloat16(v0 - __bfloat162float(h0));
        xh[128+k] = h1; xl[128+k] = __float2bfloat16(v1 - __bfloat162float(h1));
    }
}

// ---------------- mma.sync bf16 GEMM (3-pass split) + bias + relu -------------
// layer 0: X0 -> X1 (bf16 hi/lo). layer 1: X1 -> fused final 256->3 via atomics.
#define GM_BB 0
#define GM_AB 131072
#define GM_SMEM 196608

__global__ void __launch_bounds__(256, 1) gemm_mma(const float* __restrict__ bias, int layer,
                                                   const float* __restrict__ w3,
                                                   const float* __restrict__ b3,
                                                   float* __restrict__ out) {
    extern __shared__ __align__(16) char smc[];
    __shared__ float sbias[128];
    __shared__ float w3s[3*128];
    uint32_t sb;
    asm("{ .reg .u64 t; cvta.to.shared.u64 t, %1; cvt.u32.u64 %0, t; }" : "=r"(sb) : "l"(smc));
    int tid = threadIdx.x, wid = tid >> 5, lane = tid & 31;
    int grp = lane >> 2, t4 = lane & 3;
    int m0 = blockIdx.x * 128;
    int n0 = blockIdx.y * 128;
    int wm = wid >> 1, wn = wid & 1;
    int mb = wm * 32, nb = wn * 64;

    const __nv_bfloat16* Ah = layer ? g_X1h : g_X0h;
    const __nv_bfloat16* Al = layer ? g_X1l : g_X0l;
    const __nv_bfloat16* Wh = g_Wh[layer];
    const __nv_bfloat16* Wl = g_Wl[layer];

    for (int i = tid; i < 8192; i += 256) {
        int half = i >> 12; int rem = i & 4095; int n = rem >> 5; int j = rem & 31;
        const __nv_bfloat16* src = (half ? Wl : Wh) + (size_t)(n0 + n)*256 + j*8;
        cpa16(smc + GM_BB + half*65536 + n*512 + ((j*16) ^ ((n&7)<<4)), src);
    }
    for (int i = tid; i < 2048; i += 256) {
        int half = i >> 10; int rem = i & 1023; int m = rem >> 3; int j = rem & 7;
        const __nv_bfloat16* src = (half ? Al : Ah) + (size_t)(m0 + m)*256 + j*8;
        cpa16(smc + GM_AB + half*16384 + m*128 + ((j*16) ^ ((m&7)<<4)), src);
    }
    asm volatile("cp.async.commit_group;" ::: "memory");
    if (tid < 128) {
        sbias[tid] = bias[n0 + tid];
        if (layer) {
            w3s[tid]       = w3[0*256 + n0 + tid];
            w3s[128 + tid] = w3[1*256 + n0 + tid];
            w3s[256 + tid] = w3[2*256 + n0 + tid];
        }
    }

    float acc[2][8][4];
    #pragma unroll
    for (int t = 0; t < 2; t++)
        #pragma unroll
        for (int u = 0; u < 8; u++)
            #pragma unroll
            for (int j = 0; j < 4; j++) acc[t][u][j] = 0.f;

    uint32_t swz = (uint32_t)(grp << 4);
    uint32_t t4x4 = (uint32_t)(t4 * 4);
    uint32_t bB = sb + GM_BB;

    for (int c = 0; c < 4; c++) {
        if (c < 3) {
            int cn = c + 1;
            char* dstb = smc + GM_AB + (cn & 1)*32768;
            for (int i = tid; i < 2048; i += 256) {
                int half = i >> 10; int rem = i & 1023; int m = rem >> 3; int j = rem & 7;
                const __nv_bfloat16* src = (half ? Al : Ah) + (size_t)(m0 + m)*256 + cn*64 + j*8;
                cpa16(dstb + half*16384 + m*128 + ((j*16) ^ ((m&7)<<4)), src);
            }
            asm volatile("cp.async.commit_group;" ::: "memory");
            asm volatile("cp.async.wait_group 1;" ::: "memory");
        } else {
            asm volatile("cp.async.wait_group 0;" ::: "memory");
        }
        __syncthreads();

        uint32_t bA = sb + GM_AB + (c & 1)*32768;
        #pragma unroll
        for (int ks = 0; ks < 4; ks++) {
            uint32_t ko  = (((uint32_t)(ks*32)) ^ swz) + t4x4;
            uint32_t koh = (((uint32_t)(ks*32+16)) ^ swz) + t4x4;
            uint32_t ahf[2][4], alf[2][4], bhf[8][2], blf[8][2];
            #pragma unroll
            for (int t = 0; t < 2; t++) {
                uint32_t ra = bA + (uint32_t)((mb + t*16 + grp)*128);
                ahf[t][0] = lds32(ra + ko);
                ahf[t][1] = lds32(ra + 1024 + ko);
                ahf[t][2] = lds32(ra + koh);
                ahf[t][3] = lds32(ra + 1024 + koh);
                alf[t][0] = lds32(ra + 16384 + ko);
                alf[t][1] = lds32(ra + 16384 + 1024 + ko);
                alf[t][2] = lds32(ra + 16384 + koh);
                alf[t][3] = lds32(ra + 16384 + 1024 + koh);
            }
            uint32_t kob  = (((uint32_t)(c*128 + ks*32)) ^ swz) + t4x4;
            uint32_t kobh = (((uint32_t)(c*128 + ks*32+16)) ^ swz) + t4x4;
            #pragma unroll
            for (int u = 0; u < 8; u++) {
                uint32_t rb = bB + (uint32_t)((nb + u*8 + grp)*512);
                bhf[u][0] = lds32(rb + kob);
                bhf[u][1] = lds32(rb + kobh);
                blf[u][0] = lds32(rb + 65536 + kob);
                blf[u][1] = lds32(rb + 65536 + kobh);
            }
            #pragma unroll
            for (int t = 0; t < 2; t++)
                #pragma unroll
                for (int u = 0; u < 8; u++)
                    mma16816(acc[t][u], ahf[t][0], ahf[t][1], ahf[t][2], ahf[t][3], bhf[u][0], bhf[u][1]);
            #pragma unroll
            for (int t = 0; t < 2; t++)
                #pragma unroll
                for (int u = 0; u < 8; u++)
                    mma16816(acc[t][u], ahf[t][0], ahf[t][1], ahf[t][2], ahf[t][3], blf[u][0], blf[u][1]);
            #pragma unroll
            for (int t = 0; t < 2; t++)
                #pragma unroll
                for (int u = 0; u < 8; u++)
                    mma16816(acc[t][u], alf[t][0], alf[t][1], alf[t][2], alf[t][3], bhf[u][0], bhf[u][1]);
        }
        __syncthreads();
    }

    if (layer == 0) {
        #pragma unroll
        for (int t = 0; t < 2; t++) {
            int r0 = m0 + mb + t*16 + grp;
            int r1 = r0 + 8;
            #pragma unroll
            for (int u = 0; u < 8; u++) {
                int cb = nb + u*8 + t4*2;
                float b0v = sbias[cb], b1v = sbias[cb+1];
                float v00 = fmaxf(acc[t][u][0] + b0v, 0.f);
                float v01 = fmaxf(acc[t][u][1] + b1v, 0.f);
                float v10 = fmaxf(acc[t][u][2] + b0v, 0.f);
                float v11 = fmaxf(acc[t][u][3] + b1v, 0.f);
                int gcol = n0 + cb;
                __nv_bfloat162 h0 = __float22bfloat162_rn(make_float2(v00, v01));
                __nv_bfloat162 h1 = __float22bfloat162_rn(make_float2(v10, v11));
                __nv_bfloat162 l0, l1;
                l0.x = __float2bfloat16(v00 - __bfloat162float(h0.x));
                l0.y = __float2bfloat16(v01 - __bfloat162float(h0.y));
                l1.x = __float2bfloat16(v10 - __bfloat162float(h1.x));
                l1.y = __float2bfloat16(v11 - __bfloat162float(h1.y));
                *(__nv_bfloat162*)&g_X1h[(size_t)r0*256 + gcol] = h0;
                *(__nv_bfloat162*)&g_X1h[(size_t)r1*256 + gcol] = h1;
                *(__nv_bfloat162*)&g_X1l[(size_t)r0*256 + gcol] = l0;
                *(__nv_bfloat162*)&g_X1l[(size_t)r1*256 + gcol] = l1;
            }
        }
    } else {
        // fused final layer: relu, dot with w3 slice, reduce over t4, atomicAdd
        #pragma unroll
        for (int t = 0; t < 2; t++) {
            int r0 = m0 + mb + t*16 + grp;
            int r1 = r0 + 8;
            float p0[3] = {0.f, 0.f, 0.f};
            float p1[3] = {0.f, 0.f, 0.f};
            #pragma unroll
            for (int u = 0; u < 8; u++) {
                int cb = nb + u*8 + t4*2;
                float b0v = sbias[cb], b1v = sbias[cb+1];
                float v00 = fmaxf(acc[t][u][0] + b0v, 0.f);
                float v01 = fmaxf(acc[t][u][1] + b1v, 0.f);
                float v10 = fmaxf(acc[t][u][2] + b0v, 0.f);
                float v11 = fmaxf(acc[t][u][3] + b1v, 0.f);
                #pragma unroll
                for (int cc = 0; cc < 3; cc++) {
                    float w0 = w3s[cc*128 + cb], w1 = w3s[cc*128 + cb + 1];
                    p0[cc] += v00*w0 + v01*w1;
                    p1[cc] += v10*w0 + v11*w1;
                }
            }
            #pragma unroll
            for (int cc = 0; cc < 3; cc++) {
                p0[cc] += __shfl_xor_sync(0xffffffffu, p0[cc], 1);
                p0[cc] += __shfl_xor_sync(0xffffffffu, p0[cc], 2);
                p1[cc] += __shfl_xor_sync(0xffffffffu, p1[cc], 1);
                p1[cc] += __shfl_xor_sync(0xffffffffu, p1[cc], 2);
            }
            if (t4 == 0) {
                #pragma unroll
                for (int cc = 0; cc < 3; cc++) {
                    float bb = (n0 == 0) ? b3[cc] : 0.f;
                    atomicAdd(&out[(size_t)r0*3 + cc], p0[cc] + bb);
                    atomicAdd(&out[(size_t)r1*3 + cc], p1[cc] + bb);
                }
            }
        }
    }
}

// ---------------- launch -------------------------------------------------------
extern "C" void kernel_launch(void* const* d_in, const int* in_sizes, int n_in,
                              void* d_out, int out_size) {
    const float* feat    = (const float*)d_in[0];
    const float* coord   = (const float*)d_in[1];
    const float* cell    = (const float*)d_in[2];
    const float* cls_w1  = (const float*)d_in[3];
    const float* cls_b1  = (const float*)d_in[4];
    const float* cls_w2  = (const float*)d_in[5];
    const float* cls_b2  = (const float*)d_in[6];
    const float* sigma_x = (const float*)d_in[7];
    const float* sigma_y = (const float*)d_in[8];
    const float* opacity = (const float*)d_in[9];
    const float* rho     = (const float*)d_in[10];
    const float* coef_w  = (const float*)d_in[11];
    const float* coef_b  = (const float*)d_in[12];
    const float* freq_w  = (const float*)d_in[13];
    const float* freq_b  = (const float*)d_in[14];
    const float* phase_w = (const float*)d_in[15];
    const float* mlp_w1  = (const float*)d_in[16];
    const float* mlp_b1  = (const float*)d_in[17];
    const float* mlp_w2  = (const float*)d_in[18];
    const float* mlp_b2  = (const float*)d_in[19];
    const float* mlp_w3  = (const float*)d_in[20];
    const float* mlp_b3  = (const float*)d_in[21];
    float* out = (float*)d_out;

    cudaFuncSetAttribute(conv112p, cudaFuncAttributeMaxDynamicSharedMemorySize, CONVP_SMEM);
    cudaFuncSetAttribute(splat,    cudaFuncAttributeMaxDynamicSharedMemorySize, SPLAT_SMEM);
    cudaFuncSetAttribute(conv224m, cudaFuncAttributeMaxDynamicSharedMemorySize, CM_SMEM);
    cudaFuncSetAttribute(gemm_mma, cudaFuncAttributeMaxDynamicSharedMemorySize, GM_SMEM);

    conv112p<<<dim3(49, 4, BB), 256, CONVP_SMEM>>>(feat, cls_w1, cls_b1);
    conv1x1_logits<<<196, 256>>>(cls_w2, cls_b2);
    softmax_stats<<<196, 256>>>(sigma_x, sigma_y, opacity, rho);
    splat<<<1024, 392, SPLAT_SMEM>>>(feat);
    pack_cw<<<1152, 256>>>(coef_w, freq_w);
    conv224m<<<dim3(196, 2, BB*2), 512, CM_SMEM>>>(coef_b, freq_b);
    pack_mlp<<<512, 256>>>(mlp_w1, mlp_w2);
    gather_basis<<<MTOT/8, 256>>>(coord, cell, phase_w, out);
    gemm_mma<<<dim3(MTOT/128, 2), 256, GM_SMEM>>>(mlp_b1, 0, mlp_w3, mlp_b3, out);
    gemm_mma<<<dim3(MTOT/128, 2), 256, GM_SMEM>>>(mlp_b2, 1, mlp_w3, mlp_b3, out);
}

// round 9
// speedup vs baseline: 6.1190x; 1.0100x over previous
#include <cuda_runtime.h>
#include <cuda_bf16.h>
#include <math.h>
#include <stdint.h>

#define CIN 64
#define NGRP 100
#define HID 256
#define BB 4
#define HH 112
#define H2 224
#define QQ 50176
#define MTOT (BB*QQ)   // 200704

typedef unsigned long long ull;

__device__ __forceinline__ ull pk2(float a, float b) {
    ull r; asm("mov.b64 %0,{%1,%2};" : "=l"(r) : "f"(a), "f"(b)); return r;
}
__device__ __forceinline__ void fma2(ull& d, ull a, ull b) {
    asm("fma.rn.f32x2 %0,%1,%2,%0;" : "+l"(d) : "l"(a), "l"(b));
}
__device__ __forceinline__ void upk2(ull v, float& a, float& b) {
    asm("mov.b64 {%0,%1},%2;" : "=f"(a), "=f"(b) : "l"(v));
}
__device__ __forceinline__ void cpa16(void* dst, const void* src) {
    unsigned d = (unsigned)__cvta_generic_to_shared(dst);
    asm volatile("cp.async.cg.shared.global [%0], [%1], 16;" :: "r"(d), "l"(src));
}
__device__ __forceinline__ void cpa16z(void* dst, const void* src, int sz) {
    unsigned d = (unsigned)__cvta_generic_to_shared(dst);
    asm volatile("cp.async.cg.shared.global [%0], [%1], 16, %2;" :: "r"(d), "l"(src), "r"(sz));
}
__device__ __forceinline__ uint32_t lds32(uint32_t a) {
    uint32_t v; asm volatile("ld.shared.b32 %0,[%1];" : "=r"(v) : "r"(a)); return v;
}
__device__ __forceinline__ void mma16816(float* c, uint32_t a0, uint32_t a1, uint32_t a2, uint32_t a3,
                                         uint32_t b0, uint32_t b1) {
    asm volatile("mma.sync.aligned.m16n8k16.row.col.f32.bf16.bf16.f32 "
        "{%0,%1,%2,%3},{%4,%5,%6,%7},{%8,%9},{%0,%1,%2,%3};"
        : "+f"(c[0]), "+f"(c[1]), "+f"(c[2]), "+f"(c[3])
        : "r"(a0), "r"(a1), "r"(a2), "r"(a3), "r"(b0), "r"(b1));
}

// ---------------- scratch -----------------------------------------------------
__device__ float g_h[(size_t)BB*CIN*HH*HH];
__device__ float g_wstat[49*4];
__device__ int   g_ctr;
__device__ float g_ktw[49*196];
__device__ __align__(16) __nv_bfloat16 g_gfh[(size_t)BB*H2*H2*64];  // NHWC hi
__device__ __align__(16) __nv_bfloat16 g_gfl[(size_t)BB*H2*H2*64];  // NHWC lo
__device__ float g_coef[(size_t)BB*H2*H2*HID];
__device__ float g_freq[(size_t)BB*H2*H2*HID];
__device__ __nv_bfloat16 g_X0h[(size_t)MTOT*HID];
__device__ __nv_bfloat16 g_X0l[(size_t)MTOT*HID];
__device__ __nv_bfloat16 g_X1h[(size_t)MTOT*HID];
__device__ __nv_bfloat16 g_X1l[(size_t)MTOT*HID];
__device__ __align__(16) unsigned char g_cw[(size_t)2*2*9*32768];   // conv224 bf16 hi/lo swizzled
__device__ __align__(16) __nv_bfloat16 g_Wh[2][65536];
__device__ __align__(16) __nv_bfloat16 g_Wl[2][65536];

// ---------------- conv3x3 64->64 @112, relu, NCHW out (packed f32x2) ----------
#define CONVP_SMEM (64*18*18*4 + 64*8*10*8)

__global__ void conv112p(const float* __restrict__ in,
                         const float* __restrict__ w,
                         const float* __restrict__ bias) {
    extern __shared__ float sm[];
    float* ins = sm;
    ull*   wsp = (ull*)(sm + 64*324);
    int tile = blockIdx.x;
    int co0  = blockIdx.y * 16;
    int b    = blockIdx.z;
    int ty0 = (tile / 7) * 16, tx0 = (tile % 7) * 16;
    int tid = threadIdx.x;
    if (tile == 0 && blockIdx.y == 0 && b == 0 && tid < 196) g_wstat[tid] = 0.f;

    const float* inb = in + (size_t)b * CIN * HH * HH;
    for (int i = tid; i < 64*18*18; i += 256) {
        int ci = i / 324; int r = (i % 324) / 18; int c = i % 18;
        int gy = ty0 + r - 1, gx = tx0 + c - 1;
        float v = 0.f;
        if (gy >= 0 && gy < HH && gx >= 0 && gx < HH) v = inb[(ci*HH + gy)*HH + gx];
        ins[i] = v;
    }
    float* wspf = (float*)wsp;
    for (int i = tid; i < 64*8*9*2; i += 256) {
        int half = i & 1; int e = i >> 1;
        int k = e % 9; int cop = (e/9) & 7; int ci = e/72;
        wspf[((ci*8 + cop)*10 + k)*2 + half] = w[(size_t)(co0 + cop*2 + half)*576 + ci*9 + k];
    }
    __syncthreads();

    int ty = tid / 16, tx = tid % 16;
    ull acc[8];
    #pragma unroll
    for (int cop = 0; cop < 8; cop++) acc[cop] = pk2(bias[co0+2*cop], bias[co0+2*cop+1]);

    for (int ci = 0; ci < 64; ci++) {
        const float* ip = ins + ci*324 + ty*18 + tx;
        ull vv[9];
        #pragma unroll
        for (int dy = 0; dy < 3; dy++)
            #pragma unroll
            for (int dx = 0; dx < 3; dx++) {
                float v = ip[dy*18 + dx];
                vv[dy*3+dx] = pk2(v, v);
            }
        const ull* wbase = wsp + ci*80;
        #pragma unroll
        for (int cop = 0; cop < 8; cop++) {
            const ulonglong2* wc2 = (const ulonglong2*)(wbase + cop*10);
            ulonglong2 p0 = wc2[0], p1 = wc2[1], p2 = wc2[2], p3 = wc2[3];
            ull p8 = (wbase + cop*10)[8];
            fma2(acc[cop], vv[0], p0.x); fma2(acc[cop], vv[1], p0.y);
            fma2(acc[cop], vv[2], p1.x); fma2(acc[cop], vv[3], p1.y);
            fma2(acc[cop], vv[4], p2.x); fma2(acc[cop], vv[5], p2.y);
            fma2(acc[cop], vv[6], p3.x); fma2(acc[cop], vv[7], p3.y);
            fma2(acc[cop], vv[8], p8);
        }
    }
    int oy = ty0 + ty, ox = tx0 + tx;
    #pragma unroll
    for (int cop = 0; cop < 8; cop++) {
        float lo, hi; upk2(acc[cop], lo, hi);
        g_h[(((size_t)b*64 + co0 + 2*cop    )*HH + oy)*HH + ox] = fmaxf(lo, 0.f);
        g_h[(((size_t)b*64 + co0 + 2*cop + 1)*HH + oy)*HH + ox] = fmaxf(hi, 0.f);
    }
}

// ------- pack conv224 weights: bf16 hi/lo, per-tap [co128][ci64] swizzled -----
__global__ void pack_cw(const float* __restrict__ wc, const float* __restrict__ wf) {
    int i = blockIdx.x*256 + threadIdx.x;
    if (i >= 294912) return;
    int ci = i & 63; int t = i >> 6;
    int co = t & 127; t >>= 7;
    int dydx = t % 9; t /= 9;
    int half = t & 1; int sel = t >> 1;
    const float* W = sel ? wf : wc;
    float v = W[(size_t)(half*128 + co)*576 + ci*9 + dydx];
    __nv_bfloat16 h = __float2bfloat16(v);
    __nv_bfloat16 l = __float2bfloat16(v - __bfloat162float(h));
    size_t base = ((size_t)((sel*2 + half)*9 + dydx))*32768;
    uint32_t off = (uint32_t)co*128 + (((uint32_t)(ci>>3)*16) ^ (((uint32_t)co&7)<<4)) + (ci&7)*2;
    *(__nv_bfloat16*)(g_cw + base + off)         = h;
    *(__nv_bfloat16*)(g_cw + base + 16384 + off) = l;
}

// ------- fused 1x1 conv -> online softmax -> stats -> (last block) ktw --------
__global__ void logits_stats(const float* __restrict__ w2, const float* __restrict__ b2,
                             const float* __restrict__ sx, const float* __restrict__ sy,
                             const float* __restrict__ op, const float* __restrict__ rh) {
    __shared__ float buf[49*196];    // phase 1: ws[6400]; last block reuses as kpad[9604]
    __shared__ float sv[4*NGRP];
    __shared__ float b2s[NGRP];
    __shared__ float accs[196];
    __shared__ float wops[49];
    __shared__ int lastb;
    int tid = threadIdx.x;
    float* ws = buf;
    for (int i = tid; i < NGRP; i += 256) {
        sv[i] = sx[i]; sv[NGRP+i] = sy[i]; sv[2*NGRP+i] = op[i]; sv[3*NGRP+i] = rh[i];
        b2s[i] = b2[i];
    }
    for (int i = tid; i < NGRP*64; i += 256) ws[i] = w2[i];
    for (int i = tid; i < 196; i += 256) accs[i] = 0.f;
    __syncthreads();

    int t = blockIdx.x * 256 + tid;
    int b = t / (HH*HH); int pix = t % (HH*HH);
    int y = pix / HH, x = pix % HH;
    const float* hp = g_h + (size_t)b*64*HH*HH + pix;
    float hv[64];
    #pragma unroll
    for (int ci = 0; ci < 64; ci++) hv[ci] = hp[(size_t)ci*HH*HH];

    float m = -1e30f, s = 0.f, a0 = 0.f, a1 = 0.f, a2 = 0.f, a3 = 0.f;
    for (int g = 0; g < NGRP; g++) {
        float l = b2s[g];
        const float* wg = ws + g*64;
        #pragma unroll
        for (int ci = 0; ci < 64; ci += 4) {
            float4 wv = *(const float4*)(wg + ci);
            l += hv[ci]*wv.x + hv[ci+1]*wv.y + hv[ci+2]*wv.z + hv[ci+3]*wv.w;
        }
        float mn = fmaxf(m, l);
        float sc = __expf(m - mn);
        float e  = __expf(l - mn);
        s  = s*sc + e;
        a0 = a0*sc + e*sv[g];
        a1 = a1*sc + e*sv[NGRP+g];
        a2 = a2*sc + e*sv[2*NGRP+g];
        a3 = a3*sc + e*sv[3*NGRP+g];
        m = mn;
    }
    float inv = 1.f / s;
    int p = (y % 7)*7 + (x % 7);
    atomicAdd(&accs[p*4+0], a0*inv);
    atomicAdd(&accs[p*4+1], a1*inv);
    atomicAdd(&accs[p*4+2], a2*inv);
    atomicAdd(&accs[p*4+3], a3*inv);
    __syncthreads();
    for (int i = tid; i < 196; i += 256) atomicAdd(&g_wstat[i], accs[i]);

    __threadfence();
    if (tid == 0) lastb = (atomicAdd(&g_ctr, 1) == (int)gridDim.x - 1);
    __syncthreads();
    if (!lastb) return;
    if (tid == 0) g_ctr = 0;

    float* kpad = buf;
    for (int i = tid; i < 49*196; i += 256) kpad[i] = 0.f;
    __syncthreads();
    if (tid < 49) {
        int p2 = tid;
        const float inv1024 = 1.f/1024.f;
        float wsx = g_wstat[p2*4+0]*inv1024;
        float wsy = g_wstat[p2*4+1]*inv1024;
        float wop = g_wstat[p2*4+2]*inv1024;
        float wr  = g_wstat[p2*4+3]*inv1024;
        wops[p2] = wop;
        float c00 = wsx*wsx + 1e-5f;
        float c11 = wsy*wsy + 1e-5f;
        float c01 = wr*wsx*wsy;
        float det = c00*c11 - c01*c01;
        float i00 = c11/det, i11 = c00/det, i01 = -c01/det;
        float norm = 1.f/(2.f*3.14159265358979f*sqrtf(det));
        float kv[25]; float kmx = 0.f;
        #pragma unroll
        for (int i = 0; i < 5; i++)
            #pragma unroll
            for (int j = 0; j < 5; j++) {
                float yv = -5.f + 2.5f*i;
                float xv = -5.f + 2.5f*j;
                float z = -0.5f*(i00*xv*xv + 2.f*i01*xv*yv + i11*yv*yv);
                float k = expf(z)*norm;
                kv[i*5+j] = k; kmx = fmaxf(kmx, k);
            }
        float im = 1.f/kmx;
        #pragma unroll
        for (int i = 0; i < 5; i++)
            #pragma unroll
            for (int j = 0; j < 5; j++)
                kpad[p2*196 + (i+4)*14 + (j+4)] = kv[i*5+j]*im;
    }
    __syncthreads();
    for (int idx = tid; idx < 49*196; idx += 256) {
        int p2 = idx/196, hw = idx%196, h = hw/14, w = hw%14;
        float txo = (0.5f - (float)(p2/7)*(1.f/7.f))*2.f;
        float tyo = (0.5f - (float)(p2%7)*(1.f/7.f))*2.f;
        float gxv = -1.f + (2.f/13.f)*w + txo;
        float gyv = -1.f + (2.f/13.f)*h + tyo;
        float px = (gxv + 1.f)*0.5f*13.f;
        float py = (gyv + 1.f)*0.5f*13.f;
        float x0f = floorf(px), y0f = floorf(py);
        int x0 = (int)x0f, y0 = (int)y0f;
        float wx = px - x0f, wy = py - y0f;
        float s00 = (y0   >= 0 && y0   < 14 && x0   >= 0 && x0   < 14) ? kpad[p2*196 + y0*14 + x0]       : 0.f;
        float s01 = (y0   >= 0 && y0   < 14 && x0+1 >= 0 && x0+1 < 14) ? kpad[p2*196 + y0*14 + x0+1]     : 0.f;
        float s10 = (y0+1 >= 0 && y0+1 < 14 && x0   >= 0 && x0   < 14) ? kpad[p2*196 + (y0+1)*14 + x0]   : 0.f;
        float s11 = (y0+1 >= 0 && y0+1 < 14 && x0+1 >= 0 && x0+1 < 14) ? kpad[p2*196 + (y0+1)*14 + x0+1] : 0.f;
        float kt = s00*(1.f-wy)*(1.f-wx) + s01*(1.f-wy)*wx + s10*wy*(1.f-wx) + s11*wy*wx;
        g_ktw[idx] = kt * wops[p2];
    }
}

// ---------------- splat -> NHWC bf16 hi/lo (broadcast float4, 2 half-passes) --
#define SPLAT_SMEM ((49*196 + 49*64)*4)
__global__ void splat(const float* __restrict__ feat) {
    extern __shared__ float sm[];
    float* kts = sm;             // [p][196]
    float* fp  = sm + 49*196;    // [p][64]
    int bl = blockIdx.x;
    int b = bl / 256; int l = bl % 256; int pr = l / 16, pc = l % 16;
    int tid = threadIdx.x;       // 196
    for (int i = tid; i < 49*196; i += 196) kts[i] = g_ktw[i];
    const float* fb = feat + (size_t)b*64*HH*HH;
    for (int i = tid; i < 49*64; i += 196) {
        int p = i >> 6, c = i & 63;
        fp[i] = fb[((size_t)c*HH + pr*7 + p/7)*HH + pc*7 + p%7];
    }
    __syncthreads();
    int h = tid/14, w = tid%14;
    int oy = pr*14 + h, ox = pc*14 + w;
    size_t pixb = ((size_t)b*H2 + oy)*H2 + ox;
    __nv_bfloat16* gh = g_gfh + pixb*64;
    __nv_bfloat16* gl = g_gfl + pixb*64;
    #pragma unroll
    for (int half = 0; half < 2; half++) {
        float a[32];
        #pragma unroll
        for (int j = 0; j < 32; j++) a[j] = 0.f;
        for (int p = 0; p < 49; p++) {
            float k = kts[p*196 + tid];
            const float4* f4 = (const float4*)(fp + p*64 + half*32);
            #pragma unroll
            for (int j = 0; j < 8; j++) {
                float4 v = f4[j];
                a[j*4+0] += k*v.x; a[j*4+1] += k*v.y;
                a[j*4+2] += k*v.z; a[j*4+3] += k*v.w;
            }
        }
        #pragma unroll
        for (int j = 0; j < 32; j += 4) {
            int c0 = half*32 + j;
            float a0 = __saturatef(a[j]),   a1 = __saturatef(a[j+1]);
            float a2 = __saturatef(a[j+2]), a3 = __saturatef(a[j+3]);
            __nv_bfloat16 h0 = __float2bfloat16(a0), h1 = __float2bfloat16(a1);
            __nv_bfloat16 h2 = __float2bfloat16(a2), h3 = __float2bfloat16(a3);
            *(__nv_bfloat162*)(gh + c0)     = __halves2bfloat162(h0, h1);
            *(__nv_bfloat162*)(gh + c0 + 2) = __halves2bfloat162(h2, h3);
            *(__nv_bfloat162*)(gl + c0)     = __halves2bfloat162(
                __float2bfloat16(a0 - __bfloat162float(h0)),
                __float2bfloat16(a1 - __bfloat162float(h1)));
            *(__nv_bfloat162*)(gl + c0 + 2) = __halves2bfloat162(
                __float2bfloat16(a2 - __bfloat162float(h2)),
                __float2bfloat16(a3 - __bfloat162float(h3)));
        }
    }
}

// ---------------- conv3x3 64->256 @224 via mma.sync (merged sel) --------------
#define CM_ALO   41472
#define CM_WBASE 82944
#define CM_WBUF  32768
#define CM_SMEM  148480

__global__ void __launch_bounds__(512, 1) conv224m(const float* __restrict__ bias_c,
                                                   const float* __restrict__ bias_f) {
    extern __shared__ __align__(16) char smc[];
    __shared__ float sbias[128];
    uint32_t sb;
    asm("{ .reg .u64 t; cvta.to.shared.u64 t, %1; cvt.u32.u64 %0, t; }" : "=r"(sb) : "l"(smc));
    int tid = threadIdx.x, wid = tid >> 5, lane = tid & 31;
    int grp = lane >> 2, t4 = lane & 3;
    int bt = blockIdx.x, cohalf = blockIdx.y;
    int sel = blockIdx.z & 1, b = blockIdx.z >> 1;
    int row0 = (bt/14)*16, col0 = (bt%14)*16;
    int wm = wid >> 1, wn = wid & 1;
    int nb = wn*64;

    const __nv_bfloat16* gh = g_gfh + (size_t)b*H2*H2*64;
    const __nv_bfloat16* gl = g_gfl + (size_t)b*H2*H2*64;
    const unsigned char* wsrc = g_cw + (size_t)(sel*2 + cohalf)*9*32768;
    const float* bias = sel ? bias_f : bias_c;

    for (int i = tid; i < 2048; i += 512)
        cpa16(smc + CM_WBASE + i*16, wsrc + i*16);
    for (int i = tid; i < 5184; i += 512) {
        int hlf = i >= 2592; int e = hlf ? i - 2592 : i;
        int pos = e >> 3, j = e & 7;
        int r = pos / 18, c = pos - r*18;
        int gy = row0 + r - 1, gx = col0 + c - 1;
        int ok = (gy >= 0 && gy < H2 && gx >= 0 && gx < H2);
        const __nv_bfloat16* src = (hlf ? gl : gh) + ((size_t)(ok ? gy : 0)*H2 + (ok ? gx : 0))*64 + j*8;
        cpa16z(smc + (hlf ? CM_ALO : 0) + (r*18 + c)*128 + (((uint32_t)j*16) ^ (((uint32_t)c&7)<<4)),
               src, ok ? 16 : 0);
    }
    asm volatile("cp.async.commit_group;" ::: "memory");
    if (tid < 128) sbias[tid] = bias[cohalf*128 + tid];

    float acc[2][8][4];
    #pragma unroll
    for (int t = 0; t < 2; t++)
        #pragma unroll
        for (int u = 0; u < 8; u++)
            #pragma unroll
            for (int j = 0; j < 4; j++) acc[t][u][j] = 0.f;

    uint32_t swzb = (uint32_t)(grp << 4);
    uint32_t t4x4 = (uint32_t)(t4*4);

    for (int dydx = 0; dydx < 9; dydx++) {
        if (dydx < 8) {
            const unsigned char* src = wsrc + (size_t)(dydx+1)*32768;
            char* dst = smc + CM_WBASE + ((dydx+1)&1)*CM_WBUF;
            for (int i = tid; i < 2048; i += 512)
                cpa16(dst + i*16, src + i*16);
            asm volatile("cp.async.commit_group;" ::: "memory");
            asm volatile("cp.async.wait_group 1;" ::: "memory");
        } else {
            asm volatile("cp.async.wait_group 0;" ::: "memory");
        }
        __syncthreads();

        int dy = dydx/3, dx = dydx - dy*3;
        uint32_t wb = sb + CM_WBASE + (uint32_t)((dydx&1)*CM_WBUF);
        uint32_t swza = (uint32_t)(((grp + dx) & 7) << 4);
        uint32_t aRow0 = sb + (uint32_t)(((wm*2 + dy)*18 + grp + dx)*128);
        uint32_t aRow1 = aRow0 + 18*128;

        #pragma unroll
        for (int ks = 0; ks < 4; ks++) {
            uint32_t kA0 = (((uint32_t)(ks*32)) ^ swza) + t4x4;
            uint32_t kA1 = (((uint32_t)(ks*32 + 16)) ^ swza) + t4x4;
            uint32_t ah[2][4], al[2][4];
            ah[0][0] = lds32(aRow0 + kA0);        ah[0][1] = lds32(aRow0 + 1024 + kA0);
            ah[0][2] = lds32(aRow0 + kA1);        ah[0][3] = lds32(aRow0 + 1024 + kA1);
            al[0][0] = lds32(aRow0 + CM_ALO + kA0); al[0][1] = lds32(aRow0 + CM_ALO + 1024 + kA0);
            al[0][2] = lds32(aRow0 + CM_ALO + kA1); al[0][3] = lds32(aRow0 + CM_ALO + 1024 + kA1);
            ah[1][0] = lds32(aRow1 + kA0);        ah[1][1] = lds32(aRow1 + 1024 + kA0);
            ah[1][2] = lds32(aRow1 + kA1);        ah[1][3] = lds32(aRow1 + 1024 + kA1);
            al[1][0] = lds32(aRow1 + CM_ALO + kA0); al[1][1] = lds32(aRow1 + CM_ALO + 1024 + kA0);
            al[1][2] = lds32(aRow1 + CM_ALO + kA1); al[1][3] = lds32(aRow1 + CM_ALO + 1024 + kA1);
            uint32_t kB0 = (((uint32_t)(ks*32)) ^ swzb) + t4x4;
            uint32_t kB1 = (((uint32_t)(ks*32 + 16)) ^ swzb) + t4x4;
            #pragma unroll
            for (int u = 0; u < 8; u++) {
                uint32_t rb = wb + (uint32_t)((nb + u*8 + grp)*128);
                uint32_t bh0 = lds32(rb + kB0), bh1 = lds32(rb + kB1);
                uint32_t bl0 = lds32(rb + 16384 + kB0), bl1 = lds32(rb + 16384 + kB1);
                mma16816(acc[0][u], ah[0][0], ah[0][1], ah[0][2], ah[0][3], bh0, bh1);
                mma16816(acc[1][u], ah[1][0], ah[1][1], ah[1][2], ah[1][3], bh0, bh1);
                mma16816(acc[0][u], ah[0][0], ah[0][1], ah[0][2], ah[0][3], bl0, bl1);
                mma16816(acc[1][u], ah[1][0], ah[1][1], ah[1][2], ah[1][3], bl0, bl1);
                mma16816(acc[0][u], al[0][0], al[0][1], al[0][2], al[0][3], bh0, bh1);
                mma16816(acc[1][u], al[1][0], al[1][1], al[1][2], al[1][3], bh0, bh1);
            }
        }
        __syncthreads();
    }

    float* outp = sel ? g_freq : g_coef;
    #pragma unroll
    for (int t = 0; t < 2; t++) {
        int gy = row0 + wm*2 + t;
        #pragma unroll
        for (int u = 0; u < 8; u++) {
            int cidx = nb + u*8 + t4*2;
            float b0 = sbias[cidx], b1 = sbias[cidx+1];
            size_t o0 = (((size_t)b*H2 + gy)*H2 + col0 + grp)*256 + cohalf*128 + cidx;
            size_t o1 = o0 + (size_t)8*256;
            *(float2*)&outp[o0] = make_float2(acc[t][u][0] + b0, acc[t][u][1] + b1);
            *(float2*)&outp[o1] = make_float2(acc[t][u][2] + b0, acc[t][u][3] + b1);
        }
    }
}

// ---------------- pack MLP weights (bf16 hi/lo, row-major) --------------------
__global__ void pack_mlp(const float* __restrict__ w1, const float* __restrict__ w2) {
    int i = blockIdx.x*256 + threadIdx.x;
    int l = i >> 16; int e = i & 65535;
    const float* W = l ? w2 : w1;
    float v = W[e];
    __nv_bfloat16 h = __float2bfloat16(v);
    g_Wh[l][e] = h;
    g_Wl[l][e] = __float2bfloat16(v - __bfloat162float(h));
}

// ---------------- gather + fourier basis -> X0 hi/lo bf16 (+ zero out) --------
__global__ void gather_basis(const float* __restrict__ coord,
                             const float* __restrict__ cell,
                             const float* __restrict__ phase_w,
                             float* __restrict__ outz) {
    int gid = blockIdx.x*256 + threadIdx.x;
    if (gid < MTOT*3) outz[gid] = 0.f;
    int warp = threadIdx.x / 32, lane = threadIdx.x % 32;
    int m = blockIdx.x * 8 + warp;
    int b = m / QQ; int q = m % QQ;
    float cy = coord[((size_t)b*QQ + q)*2 + 0];
    float cx = coord[((size_t)b*QQ + q)*2 + 1];
    int ix = (int)rintf(((cx + 1.f)*(float)H2 - 1.f)*0.5f);
    int iy = (int)rintf(((cy + 1.f)*(float)H2 - 1.f)*0.5f);
    bool ok = (ix >= 0 && ix < H2 && iy >= 0 && iy < H2);
    __nv_bfloat16* xh = g_X0h + (size_t)m*HID;
    __nv_bfloat16* xl = g_X0l + (size_t)m*HID;
    if (!ok) {
        __nv_bfloat16 z = __float2bfloat16(0.f);
        #pragma unroll
        for (int kk = 0; kk < 4; kk++) {
            int k = lane + kk*32;
            xh[k] = z; xh[128+k] = z; xl[k] = z; xl[128+k] = z;
        }
        return;
    }
    float fcy = -1.f + 1.f/(float)H2 + (2.f/(float)H2)*(float)iy;
    float fcx = -1.f + 1.f/(float)H2 + (2.f/(float)H2)*(float)ix;
    float rely = (cy - fcy)*(float)H2;
    float relx = (cx - fcx)*(float)H2;
    float rc0 = cell[((size_t)b*QQ + q)*2 + 0]*(float)H2;
    float rc1 = cell[((size_t)b*QQ + q)*2 + 1]*(float)H2;
    size_t base = (((size_t)b*H2 + iy)*H2 + ix)*HID;
    const float*  cf = g_coef + base;
    const float2* fq = (const float2*)(g_freq + base);
    const float2* pw = (const float2*)phase_w;
    const float PI = 3.14159265358979f;
    #pragma unroll
    for (int kk = 0; kk < 4; kk++) {
        int k = lane + kk*32;
        float2 f = fq[k];
        float2 p = pw[k];
        float s = (f.x*rely + f.y*relx + rc0*p.x + rc1*p.y) * PI;
        float v0 = cf[k]       * __cosf(s);
        float v1 = cf[128 + k] * __sinf(s);
        __nv_bfloat16 h0 = __float2bfloat16(v0);
        __nv_bfloat16 h1 = __float2bfloat16(v1);
        xh[k]     = h0; xl[k]     = __float2bfloat16(v0 - __bfloat162float(h0));
        xh[128+k] = h1; xl[128+k] = __float2bfloat16(v1 - __bfloat162float(h1));
    }
}

// ---------------- mma.sync bf16 GEMM (3-pass split) + bias + relu -------------
// layer 0: X0 -> X1 (bf16 hi/lo). layer 1: X1 -> fused final 256->3 via atomics.
#define GM_BB 0
#define GM_AB 131072
#define GM_SMEM 196608

__global__ void __launch_bounds__(256, 1) gemm_mma(const float* __restrict__ bias, int layer,
                                                   const float* __restrict__ w3,
                                                   const float* __restrict__ b3,
                                                   float* __restrict__ out) {
    extern __shared__ __align__(16) char smc[];
    __shared__ float sbias[128];
    __shared__ float w3s[3*128];
    uint32_t sb;
    asm("{ .reg .u64 t; cvta.to.shared.u64 t, %1; cvt.u32.u64 %0, t; }" : "=r"(sb) : "l"(smc));
    int tid = threadIdx.x, wid = tid >> 5, lane = tid & 31;
    int grp = lane >> 2, t4 = lane & 3;
    int m0 = blockIdx.x * 128;
    int n0 = blockIdx.y * 128;
    int wm = wid >> 1, wn = wid & 1;
    int mb = wm * 32, nb = wn * 64;

    const __nv_bfloat16* Ah = layer ? g_X1h : g_X0h;
    const __nv_bfloat16* Al = layer ? g_X1l : g_X0l;
    const __nv_bfloat16* Wh = g_Wh[layer];
    const __nv_bfloat16* Wl = g_Wl[layer];

    for (int i = tid; i < 8192; i += 256) {
        int half = i >> 12; int rem = i & 4095; int n = rem >> 5; int j = rem & 31;
        const __nv_bfloat16* src = (half ? Wl : Wh) + (size_t)(n0 + n)*256 + j*8;
        cpa16(smc + GM_BB + half*65536 + n*512 + ((j*16) ^ ((n&7)<<4)), src);
    }
    for (int i = tid; i < 2048; i += 256) {
        int half = i >> 10; int rem = i & 1023; int m = rem >> 3; int j = rem & 7;
        const __nv_bfloat16* src = (half ? Al : Ah) + (size_t)(m0 + m)*256 + j*8;
        cpa16(smc + GM_AB + half*16384 + m*128 + ((j*16) ^ ((m&7)<<4)), src);
    }
    asm volatile("cp.async.commit_group;" ::: "memory");
    if (tid < 128) {
        sbias[tid] = bias[n0 + tid];
        if (layer) {
            w3s[tid]       = w3[0*256 + n0 + tid];
            w3s[128 + tid] = w3[1*256 + n0 + tid];
            w3s[256 + tid] = w3[2*256 + n0 + tid];
        }
    }

    float acc[2][8][4];
    #pragma unroll
    for (int t = 0; t < 2; t++)
        #pragma unroll
        for (int u = 0; u < 8; u++)
            #pragma unroll
            for (int j = 0; j < 4; j++) acc[t][u][j] = 0.f;

    uint32_t swz = (uint32_t)(grp << 4);
    uint32_t t4x4 = (uint32_t)(t4 * 4);
    uint32_t bB = sb + GM_BB;

    for (int c = 0; c < 4; c++) {
        if (c < 3) {
            int cn = c + 1;
            char* dstb = smc + GM_AB + (cn & 1)*32768;
            for (int i = tid; i < 2048; i += 256) {
                int half = i >> 10; int rem = i & 1023; int m = rem >> 3; int j = rem & 7;
                const __nv_bfloat16* src = (half ? Al : Ah) + (size_t)(m0 + m)*256 + cn*64 + j*8;
                cpa16(dstb + half*16384 + m*128 + ((j*16) ^ ((m&7)<<4)), src);
            }
            asm volatile("cp.async.commit_group;" ::: "memory");
            asm volatile("cp.async.wait_group 1;" ::: "memory");
        } else {
            asm volatile("cp.async.wait_group 0;" ::: "memory");
        }
        __syncthreads();

        uint32_t bA = sb + GM_AB + (c & 1)*32768;
        #pragma unroll
        for (int ks = 0; ks < 4; ks++) {
            uint32_t ko  = (((uint32_t)(ks*32)) ^ swz) + t4x4;
            uint32_t koh = (((uint32_t)(ks*32+16)) ^ swz) + t4x4;
            uint32_t ahf[2][4], alf[2][4], bhf[8][2], blf[8][2];
            #pragma unroll
            for (int t = 0; t < 2; t++) {
                uint32_t ra = bA + (uint32_t)((mb + t*16 + grp)*128);
                ahf[t][0] = lds32(ra + ko);
                ahf[t][1] = lds32(ra + 1024 + ko);
                ahf[t][2] = lds32(ra + koh);
                ahf[t][3] = lds32(ra + 1024 + koh);
                alf[t][0] = lds32(ra + 16384 + ko);
                alf[t][1] = lds32(ra + 16384 + 1024 + ko);
                alf[t][2] = lds32(ra + 16384 + koh);
                alf[t][3] = lds32(ra + 16384 + 1024 + koh);
            }
            uint32_t kob  = (((uint32_t)(c*128 + ks*32)) ^ swz) + t4x4;
            uint32_t kobh = (((uint32_t)(c*128 + ks*32+16)) ^ swz) + t4x4;
            #pragma unroll
            for (int u = 0; u < 8; u++) {
                uint32_t rb = bB + (uint32_t)((nb + u*8 + grp)*512);
                bhf[u][0] = lds32(rb + kob);
                bhf[u][1] = lds32(rb + kobh);
                blf[u][0] = lds32(rb + 65536 + kob);
                blf[u][1] = lds32(rb + 65536 + kobh);
            }
            #pragma unroll
            for (int t = 0; t < 2; t++)
                #pragma unroll
                for (int u = 0; u < 8; u++)
                    mma16816(acc[t][u], ahf[t][0], ahf[t][1], ahf[t][2], ahf[t][3], bhf[u][0], bhf[u][1]);
            #pragma unroll
            for (int t = 0; t < 2; t++)
                #pragma unroll
                for (int u = 0; u < 8; u++)
                    mma16816(acc[t][u], ahf[t][0], ahf[t][1], ahf[t][2], ahf[t][3], blf[u][0], blf[u][1]);
            #pragma unroll
            for (int t = 0; t < 2; t++)
                #pragma unroll
                for (int u = 0; u < 8; u++)
                    mma16816(acc[t][u], alf[t][0], alf[t][1], alf[t][2], alf[t][3], bhf[u][0], bhf[u][1]);
        }
        __syncthreads();
    }

    if (layer == 0) {
        #pragma unroll
        for (int t = 0; t < 2; t++) {
            int r0 = m0 + mb + t*16 + grp;
            int r1 = r0 + 8;
            #pragma unroll
            for (int u = 0; u < 8; u++) {
                int cb = nb + u*8 + t4*2;
                float b0v = sbias[cb], b1v = sbias[cb+1];
                float v00 = fmaxf(acc[t][u][0] + b0v, 0.f);
                float v01 = fmaxf(acc[t][u][1] + b1v, 0.f);
                float v10 = fmaxf(acc[t][u][2] + b0v, 0.f);
                float v11 = fmaxf(acc[t][u][3] + b1v, 0.f);
                int gcol = n0 + cb;
                __nv_bfloat162 h0 = __float22bfloat162_rn(make_float2(v00, v01));
                __nv_bfloat162 h1 = __float22bfloat162_rn(make_float2(v10, v11));
                __nv_bfloat162 l0, l1;
                l0.x = __float2bfloat16(v00 - __bfloat162float(h0.x));
                l0.y = __float2bfloat16(v01 - __bfloat162float(h0.y));
                l1.x = __float2bfloat16(v10 - __bfloat162float(h1.x));
                l1.y = __float2bfloat16(v11 - __bfloat162float(h1.y));
                *(__nv_bfloat162*)&g_X1h[(size_t)r0*256 + gcol] = h0;
                *(__nv_bfloat162*)&g_X1h[(size_t)r1*256 + gcol] = h1;
                *(__nv_bfloat162*)&g_X1l[(size_t)r0*256 + gcol] = l0;
                *(__nv_bfloat162*)&g_X1l[(size_t)r1*256 + gcol] = l1;
            }
        }
    } else {
        #pragma unroll
        for (int t = 0; t < 2; t++) {
            int r0 = m0 + mb + t*16 + grp;
            int r1 = r0 + 8;
            float p0[3] = {0.f, 0.f, 0.f};
            float p1[3] = {0.f, 0.f, 0.f};
            #pragma unroll
            for (int u = 0; u < 8; u++) {
                int cb = nb + u*8 + t4*2;
                float b0v = sbias[cb], b1v = sbias[cb+1];
                float v00 = fmaxf(acc[t][u][0] + b0v, 0.f);
                float v01 = fmaxf(acc[t][u][1] + b1v, 0.f);
                float v10 = fmaxf(acc[t][u][2] + b0v, 0.f);
                float v11 = fmaxf(acc[t][u][3] + b1v, 0.f);
                #pragma unroll
                for (int cc = 0; cc < 3; cc++) {
                    float w0 = w3s[cc*128 + cb], w1 = w3s[cc*128 + cb + 1];
                    p0[cc] += v00*w0 + v01*w1;
                    p1[cc] += v10*w0 + v11*w1;
                }
            }
            #pragma unroll
            for (int cc = 0; cc < 3; cc++) {
                p0[cc] += __shfl_xor_sync(0xffffffffu, p0[cc], 1);
                p0[cc] += __shfl_xor_sync(0xffffffffu, p0[cc], 2);
                p1[cc] += __shfl_xor_sync(0xffffffffu, p1[cc], 1);
                p1[cc] += __shfl_xor_sync(0xffffffffu, p1[cc], 2);
            }
            if (t4 == 0) {
                #pragma unroll
                for (int cc = 0; cc < 3; cc++) {
                    float bb = (n0 == 0) ? b3[cc] : 0.f;
                    atomicAdd(&out[(size_t)r0*3 + cc], p0[cc] + bb);
                    atomicAdd(&out[(size_t)r1*3 + cc], p1[cc] + bb);
                }
            }
        }
    }
}

// ---------------- launch -------------------------------------------------------
extern "C" void kernel_launch(void* const* d_in, const int* in_sizes, int n_in,
                              void* d_out, int out_size) {
    const float* feat    = (const float*)d_in[0];
    const float* coord   = (const float*)d_in[1];
    const float* cell    = (const float*)d_in[2];
    const float* cls_w1  = (const float*)d_in[3];
    const float* cls_b1  = (const float*)d_in[4];
    const float* cls_w2  = (const float*)d_in[5];
    const float* cls_b2  = (const float*)d_in[6];
    const float* sigma_x = (const float*)d_in[7];
    const float* sigma_y = (const float*)d_in[8];
    const float* opacity = (const float*)d_in[9];
    const float* rho     = (const float*)d_in[10];
    const float* coef_w  = (const float*)d_in[11];
    const float* coef_b  = (const float*)d_in[12];
    const float* freq_w  = (const float*)d_in[13];
    const float* freq_b  = (const float*)d_in[14];
    const float* phase_w = (const float*)d_in[15];
    const float* mlp_w1  = (const float*)d_in[16];
    const float* mlp_b1  = (const float*)d_in[17];
    const float* mlp_w2  = (const float*)d_in[18];
    const float* mlp_b2  = (const float*)d_in[19];
    const float* mlp_w3  = (const float*)d_in[20];
    const float* mlp_b3  = (const float*)d_in[21];
    float* out = (float*)d_out;

    cudaFuncSetAttribute(conv112p, cudaFuncAttributeMaxDynamicSharedMemorySize, CONVP_SMEM);
    cudaFuncSetAttribute(splat,    cudaFuncAttributeMaxDynamicSharedMemorySize, SPLAT_SMEM);
    cudaFuncSetAttribute(conv224m, cudaFuncAttributeMaxDynamicSharedMemorySize, CM_SMEM);
    cudaFuncSetAttribute(gemm_mma, cudaFuncAttributeMaxDynamicSharedMemorySize, GM_SMEM);

    conv112p<<<dim3(49, 4, BB), 256, CONVP_SMEM>>>(feat, cls_w1, cls_b1);
    logits_stats<<<196, 256>>>(cls_w2, cls_b2, sigma_x, sigma_y, opacity, rho);
    splat<<<1024, 196, SPLAT_SMEM>>>(feat);
    pack_cw<<<1152, 256>>>(coef_w, freq_w);
    conv224m<<<dim3(196, 2, BB*2), 512, CM_SMEM>>>(coef_b, freq_b);
    pack_mlp<<<512, 256>>>(mlp_w1, mlp_w2);
    gather_basis<<<MTOT/8, 256>>>(coord, cell, phase_w, out);
    gemm_mma<<<dim3(MTOT/128, 2), 256, GM_SMEM>>>(mlp_b1, 0, mlp_w3, mlp_b3, out);
    gemm_mma<<<dim3(MTOT/128, 2), 256, GM_SMEM>>>(mlp_b2, 1, mlp_w3, mlp_b3, out);
}

// round 10
// speedup vs baseline: 7.6838x; 1.2557x over previous
#include <cuda_runtime.h>
#include <cuda_fp16.h>
#include <math.h>
#include <stdint.h>

#define CIN 64
#define NGRP 100
#define HID 256
#define BB 4
#define HH 112
#define H2 224
#define QQ 50176
#define MTOT (BB*QQ)   // 200704

typedef unsigned long long ull;

__device__ __forceinline__ ull pk2(float a, float b) {
    ull r; asm("mov.b64 %0,{%1,%2};" : "=l"(r) : "f"(a), "f"(b)); return r;
}
__device__ __forceinline__ void fma2(ull& d, ull a, ull b) {
    asm("fma.rn.f32x2 %0,%1,%2,%0;" : "+l"(d) : "l"(a), "l"(b));
}
__device__ __forceinline__ void upk2(ull v, float& a, float& b) {
    asm("mov.b64 {%0,%1},%2;" : "=f"(a), "=f"(b) : "l"(v));
}
__device__ __forceinline__ void cpa16(void* dst, const void* src) {
    unsigned d = (unsigned)__cvta_generic_to_shared(dst);
    asm volatile("cp.async.cg.shared.global [%0], [%1], 16;" :: "r"(d), "l"(src));
}
__device__ __forceinline__ void cpa16z(void* dst, const void* src, int sz) {
    unsigned d = (unsigned)__cvta_generic_to_shared(dst);
    asm volatile("cp.async.cg.shared.global [%0], [%1], 16, %2;" :: "r"(d), "l"(src), "r"(sz));
}
__device__ __forceinline__ uint32_t lds32(uint32_t a) {
    uint32_t v; asm volatile("ld.shared.b32 %0,[%1];" : "=r"(v) : "r"(a)); return v;
}
__device__ __forceinline__ void mma16816(float* c, uint32_t a0, uint32_t a1, uint32_t a2, uint32_t a3,
                                         uint32_t b0, uint32_t b1) {
    asm volatile("mma.sync.aligned.m16n8k16.row.col.f32.f16.f16.f32 "
        "{%0,%1,%2,%3},{%4,%5,%6,%7},{%8,%9},{%0,%1,%2,%3};"
        : "+f"(c[0]), "+f"(c[1]), "+f"(c[2]), "+f"(c[3])
        : "r"(a0), "r"(a1), "r"(a2), "r"(a3), "r"(b0), "r"(b1));
}

// ---------------- scratch -----------------------------------------------------
__device__ float g_h[(size_t)BB*CIN*HH*HH];
__device__ float g_wstat[49*4];
__device__ int   g_ctr;
__device__ float g_ktw[49*196];
__device__ __align__(16) __half g_gfh[(size_t)BB*H2*H2*64];  // NHWC fp16
__device__ float g_coef[(size_t)BB*H2*H2*HID];
__device__ float g_freq[(size_t)BB*H2*H2*HID];
__device__ __align__(16) __half g_X0h[(size_t)MTOT*HID];
__device__ __align__(16) __half g_X1h[(size_t)MTOT*HID];
__device__ __align__(16) unsigned char g_cw[(size_t)2*2*9*32768];   // conv224 fp16 hi/lo swizzled
__device__ __align__(16) __half g_Wh[2][65536];
__device__ __align__(16) __half g_Wl[2][65536];

// ---------------- conv3x3 64->64 @112, relu, NCHW out (packed f32x2) ----------
#define CONVP_SMEM (64*18*18*4 + 64*8*10*8)

__global__ void conv112p(const float* __restrict__ in,
                         const float* __restrict__ w,
                         const float* __restrict__ bias) {
    extern __shared__ float sm[];
    float* ins = sm;
    ull*   wsp = (ull*)(sm + 64*324);
    int tile = blockIdx.x;
    int co0  = blockIdx.y * 16;
    int b    = blockIdx.z;
    int ty0 = (tile / 7) * 16, tx0 = (tile % 7) * 16;
    int tid = threadIdx.x;
    if (tile == 0 && blockIdx.y == 0 && b == 0 && tid < 196) g_wstat[tid] = 0.f;

    const float* inb = in + (size_t)b * CIN * HH * HH;
    for (int i = tid; i < 64*18*18; i += 256) {
        int ci = i / 324; int r = (i % 324) / 18; int c = i % 18;
        int gy = ty0 + r - 1, gx = tx0 + c - 1;
        float v = 0.f;
        if (gy >= 0 && gy < HH && gx >= 0 && gx < HH) v = inb[(ci*HH + gy)*HH + gx];
        ins[i] = v;
    }
    float* wspf = (float*)wsp;
    for (int i = tid; i < 64*8*9*2; i += 256) {
        int half = i & 1; int e = i >> 1;
        int k = e % 9; int cop = (e/9) & 7; int ci = e/72;
        wspf[((ci*8 + cop)*10 + k)*2 + half] = w[(size_t)(co0 + cop*2 + half)*576 + ci*9 + k];
    }
    __syncthreads();

    int ty = tid / 16, tx = tid % 16;
    ull acc[8];
    #pragma unroll
    for (int cop = 0; cop < 8; cop++) acc[cop] = pk2(bias[co0+2*cop], bias[co0+2*cop+1]);

    for (int ci = 0; ci < 64; ci++) {
        const float* ip = ins + ci*324 + ty*18 + tx;
        ull vv[9];
        #pragma unroll
        for (int dy = 0; dy < 3; dy++)
            #pragma unroll
            for (int dx = 0; dx < 3; dx++) {
                float v = ip[dy*18 + dx];
                vv[dy*3+dx] = pk2(v, v);
            }
        const ull* wbase = wsp + ci*80;
        #pragma unroll
        for (int cop = 0; cop < 8; cop++) {
            const ulonglong2* wc2 = (const ulonglong2*)(wbase + cop*10);
            ulonglong2 p0 = wc2[0], p1 = wc2[1], p2 = wc2[2], p3 = wc2[3];
            ull p8 = (wbase + cop*10)[8];
            fma2(acc[cop], vv[0], p0.x); fma2(acc[cop], vv[1], p0.y);
            fma2(acc[cop], vv[2], p1.x); fma2(acc[cop], vv[3], p1.y);
            fma2(acc[cop], vv[4], p2.x); fma2(acc[cop], vv[5], p2.y);
            fma2(acc[cop], vv[6], p3.x); fma2(acc[cop], vv[7], p3.y);
            fma2(acc[cop], vv[8], p8);
        }
    }
    int oy = ty0 + ty, ox = tx0 + tx;
    #pragma unroll
    for (int cop = 0; cop < 8; cop++) {
        float lo, hi; upk2(acc[cop], lo, hi);
        g_h[(((size_t)b*64 + co0 + 2*cop    )*HH + oy)*HH + ox] = fmaxf(lo, 0.f);
        g_h[(((size_t)b*64 + co0 + 2*cop + 1)*HH + oy)*HH + ox] = fmaxf(hi, 0.f);
    }
}

// ------- pack conv224 weights: fp16 hi/lo, per-tap [co128][ci64] swizzled -----
__global__ void pack_cw(const float* __restrict__ wc, const float* __restrict__ wf) {
    int i = blockIdx.x*256 + threadIdx.x;
    if (i >= 294912) return;
    int ci = i & 63; int t = i >> 6;
    int co = t & 127; t >>= 7;
    int dydx = t % 9; t /= 9;
    int half = t & 1; int sel = t >> 1;
    const float* W = sel ? wf : wc;
    float v = W[(size_t)(half*128 + co)*576 + ci*9 + dydx];
    __half h = __float2half(v);
    __half l = __float2half(v - __half2float(h));
    size_t base = ((size_t)((sel*2 + half)*9 + dydx))*32768;
    uint32_t off = (uint32_t)co*128 + (((uint32_t)(ci>>3)*16) ^ (((uint32_t)co&7)<<4)) + (ci&7)*2;
    *(__half*)(g_cw + base + off)         = h;
    *(__half*)(g_cw + base + 16384 + off) = l;
}

// ------- fused 1x1 conv -> online softmax -> stats -> (last block) ktw --------
__global__ void logits_stats(const float* __restrict__ w2, const float* __restrict__ b2,
                             const float* __restrict__ sx, const float* __restrict__ sy,
                             const float* __restrict__ op, const float* __restrict__ rh) {
    __shared__ float buf[49*196];
    __shared__ float sv[4*NGRP];
    __shared__ float b2s[NGRP];
    __shared__ float accs[196];
    __shared__ float wops[49];
    __shared__ int lastb;
    int tid = threadIdx.x;
    float* ws = buf;
    for (int i = tid; i < NGRP; i += 256) {
        sv[i] = sx[i]; sv[NGRP+i] = sy[i]; sv[2*NGRP+i] = op[i]; sv[3*NGRP+i] = rh[i];
        b2s[i] = b2[i];
    }
    for (int i = tid; i < NGRP*64; i += 256) ws[i] = w2[i];
    for (int i = tid; i < 196; i += 256) accs[i] = 0.f;
    __syncthreads();

    int t = blockIdx.x * 256 + tid;
    int b = t / (HH*HH); int pix = t % (HH*HH);
    int y = pix / HH, x = pix % HH;
    const float* hp = g_h + (size_t)b*64*HH*HH + pix;
    float hv[64];
    #pragma unroll
    for (int ci = 0; ci < 64; ci++) hv[ci] = hp[(size_t)ci*HH*HH];

    float m = -1e30f, s = 0.f, a0 = 0.f, a1 = 0.f, a2 = 0.f, a3 = 0.f;
    for (int g = 0; g < NGRP; g++) {
        float l = b2s[g];
        const float* wg = ws + g*64;
        #pragma unroll
        for (int ci = 0; ci < 64; ci += 4) {
            float4 wv = *(const float4*)(wg + ci);
            l += hv[ci]*wv.x + hv[ci+1]*wv.y + hv[ci+2]*wv.z + hv[ci+3]*wv.w;
        }
        float mn = fmaxf(m, l);
        float sc = __expf(m - mn);
        float e  = __expf(l - mn);
        s  = s*sc + e;
        a0 = a0*sc + e*sv[g];
        a1 = a1*sc + e*sv[NGRP+g];
        a2 = a2*sc + e*sv[2*NGRP+g];
        a3 = a3*sc + e*sv[3*NGRP+g];
        m = mn;
    }
    float inv = 1.f / s;
    int p = (y % 7)*7 + (x % 7);
    atomicAdd(&accs[p*4+0], a0*inv);
    atomicAdd(&accs[p*4+1], a1*inv);
    atomicAdd(&accs[p*4+2], a2*inv);
    atomicAdd(&accs[p*4+3], a3*inv);
    __syncthreads();
    for (int i = tid; i < 196; i += 256) atomicAdd(&g_wstat[i], accs[i]);

    __threadfence();
    if (tid == 0) lastb = (atomicAdd(&g_ctr, 1) == (int)gridDim.x - 1);
    __syncthreads();
    if (!lastb) return;
    if (tid == 0) g_ctr = 0;

    float* kpad = buf;
    for (int i = tid; i < 49*196; i += 256) kpad[i] = 0.f;
    __syncthreads();
    if (tid < 49) {
        int p2 = tid;
        const float inv1024 = 1.f/1024.f;
        float wsx = g_wstat[p2*4+0]*inv1024;
        float wsy = g_wstat[p2*4+1]*inv1024;
        float wop = g_wstat[p2*4+2]*inv1024;
        float wr  = g_wstat[p2*4+3]*inv1024;
        wops[p2] = wop;
        float c00 = wsx*wsx + 1e-5f;
        float c11 = wsy*wsy + 1e-5f;
        float c01 = wr*wsx*wsy;
        float det = c00*c11 - c01*c01;
        float i00 = c11/det, i11 = c00/det, i01 = -c01/det;
        float norm = 1.f/(2.f*3.14159265358979f*sqrtf(det));
        float kv[25]; float kmx = 0.f;
        #pragma unroll
        for (int i = 0; i < 5; i++)
            #pragma unroll
            for (int j = 0; j < 5; j++) {
                float yv = -5.f + 2.5f*i;
                float xv = -5.f + 2.5f*j;
                float z = -0.5f*(i00*xv*xv + 2.f*i01*xv*yv + i11*yv*yv);
                float k = expf(z)*norm;
                kv[i*5+j] = k; kmx = fmaxf(kmx, k);
            }
        float im = 1.f/kmx;
        #pragma unroll
        for (int i = 0; i < 5; i++)
            #pragma unroll
            for (int j = 0; j < 5; j++)
                kpad[p2*196 + (i+4)*14 + (j+4)] = kv[i*5+j]*im;
    }
    __syncthreads();
    for (int idx = tid; idx < 49*196; idx += 256) {
        int p2 = idx/196, hw = idx%196, h = hw/14, w = hw%14;
        float txo = (0.5f - (float)(p2/7)*(1.f/7.f))*2.f;
        float tyo = (0.5f - (float)(p2%7)*(1.f/7.f))*2.f;
        float gxv = -1.f + (2.f/13.f)*w + txo;
        float gyv = -1.f + (2.f/13.f)*h + tyo;
        float px = (gxv + 1.f)*0.5f*13.f;
        float py = (gyv + 1.f)*0.5f*13.f;
        float x0f = floorf(px), y0f = floorf(py);
        int x0 = (int)x0f, y0 = (int)y0f;
        float wx = px - x0f, wy = py - y0f;
        float s00 = (y0   >= 0 && y0   < 14 && x0   >= 0 && x0   < 14) ? kpad[p2*196 + y0*14 + x0]       : 0.f;
        float s01 = (y0   >= 0 && y0   < 14 && x0+1 >= 0 && x0+1 < 14) ? kpad[p2*196 + y0*14 + x0+1]     : 0.f;
        float s10 = (y0+1 >= 0 && y0+1 < 14 && x0   >= 0 && x0   < 14) ? kpad[p2*196 + (y0+1)*14 + x0]   : 0.f;
        float s11 = (y0+1 >= 0 && y0+1 < 14 && x0+1 >= 0 && x0+1 < 14) ? kpad[p2*196 + (y0+1)*14 + x0+1] : 0.f;
        float kt = s00*(1.f-wy)*(1.f-wx) + s01*(1.f-wy)*wx + s10*wy*(1.f-wx) + s11*wy*wx;
        g_ktw[idx] = kt * wops[p2];
    }
}

// ---------------- splat -> NHWC fp16 ------------------------------------------
#define SPLAT_SMEM ((49*196 + 49*64)*4)
__global__ void splat(const float* __restrict__ feat) {
    extern __shared__ float sm[];
    float* kts = sm;             // [p][196]
    float* fp  = sm + 49*196;    // [p][64]
    int bl = blockIdx.x;
    int b = bl / 256; int l = bl % 256; int pr = l / 16, pc = l % 16;
    int tid = threadIdx.x;       // 196
    for (int i = tid; i < 49*196; i += 196) kts[i] = g_ktw[i];
    const float* fb = feat + (size_t)b*64*HH*HH;
    for (int i = tid; i < 49*64; i += 196) {
        int p = i >> 6, c = i & 63;
        fp[i] = fb[((size_t)c*HH + pr*7 + p/7)*HH + pc*7 + p%7];
    }
    __syncthreads();
    int h = tid/14, w = tid%14;
    int oy = pr*14 + h, ox = pc*14 + w;
    size_t pixb = ((size_t)b*H2 + oy)*H2 + ox;
    __half* gh = g_gfh + pixb*64;
    #pragma unroll
    for (int half = 0; half < 2; half++) {
        float a[32];
        #pragma unroll
        for (int j = 0; j < 32; j++) a[j] = 0.f;
        for (int p = 0; p < 49; p++) {
            float k = kts[p*196 + tid];
            const float4* f4 = (const float4*)(fp + p*64 + half*32);
            #pragma unroll
            for (int j = 0; j < 8; j++) {
                float4 v = f4[j];
                a[j*4+0] += k*v.x; a[j*4+1] += k*v.y;
                a[j*4+2] += k*v.z; a[j*4+3] += k*v.w;
            }
        }
        #pragma unroll
        for (int j = 0; j < 32; j += 4) {
            int c0 = half*32 + j;
            *(__half2*)(gh + c0)     = __floats2half2_rn(__saturatef(a[j]),   __saturatef(a[j+1]));
            *(__half2*)(gh + c0 + 2) = __floats2half2_rn(__saturatef(a[j+2]), __saturatef(a[j+3]));
        }
    }
}

// ---------------- conv3x3 64->256 @224 via mma.sync (2-pass fp16) -------------
#define CM_WBASE 41472
#define CM_WBUF  32768
#define CM_SMEM  (41472 + 2*32768)   // 107008

__global__ void __launch_bounds__(512, 1) conv224m(const float* __restrict__ bias_c,
                                                   const float* __restrict__ bias_f) {
    extern __shared__ __align__(16) char smc[];
    __shared__ float sbias[128];
    uint32_t sb;
    asm("{ .reg .u64 t; cvta.to.shared.u64 t, %1; cvt.u32.u64 %0, t; }" : "=r"(sb) : "l"(smc));
    int tid = threadIdx.x, wid = tid >> 5, lane = tid & 31;
    int grp = lane >> 2, t4 = lane & 3;
    int bt = blockIdx.x, cohalf = blockIdx.y;
    int sel = blockIdx.z & 1, b = blockIdx.z >> 1;
    int row0 = (bt/14)*16, col0 = (bt%14)*16;
    int wm = wid >> 1, wn = wid & 1;
    int nb = wn*64;

    const __half* gh = g_gfh + (size_t)b*H2*H2*64;
    const unsigned char* wsrc = g_cw + (size_t)(sel*2 + cohalf)*9*32768;
    const float* bias = sel ? bias_f : bias_c;

    for (int i = tid; i < 2048; i += 512)
        cpa16(smc + CM_WBASE + i*16, wsrc + i*16);
    for (int i = tid; i < 2592; i += 512) {
        int pos = i >> 3, j = i & 7;
        int r = pos / 18, c = pos - r*18;
        int gy = row0 + r - 1, gx = col0 + c - 1;
        int ok = (gy >= 0 && gy < H2 && gx >= 0 && gx < H2);
        const __half* src = gh + ((size_t)(ok ? gy : 0)*H2 + (ok ? gx : 0))*64 + j*8;
        cpa16z(smc + (r*18 + c)*128 + (((uint32_t)j*16) ^ (((uint32_t)c&7)<<4)), src, ok ? 16 : 0);
    }
    asm volatile("cp.async.commit_group;" ::: "memory");
    if (tid < 128) sbias[tid] = bias[cohalf*128 + tid];

    float acc[2][8][4];
    #pragma unroll
    for (int t = 0; t < 2; t++)
        #pragma unroll
        for (int u = 0; u < 8; u++)
            #pragma unroll
            for (int j = 0; j < 4; j++) acc[t][u][j] = 0.f;

    uint32_t swzb = (uint32_t)(grp << 4);
    uint32_t t4x4 = (uint32_t)(t4*4);

    for (int dydx = 0; dydx < 9; dydx++) {
        if (dydx < 8) {
            const unsigned char* src = wsrc + (size_t)(dydx+1)*32768;
            char* dst = smc + CM_WBASE + ((dydx+1)&1)*CM_WBUF;
            for (int i = tid; i < 2048; i += 512)
                cpa16(dst + i*16, src + i*16);
            asm volatile("cp.async.commit_group;" ::: "memory");
            asm volatile("cp.async.wait_group 1;" ::: "memory");
        } else {
            asm volatile("cp.async.wait_group 0;" ::: "memory");
        }
        __syncthreads();

        int dy = dydx/3, dx = dydx - dy*3;
        uint32_t wb = sb + CM_WBASE + (uint32_t)((dydx&1)*CM_WBUF);
        uint32_t swza = (uint32_t)(((grp + dx) & 7) << 4);
        uint32_t aRow0 = sb + (uint32_t)(((wm*2 + dy)*18 + grp + dx)*128);
        uint32_t aRow1 = aRow0 + 18*128;

        #pragma unroll
        for (int ks = 0; ks < 4; ks++) {
            uint32_t kA0 = (((uint32_t)(ks*32)) ^ swza) + t4x4;
            uint32_t kA1 = (((uint32_t)(ks*32 + 16)) ^ swza) + t4x4;
            uint32_t ah[2][4];
            ah[0][0] = lds32(aRow0 + kA0);        ah[0][1] = lds32(aRow0 + 1024 + kA0);
            ah[0][2] = lds32(aRow0 + kA1);        ah[0][3] = lds32(aRow0 + 1024 + kA1);
            ah[1][0] = lds32(aRow1 + kA0);        ah[1][1] = lds32(aRow1 + 1024 + kA0);
            ah[1][2] = lds32(aRow1 + kA1);        ah[1][3] = lds32(aRow1 + 1024 + kA1);
            uint32_t kB0 = (((uint32_t)(ks*32)) ^ swzb) + t4x4;
            uint32_t kB1 = (((uint32_t)(ks*32 + 16)) ^ swzb) + t4x4;
            #pragma unroll
            for (int u = 0; u < 8; u++) {
                uint32_t rb = wb + (uint32_t)((nb + u*8 + grp)*128);
                uint32_t bh0 = lds32(rb + kB0), bh1 = lds32(rb + kB1);
                uint32_t bl0 = lds32(rb + 16384 + kB0), bl1 = lds32(rb + 16384 + kB1);
                mma16816(acc[0][u], ah[0][0], ah[0][1], ah[0][2], ah[0][3], bh0, bh1);
                mma16816(acc[1][u], ah[1][0], ah[1][1], ah[1][2], ah[1][3], bh0, bh1);
                mma16816(acc[0][u], ah[0][0], ah[0][1], ah[0][2], ah[0][3], bl0, bl1);
                mma16816(acc[1][u], ah[1][0], ah[1][1], ah[1][2], ah[1][3], bl0, bl1);
            }
        }
        __syncthreads();
    }

    float* outp = sel ? g_freq : g_coef;
    #pragma unroll
    for (int t = 0; t < 2; t++) {
        int gy = row0 + wm*2 + t;
        #pragma unroll
        for (int u = 0; u < 8; u++) {
            int cidx = nb + u*8 + t4*2;
            float b0 = sbias[cidx], b1 = sbias[cidx+1];
            size_t o0 = (((size_t)b*H2 + gy)*H2 + col0 + grp)*256 + cohalf*128 + cidx;
            size_t o1 = o0 + (size_t)8*256;
            *(float2*)&outp[o0] = make_float2(acc[t][u][0] + b0, acc[t][u][1] + b1);
            *(float2*)&outp[o1] = make_float2(acc[t][u][2] + b0, acc[t][u][3] + b1);
        }
    }
}

// ---------------- pack MLP weights (fp16 hi/lo, row-major) --------------------
__global__ void pack_mlp(const float* __restrict__ w1, const float* __restrict__ w2) {
    int i = blockIdx.x*256 + threadIdx.x;
    int l = i >> 16; int e = i & 65535;
    const float* W = l ? w2 : w1;
    float v = W[e];
    __half h = __float2half(v);
    g_Wh[l][e] = h;
    g_Wl[l][e] = __float2half(v - __half2float(h));
}

// ---------------- gather + fourier basis -> X0 fp16 (+ zero out) --------------
__global__ void gather_basis(const float* __restrict__ coord,
                             const float* __restrict__ cell,
                             const float* __restrict__ phase_w,
                             float* __restrict__ outz) {
    int gid = blockIdx.x*256 + threadIdx.x;
    if (gid < MTOT*3) outz[gid] = 0.f;
    int warp = threadIdx.x / 32, lane = threadIdx.x % 32;
    int m = blockIdx.x * 8 + warp;
    int b = m / QQ; int q = m % QQ;
    float cy = coord[((size_t)b*QQ + q)*2 + 0];
    float cx = coord[((size_t)b*QQ + q)*2 + 1];
    int ix = (int)rintf(((cx + 1.f)*(float)H2 - 1.f)*0.5f);
    int iy = (int)rintf(((cy + 1.f)*(float)H2 - 1.f)*0.5f);
    bool ok = (ix >= 0 && ix < H2 && iy >= 0 && iy < H2);
    __half* xh = g_X0h + (size_t)m*HID;
    if (!ok) {
        __half z = __float2half(0.f);
        #pragma unroll
        for (int kk = 0; kk < 4; kk++) {
            int k = lane + kk*32;
            xh[k] = z; xh[128+k] = z;
        }
        return;
    }
    float fcy = -1.f + 1.f/(float)H2 + (2.f/(float)H2)*(float)iy;
    float fcx = -1.f + 1.f/(float)H2 + (2.f/(float)H2)*(float)ix;
    float rely = (cy - fcy)*(float)H2;
    float relx = (cx - fcx)*(float)H2;
    float rc0 = cell[((size_t)b*QQ + q)*2 + 0]*(float)H2;
    float rc1 = cell[((size_t)b*QQ + q)*2 + 1]*(float)H2;
    size_t base = (((size_t)b*H2 + iy)*H2 + ix)*HID;
    const float*  cf = g_coef + base;
    const float2* fq = (const float2*)(g_freq + base);
    const float2* pw = (const float2*)phase_w;
    const float PI = 3.14159265358979f;
    #pragma unroll
    for (int kk = 0; kk < 4; kk++) {
        int k = lane + kk*32;
        float2 f = fq[k];
        float2 p = pw[k];
        float s = (f.x*rely + f.y*relx + rc0*p.x + rc1*p.y) * PI;
        xh[k]     = __float2half(cf[k]       * __cosf(s));
        xh[128+k] = __float2half(cf[128 + k] * __sinf(s));
    }
}

// ---------------- mma.sync fp16 GEMM (2-pass) + bias + relu -------------------
// layer 0: X0 -> X1 (fp16). layer 1: X1 -> fused final 256->3 via atomics.
#define GM_BB 0
#define GM_AB 131072
#define GM_SMEM (131072 + 2*16384)   // 163840

__global__ void __launch_bounds__(256, 1) gemm_mma(const float* __restrict__ bias, int layer,
                                                   const float* __restrict__ w3,
                                                   const float* __restrict__ b3,
                                                   float* __restrict__ out) {
    extern __shared__ __align__(16) char smc[];
    __shared__ float sbias[128];
    __shared__ float w3s[3*128];
    uint32_t sb;
    asm("{ .reg .u64 t; cvta.to.shared.u64 t, %1; cvt.u32.u64 %0, t; }" : "=r"(sb) : "l"(smc));
    int tid = threadIdx.x, wid = tid >> 5, lane = tid & 31;
    int grp = lane >> 2, t4 = lane & 3;
    int m0 = blockIdx.x * 128;
    int n0 = blockIdx.y * 128;
    int wm = wid >> 1, wn = wid & 1;
    int mb = wm * 32, nb = wn * 64;

    const __half* Ah = layer ? g_X1h : g_X0h;
    const __half* Wh = g_Wh[layer];
    const __half* Wl = g_Wl[layer];

    for (int i = tid; i < 8192; i += 256) {
        int half = i >> 12; int rem = i & 4095; int n = rem >> 5; int j = rem & 31;
        const __half* src = (half ? Wl : Wh) + (size_t)(n0 + n)*256 + j*8;
        cpa16(smc + GM_BB + half*65536 + n*512 + ((j*16) ^ ((n&7)<<4)), src);
    }
    for (int i = tid; i < 1024; i += 256) {
        int m = i >> 3; int j = i & 7;
        const __half* src = Ah + (size_t)(m0 + m)*256 + j*8;
        cpa16(smc + GM_AB + m*128 + ((j*16) ^ ((m&7)<<4)), src);
    }
    asm volatile("cp.async.commit_group;" ::: "memory");
    if (tid < 128) {
        sbias[tid] = bias[n0 + tid];
        if (layer) {
            w3s[tid]       = w3[0*256 + n0 + tid];
            w3s[128 + tid] = w3[1*256 + n0 + tid];
            w3s[256 + tid] = w3[2*256 + n0 + tid];
        }
    }

    float acc[2][8][4];
    #pragma unroll
    for (int t = 0; t < 2; t++)
        #pragma unroll
        for (int u = 0; u < 8; u++)
            #pragma unroll
            for (int j = 0; j < 4; j++) acc[t][u][j] = 0.f;

    uint32_t swz = (uint32_t)(grp << 4);
    uint32_t t4x4 = (uint32_t)(t4 * 4);
    uint32_t bB = sb + GM_BB;

    for (int c = 0; c < 4; c++) {
        if (c < 3) {
            int cn = c + 1;
            char* dstb = smc + GM_AB + (cn & 1)*16384;
            for (int i = tid; i < 1024; i += 256) {
                int m = i >> 3; int j = i & 7;
                const __half* src = Ah + (size_t)(m0 + m)*256 + cn*64 + j*8;
                cpa16(dstb + m*128 + ((j*16) ^ ((m&7)<<4)), src);
            }
            asm volatile("cp.async.commit_group;" ::: "memory");
            asm volatile("cp.async.wait_group 1;" ::: "memory");
        } else {
            asm volatile("cp.async.wait_group 0;" ::: "memory");
        }
        __syncthreads();

        uint32_t bA = sb + GM_AB + (c & 1)*16384;
        #pragma unroll
        for (int ks = 0; ks < 4; ks++) {
            uint32_t ko  = (((uint32_t)(ks*32)) ^ swz) + t4x4;
            uint32_t koh = (((uint32_t)(ks*32+16)) ^ swz) + t4x4;
            uint32_t ahf[2][4], bhf[8][2], blf[8][2];
            #pragma unroll
            for (int t = 0; t < 2; t++) {
                uint32_t ra = bA + (uint32_t)((mb + t*16 + grp)*128);
                ahf[t][0] = lds32(ra + ko);
                ahf[t][1] = lds32(ra + 1024 + ko);
                ahf[t][2] = lds32(ra + koh);
                ahf[t][3] = lds32(ra + 1024 + koh);
            }
            uint32_t kob  = (((uint32_t)(c*128 + ks*32)) ^ swz) + t4x4;
            uint32_t kobh = (((uint32_t)(c*128 + ks*32+16)) ^ swz) + t4x4;
            #pragma unroll
            for (int u = 0; u < 8; u++) {
                uint32_t rb = bB + (uint32_t)((nb + u*8 + grp)*512);
                bhf[u][0] = lds32(rb + kob);
                bhf[u][1] = lds32(rb + kobh);
                blf[u][0] = lds32(rb + 65536 + kob);
                blf[u][1] = lds32(rb + 65536 + kobh);
            }
            #pragma unroll
            for (int t = 0; t < 2; t++)
                #pragma unroll
                for (int u = 0; u < 8; u++)
                    mma16816(acc[t][u], ahf[t][0], ahf[t][1], ahf[t][2], ahf[t][3], bhf[u][0], bhf[u][1]);
            #pragma unroll
            for (int t = 0; t < 2; t++)
                #pragma unroll
                for (int u = 0; u < 8; u++)
                    mma16816(acc[t][u], ahf[t][0], ahf[t][1], ahf[t][2], ahf[t][3], blf[u][0], blf[u][1]);
        }
        __syncthreads();
    }

    if (layer == 0) {
        #pragma unroll
        for (int t = 0; t < 2; t++) {
            int r0 = m0 + mb + t*16 + grp;
            int r1 = r0 + 8;
            #pragma unroll
            for (int u = 0; u < 8; u++) {
                int cb = nb + u*8 + t4*2;
                float b0v = sbias[cb], b1v = sbias[cb+1];
                float v00 = fmaxf(acc[t][u][0] + b0v, 0.f);
                float v01 = fmaxf(acc[t][u][1] + b1v, 0.f);
                float v10 = fmaxf(acc[t][u][2] + b0v, 0.f);
                float v11 = fmaxf(acc[t][u][3] + b1v, 0.f);
                int gcol = n0 + cb;
                *(__half2*)&g_X1h[(size_t)r0*256 + gcol] = __floats2half2_rn(v00, v01);
                *(__half2*)&g_X1h[(size_t)r1*256 + gcol] = __floats2half2_rn(v10, v11);
            }
        }
    } else {
        #pragma unroll
        for (int t = 0; t < 2; t++) {
            int r0 = m0 + mb + t*16 + grp;
            int r1 = r0 + 8;
            float p0[3] = {0.f, 0.f, 0.f};
            float p1[3] = {0.f, 0.f, 0.f};
            #pragma unroll
            for (int u = 0; u < 8; u++) {
                int cb = nb + u*8 + t4*2;
                float b0v = sbias[cb], b1v = sbias[cb+1];
                float v00 = fmaxf(acc[t][u][0] + b0v, 0.f);
                float v01 = fmaxf(acc[t][u][1] + b1v, 0.f);
                float v10 = fmaxf(acc[t][u][2] + b0v, 0.f);
                float v11 = fmaxf(acc[t][u][3] + b1v, 0.f);
                #pragma unroll
                for (int cc = 0; cc < 3; cc++) {
                    float w0 = w3s[cc*128 + cb], w1 = w3s[cc*128 + cb + 1];
                    p0[cc] += v00*w0 + v01*w1;
                    p1[cc] += v10*w0 + v11*w1;
                }
            }
            #pragma unroll
            for (int cc = 0; cc < 3; cc++) {
                p0[cc] += __shfl_xor_sync(0xffffffffu, p0[cc], 1);
                p0[cc] += __shfl_xor_sync(0xffffffffu, p0[cc], 2);
                p1[cc] += __shfl_xor_sync(0xffffffffu, p1[cc], 1);
                p1[cc] += __shfl_xor_sync(0xffffffffu, p1[cc], 2);
            }
            if (t4 == 0) {
                #pragma unroll
                for (int cc = 0; cc < 3; cc++) {
                    float bb = (n0 == 0) ? b3[cc] : 0.f;
                    atomicAdd(&out[(size_t)r0*3 + cc], p0[cc] + bb);
                    atomicAdd(&out[(size_t)r1*3 + cc], p1[cc] + bb);
                }
            }
        }
    }
}

// ---------------- launch -------------------------------------------------------
extern "C" void kernel_launch(void* const* d_in, const int* in_sizes, int n_in,
                              void* d_out, int out_size) {
    const float* feat    = (const float*)d_in[0];
    const float* coord   = (const float*)d_in[1];
    const float* cell    = (const float*)d_in[2];
    const float* cls_w1  = (const float*)d_in[3];
    const float* cls_b1  = (const float*)d_in[4];
    const float* cls_w2  = (const float*)d_in[5];
    const float* cls_b2  = (const float*)d_in[6];
    const float* sigma_x = (const float*)d_in[7];
    const float* sigma_y = (const float*)d_in[8];
    const float* opacity = (const float*)d_in[9];
    const float* rho     = (const float*)d_in[10];
    const float* coef_w  = (const float*)d_in[11];
    const float* coef_b  = (const float*)d_in[12];
    const float* freq_w  = (const float*)d_in[13];
    const float* freq_b  = (const float*)d_in[14];
    const float* phase_w = (const float*)d_in[15];
    const float* mlp_w1  = (const float*)d_in[16];
    const float* mlp_b1  = (const float*)d_in[17];
    const float* mlp_w2  = (const float*)d_in[18];
    const float* mlp_b2  = (const float*)d_in[19];
    const float* mlp_w3  = (const float*)d_in[20];
    const float* mlp_b3  = (const float*)d_in[21];
    float* out = (float*)d_out;

    cudaFuncSetAttribute(conv112p, cudaFuncAttributeMaxDynamicSharedMemorySize, CONVP_SMEM);
    cudaFuncSetAttribute(splat,    cudaFuncAttributeMaxDynamicSharedMemorySize, SPLAT_SMEM);
    cudaFuncSetAttribute(conv224m, cudaFuncAttributeMaxDynamicSharedMemorySize, CM_SMEM);
    cudaFuncSetAttribute(gemm_mma, cudaFuncAttributeMaxDynamicSharedMemorySize, GM_SMEM);

    conv112p<<<dim3(49, 4, BB), 256, CONVP_SMEM>>>(feat, cls_w1, cls_b1);
    logits_stats<<<196, 256>>>(cls_w2, cls_b2, sigma_x, sigma_y, opacity, rho);
    splat<<<1024, 196, SPLAT_SMEM>>>(feat);
    pack_cw<<<1152, 256>>>(coef_w, freq_w);
    conv224m<<<dim3(196, 2, BB*2), 512, CM_SMEM>>>(coef_b, freq_b);
    pack_mlp<<<512, 256>>>(mlp_w1, mlp_w2);
    gather_basis<<<MTOT/8, 256>>>(coord, cell, phase_w, out);
    gemm_mma<<<dim3(MTOT/128, 2), 256, GM_SMEM>>>(mlp_b1, 0, mlp_w3, mlp_b3, out);
    gemm_mma<<<dim3(MTOT/128, 2), 256, GM_SMEM>>>(mlp_b2, 1, mlp_w3, mlp_b3, out);
}

// round 11
// speedup vs baseline: 10.2410x; 1.3328x over previous
#include <cuda_runtime.h>
#include <cuda_fp16.h>
#include <math.h>
#include <stdint.h>

#define CIN 64
#define NGRP 100
#define HID 256
#define BB 4
#define HH 112
#define H2 224
#define QQ 50176
#define MTOT (BB*QQ)   // 200704

typedef unsigned long long ull;

__device__ __forceinline__ ull pk2(float a, float b) {
    ull r; asm("mov.b64 %0,{%1,%2};" : "=l"(r) : "f"(a), "f"(b)); return r;
}
__device__ __forceinline__ void fma2(ull& d, ull a, ull b) {
    asm("fma.rn.f32x2 %0,%1,%2,%0;" : "+l"(d) : "l"(a), "l"(b));
}
__device__ __forceinline__ void upk2(ull v, float& a, float& b) {
    asm("mov.b64 {%0,%1},%2;" : "=f"(a), "=f"(b) : "l"(v));
}
__device__ __forceinline__ void cpa16(void* dst, const void* src) {
    unsigned d = (unsigned)__cvta_generic_to_shared(dst);
    asm volatile("cp.async.cg.shared.global [%0], [%1], 16;" :: "r"(d), "l"(src));
}
__device__ __forceinline__ void cpa16z(void* dst, const void* src, int sz) {
    unsigned d = (unsigned)__cvta_generic_to_shared(dst);
    asm volatile("cp.async.cg.shared.global [%0], [%1], 16, %2;" :: "r"(d), "l"(src), "r"(sz));
}
__device__ __forceinline__ uint32_t lds32(uint32_t a) {
    uint32_t v; asm volatile("ld.shared.b32 %0,[%1];" : "=r"(v) : "r"(a)); return v;
}
__device__ __forceinline__ void mma16816(float* c, uint32_t a0, uint32_t a1, uint32_t a2, uint32_t a3,
                                         uint32_t b0, uint32_t b1) {
    asm volatile("mma.sync.aligned.m16n8k16.row.col.f32.f16.f16.f32 "
        "{%0,%1,%2,%3},{%4,%5,%6,%7},{%8,%9},{%0,%1,%2,%3};"
        : "+f"(c[0]), "+f"(c[1]), "+f"(c[2]), "+f"(c[3])
        : "r"(a0), "r"(a1), "r"(a2), "r"(a3), "r"(b0), "r"(b1));
}

// ---------------- scratch -----------------------------------------------------
__device__ float g_h[(size_t)BB*CIN*HH*HH];
__device__ float g_wstat[49*4];
__device__ int   g_ctr;
__device__ float g_ktw[49*196];
__device__ __align__(16) __half g_gfh[(size_t)BB*H2*H2*64];  // NHWC fp16
__device__ float g_coef[(size_t)BB*H2*H2*HID];
__device__ float g_freq[(size_t)BB*H2*H2*HID];
__device__ __align__(16) __half g_X0h[(size_t)MTOT*HID];
__device__ __align__(16) __half g_X1h[(size_t)MTOT*HID];
__device__ __align__(16) unsigned char g_cw[(size_t)2*2*9*16384];   // conv224 fp16 swizzled
__device__ __align__(16) __half g_Wh[2][65536];

// ---------------- conv3x3 64->64 @112, relu, NCHW out (packed f32x2) ----------
#define CONVP_SMEM (64*18*18*4 + 64*8*10*8)

__global__ void conv112p(const float* __restrict__ in,
                         const float* __restrict__ w,
                         const float* __restrict__ bias) {
    extern __shared__ float sm[];
    float* ins = sm;
    ull*   wsp = (ull*)(sm + 64*324);
    int tile = blockIdx.x;
    int co0  = blockIdx.y * 16;
    int b    = blockIdx.z;
    int ty0 = (tile / 7) * 16, tx0 = (tile % 7) * 16;
    int tid = threadIdx.x;
    if (tile == 0 && blockIdx.y == 0 && b == 0 && tid < 196) g_wstat[tid] = 0.f;

    const float* inb = in + (size_t)b * CIN * HH * HH;
    for (int i = tid; i < 64*18*18; i += 256) {
        int ci = i / 324; int r = (i % 324) / 18; int c = i % 18;
        int gy = ty0 + r - 1, gx = tx0 + c - 1;
        float v = 0.f;
        if (gy >= 0 && gy < HH && gx >= 0 && gx < HH) v = inb[(ci*HH + gy)*HH + gx];
        ins[i] = v;
    }
    float* wspf = (float*)wsp;
    for (int i = tid; i < 64*8*9*2; i += 256) {
        int half = i & 1; int e = i >> 1;
        int k = e % 9; int cop = (e/9) & 7; int ci = e/72;
        wspf[((ci*8 + cop)*10 + k)*2 + half] = w[(size_t)(co0 + cop*2 + half)*576 + ci*9 + k];
    }
    __syncthreads();

    int ty = tid / 16, tx = tid % 16;
    ull acc[8];
    #pragma unroll
    for (int cop = 0; cop < 8; cop++) acc[cop] = pk2(bias[co0+2*cop], bias[co0+2*cop+1]);

    for (int ci = 0; ci < 64; ci++) {
        const float* ip = ins + ci*324 + ty*18 + tx;
        ull vv[9];
        #pragma unroll
        for (int dy = 0; dy < 3; dy++)
            #pragma unroll
            for (int dx = 0; dx < 3; dx++) {
                float v = ip[dy*18 + dx];
                vv[dy*3+dx] = pk2(v, v);
            }
        const ull* wbase = wsp + ci*80;
        #pragma unroll
        for (int cop = 0; cop < 8; cop++) {
            const ulonglong2* wc2 = (const ulonglong2*)(wbase + cop*10);
            ulonglong2 p0 = wc2[0], p1 = wc2[1], p2 = wc2[2], p3 = wc2[3];
            ull p8 = (wbase + cop*10)[8];
            fma2(acc[cop], vv[0], p0.x); fma2(acc[cop], vv[1], p0.y);
            fma2(acc[cop], vv[2], p1.x); fma2(acc[cop], vv[3], p1.y);
            fma2(acc[cop], vv[4], p2.x); fma2(acc[cop], vv[5], p2.y);
            fma2(acc[cop], vv[6], p3.x); fma2(acc[cop], vv[7], p3.y);
            fma2(acc[cop], vv[8], p8);
        }
    }
    int oy = ty0 + ty, ox = tx0 + tx;
    #pragma unroll
    for (int cop = 0; cop < 8; cop++) {
        float lo, hi; upk2(acc[cop], lo, hi);
        g_h[(((size_t)b*64 + co0 + 2*cop    )*HH + oy)*HH + ox] = fmaxf(lo, 0.f);
        g_h[(((size_t)b*64 + co0 + 2*cop + 1)*HH + oy)*HH + ox] = fmaxf(hi, 0.f);
    }
}

// ------- fused 1x1 conv -> online softmax -> stats -> (last block) ktw --------
__global__ void logits_stats(const float* __restrict__ w2, const float* __restrict__ b2,
                             const float* __restrict__ sx, const float* __restrict__ sy,
                             const float* __restrict__ op, const float* __restrict__ rh) {
    __shared__ float buf[49*196];
    __shared__ float sv[4*NGRP];
    __shared__ float b2s[NGRP];
    __shared__ float accs[196];
    __shared__ float wops[49];
    __shared__ int lastb;
    int tid = threadIdx.x;
    float* ws = buf;
    for (int i = tid; i < NGRP; i += 256) {
        sv[i] = sx[i]; sv[NGRP+i] = sy[i]; sv[2*NGRP+i] = op[i]; sv[3*NGRP+i] = rh[i];
        b2s[i] = b2[i];
    }
    for (int i = tid; i < NGRP*64; i += 256) ws[i] = w2[i];
    for (int i = tid; i < 196; i += 256) accs[i] = 0.f;
    __syncthreads();

    int t = blockIdx.x * 256 + tid;
    int b = t / (HH*HH); int pix = t % (HH*HH);
    int y = pix / HH, x = pix % HH;
    const float* hp = g_h + (size_t)b*64*HH*HH + pix;
    float hv[64];
    #pragma unroll
    for (int ci = 0; ci < 64; ci++) hv[ci] = hp[(size_t)ci*HH*HH];

    float m = -1e30f, s = 0.f, a0 = 0.f, a1 = 0.f, a2 = 0.f, a3 = 0.f;
    for (int g = 0; g < NGRP; g++) {
        float l = b2s[g];
        const float* wg = ws + g*64;
        #pragma unroll
        for (int ci = 0; ci < 64; ci += 4) {
            float4 wv = *(const float4*)(wg + ci);
            l += hv[ci]*wv.x + hv[ci+1]*wv.y + hv[ci+2]*wv.z + hv[ci+3]*wv.w;
        }
        float mn = fmaxf(m, l);
        float sc = __expf(m - mn);
        float e  = __expf(l - mn);
        s  = s*sc + e;
        a0 = a0*sc + e*sv[g];
        a1 = a1*sc + e*sv[NGRP+g];
        a2 = a2*sc + e*sv[2*NGRP+g];
        a3 = a3*sc + e*sv[3*NGRP+g];
        m = mn;
    }
    float inv = 1.f / s;
    int p = (y % 7)*7 + (x % 7);
    atomicAdd(&accs[p*4+0], a0*inv);
    atomicAdd(&accs[p*4+1], a1*inv);
    atomicAdd(&accs[p*4+2], a2*inv);
    atomicAdd(&accs[p*4+3], a3*inv);
    __syncthreads();
    for (int i = tid; i < 196; i += 256) atomicAdd(&g_wstat[i], accs[i]);

    __threadfence();
    if (tid == 0) lastb = (atomicAdd(&g_ctr, 1) == (int)gridDim.x - 1);
    __syncthreads();
    if (!lastb) return;
    if (tid == 0) g_ctr = 0;

    float* kpad = buf;
    for (int i = tid; i < 49*196; i += 256) kpad[i] = 0.f;
    __syncthreads();
    if (tid < 49) {
        int p2 = tid;
        const float inv1024 = 1.f/1024.f;
        float wsx = g_wstat[p2*4+0]*inv1024;
        float wsy = g_wstat[p2*4+1]*inv1024;
        float wop = g_wstat[p2*4+2]*inv1024;
        float wr  = g_wstat[p2*4+3]*inv1024;
        wops[p2] = wop;
        float c00 = wsx*wsx + 1e-5f;
        float c11 = wsy*wsy + 1e-5f;
        float c01 = wr*wsx*wsy;
        float det = c00*c11 - c01*c01;
        float i00 = c11/det, i11 = c00/det, i01 = -c01/det;
        float norm = 1.f/(2.f*3.14159265358979f*sqrtf(det));
        float kv[25]; float kmx = 0.f;
        #pragma unroll
        for (int i = 0; i < 5; i++)
            #pragma unroll
            for (int j = 0; j < 5; j++) {
                float yv = -5.f + 2.5f*i;
                float xv = -5.f + 2.5f*j;
                float z = -0.5f*(i00*xv*xv + 2.f*i01*xv*yv + i11*yv*yv);
                float k = expf(z)*norm;
                kv[i*5+j] = k; kmx = fmaxf(kmx, k);
            }
        float im = 1.f/kmx;
        #pragma unroll
        for (int i = 0; i < 5; i++)
            #pragma unroll
            for (int j = 0; j < 5; j++)
                kpad[p2*196 + (i+4)*14 + (j+4)] = kv[i*5+j]*im;
    }
    __syncthreads();
    for (int idx = tid; idx < 49*196; idx += 256) {
        int p2 = idx/196, hw = idx%196, h = hw/14, w = hw%14;
        float txo = (0.5f - (float)(p2/7)*(1.f/7.f))*2.f;
        float tyo = (0.5f - (float)(p2%7)*(1.f/7.f))*2.f;
        float gxv = -1.f + (2.f/13.f)*w + txo;
        float gyv = -1.f + (2.f/13.f)*h + tyo;
        float px = (gxv + 1.f)*0.5f*13.f;
        float py = (gyv + 1.f)*0.5f*13.f;
        float x0f = floorf(px), y0f = floorf(py);
        int x0 = (int)x0f, y0 = (int)y0f;
        float wx = px - x0f, wy = py - y0f;
        float s00 = (y0   >= 0 && y0   < 14 && x0   >= 0 && x0   < 14) ? kpad[p2*196 + y0*14 + x0]       : 0.f;
        float s01 = (y0   >= 0 && y0   < 14 && x0+1 >= 0 && x0+1 < 14) ? kpad[p2*196 + y0*14 + x0+1]     : 0.f;
        float s10 = (y0+1 >= 0 && y0+1 < 14 && x0   >= 0 && x0   < 14) ? kpad[p2*196 + (y0+1)*14 + x0]   : 0.f;
        float s11 = (y0+1 >= 0 && y0+1 < 14 && x0+1 >= 0 && x0+1 < 14) ? kpad[p2*196 + (y0+1)*14 + x0+1] : 0.f;
        float kt = s00*(1.f-wy)*(1.f-wx) + s01*(1.f-wy)*wx + s10*wy*(1.f-wx) + s11*wy*wx;
        g_ktw[idx] = kt * wops[p2];
    }
}

// ------- splat -> NHWC fp16  (+ side job: pack conv224 weights fp16) ----------
#define SPLAT_SMEM ((49*196 + 49*64)*4)
__global__ void splat(const float* __restrict__ feat,
                      const float* __restrict__ wc, const float* __restrict__ wf) {
    extern __shared__ float sm[];
    float* kts = sm;             // [p][196]
    float* fp  = sm + 49*196;    // [p][64]
    int bl = blockIdx.x;
    int b = bl / 256; int l = bl % 256; int pr = l / 16, pc = l % 16;
    int tid = threadIdx.x;       // 196

    // side job: pack conv224 weights (294912 elements over 200704 threads)
    for (int i = bl*196 + tid; i < 294912; i += 1024*196) {
        int ci = i & 63; int t = i >> 6;
        int co = t & 127; t >>= 7;
        int dydx = t % 9; t /= 9;
        int half = t & 1; int sel = t >> 1;
        const float* W = sel ? wf : wc;
        float v = W[(size_t)(half*128 + co)*576 + ci*9 + dydx];
        size_t base = ((size_t)((sel*2 + half)*9 + dydx))*16384;
        uint32_t off = (uint32_t)co*128 + (((uint32_t)(ci>>3)*16) ^ (((uint32_t)co&7)<<4)) + (ci&7)*2;
        *(__half*)(g_cw + base + off) = __float2half(v);
    }

    for (int i = tid; i < 49*196; i += 196) kts[i] = g_ktw[i];
    const float* fb = feat + (size_t)b*64*HH*HH;
    for (int i = tid; i < 49*64; i += 196) {
        int p = i >> 6, c = i & 63;
        fp[i] = fb[((size_t)c*HH + pr*7 + p/7)*HH + pc*7 + p%7];
    }
    __syncthreads();
    int h = tid/14, w = tid%14;
    int oy = pr*14 + h, ox = pc*14 + w;
    size_t pixb = ((size_t)b*H2 + oy)*H2 + ox;
    __half* gh = g_gfh + pixb*64;
    #pragma unroll
    for (int half = 0; half < 2; half++) {
        float a[32];
        #pragma unroll
        for (int j = 0; j < 32; j++) a[j] = 0.f;
        for (int p = 0; p < 49; p++) {
            float k = kts[p*196 + tid];
            const float4* f4 = (const float4*)(fp + p*64 + half*32);
            #pragma unroll
            for (int j = 0; j < 8; j++) {
                float4 v = f4[j];
                a[j*4+0] += k*v.x; a[j*4+1] += k*v.y;
                a[j*4+2] += k*v.z; a[j*4+3] += k*v.w;
            }
        }
        #pragma unroll
        for (int j = 0; j < 32; j += 4) {
            int c0 = half*32 + j;
            *(__half2*)(gh + c0)     = __floats2half2_rn(__saturatef(a[j]),   __saturatef(a[j+1]));
            *(__half2*)(gh + c0 + 2) = __floats2half2_rn(__saturatef(a[j+2]), __saturatef(a[j+3]));
        }
    }
}

// ---------------- conv3x3 64->256 @224 via mma.sync (1-pass fp16) -------------
#define CM_WBASE 41472
#define CM_WBUF  16384
#define CM_SMEM  (41472 + 2*16384)   // 74240

__global__ void __launch_bounds__(512, 1) conv224m(const float* __restrict__ bias_c,
                                                   const float* __restrict__ bias_f) {
    extern __shared__ __align__(16) char smc[];
    __shared__ float sbias[128];
    uint32_t sb;
    asm("{ .reg .u64 t; cvta.to.shared.u64 t, %1; cvt.u32.u64 %0, t; }" : "=r"(sb) : "l"(smc));
    int tid = threadIdx.x, wid = tid >> 5, lane = tid & 31;
    int grp = lane >> 2, t4 = lane & 3;
    int bt = blockIdx.x, cohalf = blockIdx.y;
    int sel = blockIdx.z & 1, b = blockIdx.z >> 1;
    int row0 = (bt/14)*16, col0 = (bt%14)*16;
    int wm = wid >> 1, wn = wid & 1;
    int nb = wn*64;

    const __half* gh = g_gfh + (size_t)b*H2*H2*64;
    const unsigned char* wsrc = g_cw + (size_t)(sel*2 + cohalf)*9*16384;
    const float* bias = sel ? bias_f : bias_c;

    for (int i = tid; i < 1024; i += 512)
        cpa16(smc + CM_WBASE + i*16, wsrc + i*16);
    for (int i = tid; i < 2592; i += 512) {
        int pos = i >> 3, j = i & 7;
        int r = pos / 18, c = pos - r*18;
        int gy = row0 + r - 1, gx = col0 + c - 1;
        int ok = (gy >= 0 && gy < H2 && gx >= 0 && gx < H2);
        const __half* src = gh + ((size_t)(ok ? gy : 0)*H2 + (ok ? gx : 0))*64 + j*8;
        cpa16z(smc + (r*18 + c)*128 + (((uint32_t)j*16) ^ (((uint32_t)c&7)<<4)), src, ok ? 16 : 0);
    }
    asm volatile("cp.async.commit_group;" ::: "memory");
    if (tid < 128) sbias[tid] = bias[cohalf*128 + tid];

    float acc[2][8][4];
    #pragma unroll
    for (int t = 0; t < 2; t++)
        #pragma unroll
        for (int u = 0; u < 8; u++)
            #pragma unroll
            for (int j = 0; j < 4; j++) acc[t][u][j] = 0.f;

    uint32_t swzb = (uint32_t)(grp << 4);
    uint32_t t4x4 = (uint32_t)(t4*4);

    for (int dydx = 0; dydx < 9; dydx++) {
        if (dydx < 8) {
            const unsigned char* src = wsrc + (size_t)(dydx+1)*16384;
            char* dst = smc + CM_WBASE + ((dydx+1)&1)*CM_WBUF;
            for (int i = tid; i < 1024; i += 512)
                cpa16(dst + i*16, src + i*16);
            asm volatile("cp.async.commit_group;" ::: "memory");
            asm volatile("cp.async.wait_group 1;" ::: "memory");
        } else {
            asm volatile("cp.async.wait_group 0;" ::: "memory");
        }
        __syncthreads();

        int dy = dydx/3, dx = dydx - dy*3;
        uint32_t wb = sb + CM_WBASE + (uint32_t)((dydx&1)*CM_WBUF);
        uint32_t swza = (uint32_t)(((grp + dx) & 7) << 4);
        uint32_t aRow0 = sb + (uint32_t)(((wm*2 + dy)*18 + grp + dx)*128);
        uint32_t aRow1 = aRow0 + 18*128;

        #pragma unroll
        for (int ks = 0; ks < 4; ks++) {
            uint32_t kA0 = (((uint32_t)(ks*32)) ^ swza) + t4x4;
            uint32_t kA1 = (((uint32_t)(ks*32 + 16)) ^ swza) + t4x4;
            uint32_t ah[2][4];
            ah[0][0] = lds32(aRow0 + kA0);        ah[0][1] = lds32(aRow0 + 1024 + kA0);
            ah[0][2] = lds32(aRow0 + kA1);        ah[0][3] = lds32(aRow0 + 1024 + kA1);
            ah[1][0] = lds32(aRow1 + kA0);        ah[1][1] = lds32(aRow1 + 1024 + kA0);
            ah[1][2] = lds32(aRow1 + kA1);        ah[1][3] = lds32(aRow1 + 1024 + kA1);
            uint32_t kB0 = (((uint32_t)(ks*32)) ^ swzb) + t4x4;
            uint32_t kB1 = (((uint32_t)(ks*32 + 16)) ^ swzb) + t4x4;
            #pragma unroll
            for (int u = 0; u < 8; u++) {
                uint32_t rb = wb + (uint32_t)((nb + u*8 + grp)*128);
                uint32_t bh0 = lds32(rb + kB0), bh1 = lds32(rb + kB1);
                mma16816(acc[0][u], ah[0][0], ah[0][1], ah[0][2], ah[0][3], bh0, bh1);
                mma16816(acc[1][u], ah[1][0], ah[1][1], ah[1][2], ah[1][3], bh0, bh1);
            }
        }
        __syncthreads();
    }

    float* outp = sel ? g_freq : g_coef;
    #pragma unroll
    for (int t = 0; t < 2; t++) {
        int gy = row0 + wm*2 + t;
        #pragma unroll
        for (int u = 0; u < 8; u++) {
            int cidx = nb + u*8 + t4*2;
            float b0 = sbias[cidx], b1 = sbias[cidx+1];
            size_t o0 = (((size_t)b*H2 + gy)*H2 + col0 + grp)*256 + cohalf*128 + cidx;
            size_t o1 = o0 + (size_t)8*256;
            *(float2*)&outp[o0] = make_float2(acc[t][u][0] + b0, acc[t][u][1] + b1);
            *(float2*)&outp[o1] = make_float2(acc[t][u][2] + b0, acc[t][u][3] + b1);
        }
    }
}

// ---------------- pack MLP weights (fp16, row-major) --------------------------
__global__ void pack_mlp(const float* __restrict__ w1, const float* __restrict__ w2) {
    int i = blockIdx.x*256 + threadIdx.x;
    int l = i >> 16; int e = i & 65535;
    const float* W = l ? w2 : w1;
    g_Wh[l][e] = __float2half(W[e]);
}

// ---------------- gather + fourier basis -> X0 fp16 (+ zero out) --------------
__global__ void gather_basis(const float* __restrict__ coord,
                             const float* __restrict__ cell,
                             const float* __restrict__ phase_w,
                             float* __restrict__ outz) {
    int gid = blockIdx.x*256 + threadIdx.x;
    if (gid < MTOT*3) outz[gid] = 0.f;
    int warp = threadIdx.x / 32, lane = threadIdx.x % 32;
    int m = blockIdx.x * 8 + warp;
    int b = m / QQ; int q = m % QQ;
    float cy = coord[((size_t)b*QQ + q)*2 + 0];
    float cx = coord[((size_t)b*QQ + q)*2 + 1];
    int ix = (int)rintf(((cx + 1.f)*(float)H2 - 1.f)*0.5f);
    int iy = (int)rintf(((cy + 1.f)*(float)H2 - 1.f)*0.5f);
    bool ok = (ix >= 0 && ix < H2 && iy >= 0 && iy < H2);
    __half* xh = g_X0h + (size_t)m*HID;
    if (!ok) {
        __half z = __float2half(0.f);
        #pragma unroll
        for (int kk = 0; kk < 4; kk++) {
            int k = lane + kk*32;
            xh[k] = z; xh[128+k] = z;
        }
        return;
    }
    float fcy = -1.f + 1.f/(float)H2 + (2.f/(float)H2)*(float)iy;
    float fcx = -1.f + 1.f/(float)H2 + (2.f/(float)H2)*(float)ix;
    float rely = (cy - fcy)*(float)H2;
    float relx = (cx - fcx)*(float)H2;
    float rc0 = cell[((size_t)b*QQ + q)*2 + 0]*(float)H2;
    float rc1 = cell[((size_t)b*QQ + q)*2 + 1]*(float)H2;
    size_t base = (((size_t)b*H2 + iy)*H2 + ix)*HID;
    const float*  cf = g_coef + base;
    const float2* fq = (const float2*)(g_freq + base);
    const float2* pw = (const float2*)phase_w;
    const float PI = 3.14159265358979f;
    #pragma unroll
    for (int kk = 0; kk < 4; kk++) {
        int k = lane + kk*32;
        float2 f = fq[k];
        float2 p = pw[k];
        float s = (f.x*rely + f.y*relx + rc0*p.x + rc1*p.y) * PI;
        xh[k]     = __float2half(cf[k]       * __cosf(s));
        xh[128+k] = __float2half(cf[128 + k] * __sinf(s));
    }
}

// ---------------- mma.sync fp16 GEMM (1-pass) + bias + relu -------------------
// layer 0: X0 -> X1 (fp16). layer 1: X1 -> fused final 256->3 via atomics.
#define GM_BB 0
#define GM_AB 65536
#define GM_SMEM (65536 + 2*16384)   // 98304

__global__ void __launch_bounds__(256, 1) gemm_mma(const float* __restrict__ bias, int layer,
                                                   const float* __restrict__ w3,
                                                   const float* __restrict__ b3,
                                                   float* __restrict__ out) {
    extern __shared__ __align__(16) char smc[];
    __shared__ float sbias[128];
    __shared__ float w3s[3*128];
    uint32_t sb;
    asm("{ .reg .u64 t; cvta.to.shared.u64 t, %1; cvt.u32.u64 %0, t; }" : "=r"(sb) : "l"(smc));
    int tid = threadIdx.x, wid = tid >> 5, lane = tid & 31;
    int grp = lane >> 2, t4 = lane & 3;
    int m0 = blockIdx.x * 128;
    int n0 = blockIdx.y * 128;
    int wm = wid >> 1, wn = wid & 1;
    int mb = wm * 32, nb = wn * 64;

    const __half* Ah = layer ? g_X1h : g_X0h;
    const __half* Wh = g_Wh[layer];

    for (int i = tid; i < 4096; i += 256) {
        int n = i >> 5; int j = i & 31;
        const __half* src = Wh + (size_t)(n0 + n)*256 + j*8;
        cpa16(smc + GM_BB + n*512 + ((j*16) ^ ((n&7)<<4)), src);
    }
    for (int i = tid; i < 1024; i += 256) {
        int m = i >> 3; int j = i & 7;
        const __half* src = Ah + (size_t)(m0 + m)*256 + j*8;
        cpa16(smc + GM_AB + m*128 + ((j*16) ^ ((m&7)<<4)), src);
    }
    asm volatile("cp.async.commit_group;" ::: "memory");
    if (tid < 128) {
        sbias[tid] = bias[n0 + tid];
        if (layer) {
            w3s[tid]       = w3[0*256 + n0 + tid];
            w3s[128 + tid] = w3[1*256 + n0 + tid];
            w3s[256 + tid] = w3[2*256 + n0 + tid];
        }
    }

    float acc[2][8][4];
    #pragma unroll
    for (int t = 0; t < 2; t++)
        #pragma unroll
        for (int u = 0; u < 8; u++)
            #pragma unroll
            for (int j = 0; j < 4; j++) acc[t][u][j] = 0.f;

    uint32_t swz = (uint32_t)(grp << 4);
    uint32_t t4x4 = (uint32_t)(t4 * 4);
    uint32_t bB = sb + GM_BB;

    for (int c = 0; c < 4; c++) {
        if (c < 3) {
            int cn = c + 1;
            char* dstb = smc + GM_AB + (cn & 1)*16384;
            for (int i = tid; i < 1024; i += 256) {
                int m = i >> 3; int j = i & 7;
                const __half* src = Ah + (size_t)(m0 + m)*256 + cn*64 + j*8;
                cpa16(dstb + m*128 + ((j*16) ^ ((m&7)<<4)), src);
            }
            asm volatile("cp.async.commit_group;" ::: "memory");
            asm volatile("cp.async.wait_group 1;" ::: "memory");
        } else {
            asm volatile("cp.async.wait_group 0;" ::: "memory");
        }
        __syncthreads();

        uint32_t bA = sb + GM_AB + (c & 1)*16384;
        #pragma unroll
        for (int ks = 0; ks < 4; ks++) {
            uint32_t ko  = (((uint32_t)(ks*32)) ^ swz) + t4x4;
            uint32_t koh = (((uint32_t)(ks*32+16)) ^ swz) + t4x4;
            uint32_t ahf[2][4], bhf[8][2];
            #pragma unroll
            for (int t = 0; t < 2; t++) {
                uint32_t ra = bA + (uint32_t)((mb + t*16 + grp)*128);
                ahf[t][0] = lds32(ra + ko);
                ahf[t][1] = lds32(ra + 1024 + ko);
                ahf[t][2] = lds32(ra + koh);
                ahf[t][3] = lds32(ra + 1024 + koh);
            }
            uint32_t kob  = (((uint32_t)(c*128 + ks*32)) ^ swz) + t4x4;
            uint32_t kobh = (((uint32_t)(c*128 + ks*32+16)) ^ swz) + t4x4;
            #pragma unroll
            for (int u = 0; u < 8; u++) {
                uint32_t rb = bB + (uint32_t)((nb + u*8 + grp)*512);
                bhf[u][0] = lds32(rb + kob);
                bhf[u][1] = lds32(rb + kobh);
            }
            #pragma unroll
            for (int t = 0; t < 2; t++)
                #pragma unroll
                for (int u = 0; u < 8; u++)
                    mma16816(acc[t][u], ahf[t][0], ahf[t][1], ahf[t][2], ahf[t][3], bhf[u][0], bhf[u][1]);
        }
        __syncthreads();
    }

    if (layer == 0) {
        #pragma unroll
        for (int t = 0; t < 2; t++) {
            int r0 = m0 + mb + t*16 + grp;
            int r1 = r0 + 8;
            #pragma unroll
            for (int u = 0; u < 8; u++) {
                int cb = nb + u*8 + t4*2;
                float b0v = sbias[cb], b1v = sbias[cb+1];
                float v00 = fmaxf(acc[t][u][0] + b0v, 0.f);
                float v01 = fmaxf(acc[t][u][1] + b1v, 0.f);
                float v10 = fmaxf(acc[t][u][2] + b0v, 0.f);
                float v11 = fmaxf(acc[t][u][3] + b1v, 0.f);
                int gcol = n0 + cb;
                *(__half2*)&g_X1h[(size_t)r0*256 + gcol] = __floats2half2_rn(v00, v01);
                *(__half2*)&g_X1h[(size_t)r1*256 + gcol] = __floats2half2_rn(v10, v11);
            }
        }
    } else {
        #pragma unroll
        for (int t = 0; t < 2; t++) {
            int r0 = m0 + mb + t*16 + grp;
            int r1 = r0 + 8;
            float p0[3] = {0.f, 0.f, 0.f};
            float p1[3] = {0.f, 0.f, 0.f};
            #pragma unroll
            for (int u = 0; u < 8; u++) {
                int cb = nb + u*8 + t4*2;
                float b0v = sbias[cb], b1v = sbias[cb+1];
                float v00 = fmaxf(acc[t][u][0] + b0v, 0.f);
                float v01 = fmaxf(acc[t][u][1] + b1v, 0.f);
                float v10 = fmaxf(acc[t][u][2] + b0v, 0.f);
                float v11 = fmaxf(acc[t][u][3] + b1v, 0.f);
                #pragma unroll
                for (int cc = 0; cc < 3; cc++) {
                    float w0 = w3s[cc*128 + cb], w1 = w3s[cc*128 + cb + 1];
                    p0[cc] += v00*w0 + v01*w1;
                    p1[cc] += v10*w0 + v11*w1;
                }
            }
            #pragma unroll
            for (int cc = 0; cc < 3; cc++) {
                p0[cc] += __shfl_xor_sync(0xffffffffu, p0[cc], 1);
                p0[cc] += __shfl_xor_sync(0xffffffffu, p0[cc], 2);
                p1[cc] += __shfl_xor_sync(0xffffffffu, p1[cc], 1);
                p1[cc] += __shfl_xor_sync(0xffffffffu, p1[cc], 2);
            }
            if (t4 == 0) {
                #pragma unroll
                for (int cc = 0; cc < 3; cc++) {
                    float bb = (n0 == 0) ? b3[cc] : 0.f;
                    atomicAdd(&out[(size_t)r0*3 + cc], p0[cc] + bb);
                    atomicAdd(&out[(size_t)r1*3 + cc], p1[cc] + bb);
                }
            }
        }
    }
}

// ---------------- launch -------------------------------------------------------
extern "C" void kernel_launch(void* const* d_in, const int* in_sizes, int n_in,
                              void* d_out, int out_size) {
    const float* feat    = (const float*)d_in[0];
    const float* coord   = (const float*)d_in[1];
    const float* cell    = (const float*)d_in[2];
    const float* cls_w1  = (const float*)d_in[3];
    const float* cls_b1  = (const float*)d_in[4];
    const float* cls_w2  = (const float*)d_in[5];
    const float* cls_b2  = (const float*)d_in[6];
    const float* sigma_x = (const float*)d_in[7];
    const float* sigma_y = (const float*)d_in[8];
    const float* opacity = (const float*)d_in[9];
    const float* rho     = (const float*)d_in[10];
    const float* coef_w  = (const float*)d_in[11];
    const float* coef_b  = (const float*)d_in[12];
    const float* freq_w  = (const float*)d_in[13];
    const float* freq_b  = (const float*)d_in[14];
    const float* phase_w = (const float*)d_in[15];
    const float* mlp_w1  = (const float*)d_in[16];
    const float* mlp_b1  = (const float*)d_in[17];
    const float* mlp_w2  = (const float*)d_in[18];
    const float* mlp_b2  = (const float*)d_in[19];
    const float* mlp_w3  = (const float*)d_in[20];
    const float* mlp_b3  = (const float*)d_in[21];
    float* out = (float*)d_out;

    cudaFuncSetAttribute(conv112p, cudaFuncAttributeMaxDynamicSharedMemorySize, CONVP_SMEM);
    cudaFuncSetAttribute(splat,    cudaFuncAttributeMaxDynamicSharedMemorySize, SPLAT_SMEM);
    cudaFuncSetAttribute(conv224m, cudaFuncAttributeMaxDynamicSharedMemorySize, CM_SMEM);
    cudaFuncSetAttribute(gemm_mma, cudaFuncAttributeMaxDynamicSharedMemorySize, GM_SMEM);

    conv112p<<<dim3(49, 4, BB), 256, CONVP_SMEM>>>(feat, cls_w1, cls_b1);          // #1
    logits_stats<<<196, 256>>>(cls_w2, cls_b2, sigma_x, sigma_y, opacity, rho);    // #2
    splat<<<1024, 196, SPLAT_SMEM>>>(feat, coef_w, freq_w);                        // #3
    conv224m<<<dim3(196, 2, BB*2), 512, CM_SMEM>>>(coef_b, freq_b);                // #4 (profiled)
    pack_mlp<<<512, 256>>>(mlp_w1, mlp_w2);                                        // #5
    gather_basis<<<MTOT/8, 256>>>(coord, cell, phase_w, out);                      // #6
    gemm_mma<<<dim3(MTOT/128, 2), 256, GM_SMEM>>>(mlp_b1, 0, mlp_w3, mlp_b3, out); // #7
    gemm_mma<<<dim3(MTOT/128, 2), 256, GM_SMEM>>>(mlp_b2, 1, mlp_w3, mlp_b3, out); // #8
}

// round 12
// speedup vs baseline: 10.4730x; 1.0227x over previous
#include <cuda_runtime.h>
#include <cuda_fp16.h>
#include <math.h>
#include <stdint.h>

#define CIN 64
#define NGRP 100
#define HID 256
#define BB 4
#define HH 112
#define H2 224
#define QQ 50176
#define MTOT (BB*QQ)   // 200704

typedef unsigned long long ull;

__device__ __forceinline__ ull pk2(float a, float b) {
    ull r; asm("mov.b64 %0,{%1,%2};" : "=l"(r) : "f"(a), "f"(b)); return r;
}
__device__ __forceinline__ void fma2(ull& d, ull a, ull b) {
    asm("fma.rn.f32x2 %0,%1,%2,%0;" : "+l"(d) : "l"(a), "l"(b));
}
__device__ __forceinline__ void upk2(ull v, float& a, float& b) {
    asm("mov.b64 {%0,%1},%2;" : "=f"(a), "=f"(b) : "l"(v));
}
__device__ __forceinline__ void cpa16(void* dst, const void* src) {
    unsigned d = (unsigned)__cvta_generic_to_shared(dst);
    asm volatile("cp.async.cg.shared.global [%0], [%1], 16;" :: "r"(d), "l"(src));
}
__device__ __forceinline__ void cpa16z(void* dst, const void* src, int sz) {
    unsigned d = (unsigned)__cvta_generic_to_shared(dst);
    asm volatile("cp.async.cg.shared.global [%0], [%1], 16, %2;" :: "r"(d), "l"(src), "r"(sz));
}
__device__ __forceinline__ void ldsm4(uint32_t& r0, uint32_t& r1, uint32_t& r2, uint32_t& r3, uint32_t a) {
    asm volatile("ldmatrix.sync.aligned.m8n8.x4.shared.b16 {%0,%1,%2,%3}, [%4];"
        : "=r"(r0), "=r"(r1), "=r"(r2), "=r"(r3) : "r"(a));
}
__device__ __forceinline__ void mma16816(float* c, uint32_t a0, uint32_t a1, uint32_t a2, uint32_t a3,
                                         uint32_t b0, uint32_t b1) {
    asm volatile("mma.sync.aligned.m16n8k16.row.col.f32.f16.f16.f32 "
        "{%0,%1,%2,%3},{%4,%5,%6,%7},{%8,%9},{%0,%1,%2,%3};"
        : "+f"(c[0]), "+f"(c[1]), "+f"(c[2]), "+f"(c[3])
        : "r"(a0), "r"(a1), "r"(a2), "r"(a3), "r"(b0), "r"(b1));
}

// ---------------- scratch -----------------------------------------------------
__device__ float g_h[(size_t)BB*CIN*HH*HH];
__device__ float g_wstat[49*4];
__device__ int   g_ctr;
__device__ float g_ktw[49*196];
__device__ __align__(16) __half g_gfh[(size_t)BB*H2*H2*64];  // NHWC fp16
__device__ float g_coef[(size_t)BB*H2*H2*HID];
__device__ float g_freq[(size_t)BB*H2*H2*HID];
__device__ __align__(16) __half g_X0h[(size_t)MTOT*HID];
__device__ __align__(16) __half g_X1h[(size_t)MTOT*HID];
__device__ __align__(16) unsigned char g_cw[(size_t)2*2*9*16384];   // conv224 fp16 swizzled
__device__ __align__(16) __half g_Wh[2][65536];

// ---------------- conv3x3 64->64 @112, relu, NCHW out (packed f32x2) ----------
#define CONVP_SMEM (64*18*18*4 + 64*8*10*8)

__global__ void conv112p(const float* __restrict__ in,
                         const float* __restrict__ w,
                         const float* __restrict__ bias) {
    extern __shared__ float sm[];
    float* ins = sm;
    ull*   wsp = (ull*)(sm + 64*324);
    int tile = blockIdx.x;
    int co0  = blockIdx.y * 16;
    int b    = blockIdx.z;
    int ty0 = (tile / 7) * 16, tx0 = (tile % 7) * 16;
    int tid = threadIdx.x;
    if (tile == 0 && blockIdx.y == 0 && b == 0 && tid < 196) g_wstat[tid] = 0.f;

    const float* inb = in + (size_t)b * CIN * HH * HH;
    for (int i = tid; i < 64*18*18; i += 256) {
        int ci = i / 324; int r = (i % 324) / 18; int c = i % 18;
        int gy = ty0 + r - 1, gx = tx0 + c - 1;
        float v = 0.f;
        if (gy >= 0 && gy < HH && gx >= 0 && gx < HH) v = inb[(ci*HH + gy)*HH + gx];
        ins[i] = v;
    }
    float* wspf = (float*)wsp;
    for (int i = tid; i < 64*8*9*2; i += 256) {
        int half = i & 1; int e = i >> 1;
        int k = e % 9; int cop = (e/9) & 7; int ci = e/72;
        wspf[((ci*8 + cop)*10 + k)*2 + half] = w[(size_t)(co0 + cop*2 + half)*576 + ci*9 + k];
    }
    __syncthreads();

    int ty = tid / 16, tx = tid % 16;
    ull acc[8];
    #pragma unroll
    for (int cop = 0; cop < 8; cop++) acc[cop] = pk2(bias[co0+2*cop], bias[co0+2*cop+1]);

    for (int ci = 0; ci < 64; ci++) {
        const float* ip = ins + ci*324 + ty*18 + tx;
        ull vv[9];
        #pragma unroll
        for (int dy = 0; dy < 3; dy++)
            #pragma unroll
            for (int dx = 0; dx < 3; dx++) {
                float v = ip[dy*18 + dx];
                vv[dy*3+dx] = pk2(v, v);
            }
        const ull* wbase = wsp + ci*80;
        #pragma unroll
        for (int cop = 0; cop < 8; cop++) {
            const ulonglong2* wc2 = (const ulonglong2*)(wbase + cop*10);
            ulonglong2 p0 = wc2[0], p1 = wc2[1], p2 = wc2[2], p3 = wc2[3];
            ull p8 = (wbase + cop*10)[8];
            fma2(acc[cop], vv[0], p0.x); fma2(acc[cop], vv[1], p0.y);
            fma2(acc[cop], vv[2], p1.x); fma2(acc[cop], vv[3], p1.y);
            fma2(acc[cop], vv[4], p2.x); fma2(acc[cop], vv[5], p2.y);
            fma2(acc[cop], vv[6], p3.x); fma2(acc[cop], vv[7], p3.y);
            fma2(acc[cop], vv[8], p8);
        }
    }
    int oy = ty0 + ty, ox = tx0 + tx;
    #pragma unroll
    for (int cop = 0; cop < 8; cop++) {
        float lo, hi; upk2(acc[cop], lo, hi);
        g_h[(((size_t)b*64 + co0 + 2*cop    )*HH + oy)*HH + ox] = fmaxf(lo, 0.f);
        g_h[(((size_t)b*64 + co0 + 2*cop + 1)*HH + oy)*HH + ox] = fmaxf(hi, 0.f);
    }
}

// ------- fused 1x1 conv -> online softmax -> stats -> (last block) ktw --------
__global__ void logits_stats(const float* __restrict__ w2, const float* __restrict__ b2,
                             const float* __restrict__ sx, const float* __restrict__ sy,
                             const float* __restrict__ op, const float* __restrict__ rh) {
    __shared__ float buf[49*196];
    __shared__ float sv[4*NGRP];
    __shared__ float b2s[NGRP];
    __shared__ float accs[196];
    __shared__ float wops[49];
    __shared__ int lastb;
    int tid = threadIdx.x;
    float* ws = buf;
    for (int i = tid; i < NGRP; i += 256) {
        sv[i] = sx[i]; sv[NGRP+i] = sy[i]; sv[2*NGRP+i] = op[i]; sv[3*NGRP+i] = rh[i];
        b2s[i] = b2[i];
    }
    for (int i = tid; i < NGRP*64; i += 256) ws[i] = w2[i];
    for (int i = tid; i < 196; i += 256) accs[i] = 0.f;
    __syncthreads();

    int t = blockIdx.x * 256 + tid;
    int b = t / (HH*HH); int pix = t % (HH*HH);
    int y = pix / HH, x = pix % HH;
    const float* hp = g_h + (size_t)b*64*HH*HH + pix;
    float hv[64];
    #pragma unroll
    for (int ci = 0; ci < 64; ci++) hv[ci] = hp[(size_t)ci*HH*HH];

    float m = -1e30f, s = 0.f, a0 = 0.f, a1 = 0.f, a2 = 0.f, a3 = 0.f;
    for (int g = 0; g < NGRP; g++) {
        float l = b2s[g];
        const float* wg = ws + g*64;
        #pragma unroll
        for (int ci = 0; ci < 64; ci += 4) {
            float4 wv = *(const float4*)(wg + ci);
            l += hv[ci]*wv.x + hv[ci+1]*wv.y + hv[ci+2]*wv.z + hv[ci+3]*wv.w;
        }
        float mn = fmaxf(m, l);
        float sc = __expf(m - mn);
        float e  = __expf(l - mn);
        s  = s*sc + e;
        a0 = a0*sc + e*sv[g];
        a1 = a1*sc + e*sv[NGRP+g];
        a2 = a2*sc + e*sv[2*NGRP+g];
        a3 = a3*sc + e*sv[3*NGRP+g];
        m = mn;
    }
    float inv = 1.f / s;
    int p = (y % 7)*7 + (x % 7);
    atomicAdd(&accs[p*4+0], a0*inv);
    atomicAdd(&accs[p*4+1], a1*inv);
    atomicAdd(&accs[p*4+2], a2*inv);
    atomicAdd(&accs[p*4+3], a3*inv);
    __syncthreads();
    for (int i = tid; i < 196; i += 256) atomicAdd(&g_wstat[i], accs[i]);

    __threadfence();
    if (tid == 0) lastb = (atomicAdd(&g_ctr, 1) == (int)gridDim.x - 1);
    __syncthreads();
    if (!lastb) return;
    if (tid == 0) g_ctr = 0;

    float* kpad = buf;
    for (int i = tid; i < 49*196; i += 256) kpad[i] = 0.f;
    __syncthreads();
    if (tid < 49) {
        int p2 = tid;
        const float inv1024 = 1.f/1024.f;
        float wsx = g_wstat[p2*4+0]*inv1024;
        float wsy = g_wstat[p2*4+1]*inv1024;
        float wop = g_wstat[p2*4+2]*inv1024;
        float wr  = g_wstat[p2*4+3]*inv1024;
        wops[p2] = wop;
        float c00 = wsx*wsx + 1e-5f;
        float c11 = wsy*wsy + 1e-5f;
        float c01 = wr*wsx*wsy;
        float det = c00*c11 - c01*c01;
        float i00 = c11/det, i11 = c00/det, i01 = -c01/det;
        float norm = 1.f/(2.f*3.14159265358979f*sqrtf(det));
        float kv[25]; float kmx = 0.f;
        #pragma unroll
        for (int i = 0; i < 5; i++)
            #pragma unroll
            for (int j = 0; j < 5; j++) {
                float yv = -5.f + 2.5f*i;
                float xv = -5.f + 2.5f*j;
                float z = -0.5f*(i00*xv*xv + 2.f*i01*xv*yv + i11*yv*yv);
                float k = expf(z)*norm;
                kv[i*5+j] = k; kmx = fmaxf(kmx, k);
            }
        float im = 1.f/kmx;
        #pragma unroll
        for (int i = 0; i < 5; i++)
            #pragma unroll
            for (int j = 0; j < 5; j++)
                kpad[p2*196 + (i+4)*14 + (j+4)] = kv[i*5+j]*im;
    }
    __syncthreads();
    for (int idx = tid; idx < 49*196; idx += 256) {
        int p2 = idx/196, hw = idx%196, h = hw/14, w = hw%14;
        float txo = (0.5f - (float)(p2/7)*(1.f/7.f))*2.f;
        float tyo = (0.5f - (float)(p2%7)*(1.f/7.f))*2.f;
        float gxv = -1.f + (2.f/13.f)*w + txo;
        float gyv = -1.f + (2.f/13.f)*h + tyo;
        float px = (gxv + 1.f)*0.5f*13.f;
        float py = (gyv + 1.f)*0.5f*13.f;
        float x0f = floorf(px), y0f = floorf(py);
        int x0 = (int)x0f, y0 = (int)y0f;
        float wx = px - x0f, wy = py - y0f;
        float s00 = (y0   >= 0 && y0   < 14 && x0   >= 0 && x0   < 14) ? kpad[p2*196 + y0*14 + x0]       : 0.f;
        float s01 = (y0   >= 0 && y0   < 14 && x0+1 >= 0 && x0+1 < 14) ? kpad[p2*196 + y0*14 + x0+1]     : 0.f;
        float s10 = (y0+1 >= 0 && y0+1 < 14 && x0   >= 0 && x0   < 14) ? kpad[p2*196 + (y0+1)*14 + x0]   : 0.f;
        float s11 = (y0+1 >= 0 && y0+1 < 14 && x0+1 >= 0 && x0+1 < 14) ? kpad[p2*196 + (y0+1)*14 + x0+1] : 0.f;
        float kt = s00*(1.f-wy)*(1.f-wx) + s01*(1.f-wy)*wx + s10*wy*(1.f-wx) + s11*wy*wx;
        g_ktw[idx] = kt * wops[p2];
    }
}

// ------- splat -> NHWC fp16  (+ side job: pack conv224 weights fp16) ----------
#define SPLAT_SMEM ((49*196 + 49*64)*4)
__global__ void splat(const float* __restrict__ feat,
                      const float* __restrict__ wc, const float* __restrict__ wf) {
    extern __shared__ float sm[];
    float* kts = sm;             // [p][196]
    float* fp  = sm + 49*196;    // [p][64]
    int bl = blockIdx.x;
    int b = bl / 256; int l = bl % 256; int pr = l / 16, pc = l % 16;
    int tid = threadIdx.x;       // 196

    for (int i = bl*196 + tid; i < 294912; i += 1024*196) {
        int ci = i & 63; int t = i >> 6;
        int co = t & 127; t >>= 7;
        int dydx = t % 9; t /= 9;
        int half = t & 1; int sel = t >> 1;
        const float* W = sel ? wf : wc;
        float v = W[(size_t)(half*128 + co)*576 + ci*9 + dydx];
        size_t base = ((size_t)((sel*2 + half)*9 + dydx))*16384;
        uint32_t off = (uint32_t)co*128 + (((uint32_t)(ci>>3)*16) ^ (((uint32_t)co&7)<<4)) + (ci&7)*2;
        *(__half*)(g_cw + base + off) = __float2half(v);
    }

    for (int i = tid; i < 49*196; i += 196) kts[i] = g_ktw[i];
    const float* fb = feat + (size_t)b*64*HH*HH;
    for (int i = tid; i < 49*64; i += 196) {
        int p = i >> 6, c = i & 63;
        fp[i] = fb[((size_t)c*HH + pr*7 + p/7)*HH + pc*7 + p%7];
    }
    __syncthreads();
    int h = tid/14, w = tid%14;
    int oy = pr*14 + h, ox = pc*14 + w;
    size_t pixb = ((size_t)b*H2 + oy)*H2 + ox;
    __half* gh = g_gfh + pixb*64;
    #pragma unroll
    for (int half = 0; half < 2; half++) {
        float a[32];
        #pragma unroll
        for (int j = 0; j < 32; j++) a[j] = 0.f;
        for (int p = 0; p < 49; p++) {
            float k = kts[p*196 + tid];
            const float4* f4 = (const float4*)(fp + p*64 + half*32);
            #pragma unroll
            for (int j = 0; j < 8; j++) {
                float4 v = f4[j];
                a[j*4+0] += k*v.x; a[j*4+1] += k*v.y;
                a[j*4+2] += k*v.z; a[j*4+3] += k*v.w;
            }
        }
        #pragma unroll
        for (int j = 0; j < 32; j += 4) {
            int c0 = half*32 + j;
            *(__half2*)(gh + c0)     = __floats2half2_rn(__saturatef(a[j]),   __saturatef(a[j+1]));
            *(__half2*)(gh + c0 + 2) = __floats2half2_rn(__saturatef(a[j+2]), __saturatef(a[j+3]));
        }
    }
}

// ---------------- conv3x3 64->256 @224 via mma.sync (1-pass fp16 + ldmatrix) --
#define CM_WBASE 41472
#define CM_WBUF  16384
#define CM_SMEM  (41472 + 2*16384)   // 74240

__global__ void __launch_bounds__(512, 1) conv224m(const float* __restrict__ bias_c,
                                                   const float* __restrict__ bias_f) {
    extern __shared__ __align__(16) char smc[];
    __shared__ float sbias[128];
    uint32_t sb;
    asm("{ .reg .u64 t; cvta.to.shared.u64 t, %1; cvt.u32.u64 %0, t; }" : "=r"(sb) : "l"(smc));
    int tid = threadIdx.x, wid = tid >> 5, lane = tid & 31;
    int grp = lane >> 2, t4 = lane & 3;
    int bt = blockIdx.x, cohalf = blockIdx.y;
    int sel = blockIdx.z & 1, b = blockIdx.z >> 1;
    int row0 = (bt/14)*16, col0 = (bt%14)*16;
    int wm = wid >> 1, wn = wid & 1;
    int nb = wn*64;
    (void)grp; (void)t4;

    // ldmatrix lane decomposition
    int lr8  = lane & 7;
    int a_mh = (lane >> 3) & 1;   // A: m-half
    int a_jh = (lane >> 4) & 1;   // A: k-half
    int b_jh = (lane >> 3) & 1;   // B: k-half
    int b_nh = (lane >> 4) & 1;   // B: n-half

    const __half* gh = g_gfh + (size_t)b*H2*H2*64;
    const unsigned char* wsrc = g_cw + (size_t)(sel*2 + cohalf)*9*16384;
    const float* bias = sel ? bias_f : bias_c;

    for (int i = tid; i < 1024; i += 512)
        cpa16(smc + CM_WBASE + i*16, wsrc + i*16);
    for (int i = tid; i < 2592; i += 512) {
        int pos = i >> 3, j = i & 7;
        int r = pos / 18, c = pos - r*18;
        int gy = row0 + r - 1, gx = col0 + c - 1;
        int ok = (gy >= 0 && gy < H2 && gx >= 0 && gx < H2);
        const __half* src = gh + ((size_t)(ok ? gy : 0)*H2 + (ok ? gx : 0))*64 + j*8;
        cpa16z(smc + (r*18 + c)*128 + (((uint32_t)j*16) ^ (((uint32_t)c&7)<<4)), src, ok ? 16 : 0);
    }
    asm volatile("cp.async.commit_group;" ::: "memory");
    if (tid < 128) sbias[tid] = bias[cohalf*128 + tid];

    float acc[2][8][4];
    #pragma unroll
    for (int t = 0; t < 2; t++)
        #pragma unroll
        for (int u = 0; u < 8; u++)
            #pragma unroll
            for (int j = 0; j < 4; j++) acc[t][u][j] = 0.f;

    // B per-lane base (row within 128-co block, invariant)
    uint32_t bRowOff = (uint32_t)((nb + b_nh*8 + lr8)*128);
    uint32_t swB = (uint32_t)(lr8 << 4);

    for (int dydx = 0; dydx < 9; dydx++) {
        if (dydx < 8) {
            const unsigned char* src = wsrc + (size_t)(dydx+1)*16384;
            char* dst = smc + CM_WBASE + ((dydx+1)&1)*CM_WBUF;
            for (int i = tid; i < 1024; i += 512)
                cpa16(dst + i*16, src + i*16);
            asm volatile("cp.async.commit_group;" ::: "memory");
            asm volatile("cp.async.wait_group 1;" ::: "memory");
        } else {
            asm volatile("cp.async.wait_group 0;" ::: "memory");
        }
        __syncthreads();

        int dy = dydx/3, dx = dydx - dy*3;
        uint32_t wb = sb + CM_WBASE + (uint32_t)((dydx&1)*CM_WBUF) + bRowOff;

        int cA = dx + lr8 + a_mh*8;
        uint32_t swA = (uint32_t)(((dx + lr8) & 7) << 4);
        uint32_t aBase0 = sb + (uint32_t)((((wm*2 + dy)*18 + cA))*128);
        uint32_t aBase1 = aBase0 + 18*128;

        #pragma unroll
        for (int ks = 0; ks < 4; ks++) {
            uint32_t ka = (uint32_t)(((ks*2 + a_jh)*16)) ^ swA;
            uint32_t a0[4], a1[4];
            ldsm4(a0[0], a0[1], a0[2], a0[3], aBase0 + ka);
            ldsm4(a1[0], a1[1], a1[2], a1[3], aBase1 + ka);
            uint32_t kb = (uint32_t)(((ks*2 + b_jh)*16)) ^ swB;
            #pragma unroll
            for (int up = 0; up < 4; up++) {
                uint32_t br[4];
                ldsm4(br[0], br[1], br[2], br[3], wb + (uint32_t)(up*2048) + kb);
                mma16816(acc[0][2*up],   a0[0], a0[1], a0[2], a0[3], br[0], br[1]);
                mma16816(acc[0][2*up+1], a0[0], a0[1], a0[2], a0[3], br[2], br[3]);
                mma16816(acc[1][2*up],   a1[0], a1[1], a1[2], a1[3], br[0], br[1]);
                mma16816(acc[1][2*up+1], a1[0], a1[1], a1[2], a1[3], br[2], br[3]);
            }
        }
        __syncthreads();
    }

    int egrp = lane >> 2, et4 = lane & 3;
    float* outp = sel ? g_freq : g_coef;
    #pragma unroll
    for (int t = 0; t < 2; t++) {
        int gy = row0 + wm*2 + t;
        #pragma unroll
        for (int u = 0; u < 8; u++) {
            int cidx = nb + u*8 + et4*2;
            float b0 = sbias[cidx], b1 = sbias[cidx+1];
            size_t o0 = (((size_t)b*H2 + gy)*H2 + col0 + egrp)*256 + cohalf*128 + cidx;
            size_t o1 = o0 + (size_t)8*256;
            *(float2*)&outp[o0] = make_float2(acc[t][u][0] + b0, acc[t][u][1] + b1);
            *(float2*)&outp[o1] = make_float2(acc[t][u][2] + b0, acc[t][u][3] + b1);
        }
    }
}

// ---------------- pack MLP weights (fp16, row-major) --------------------------
__global__ void pack_mlp(const float* __restrict__ w1, const float* __restrict__ w2) {
    int i = blockIdx.x*256 + threadIdx.x;
    int l = i >> 16; int e = i & 65535;
    const float* W = l ? w2 : w1;
    g_Wh[l][e] = __float2half(W[e]);
}

// ---------------- gather + fourier basis -> X0 fp16 (+ zero out) --------------
__global__ void gather_basis(const float* __restrict__ coord,
                             const float* __restrict__ cell,
                             const float* __restrict__ phase_w,
                             float* __restrict__ outz) {
    int gid = blockIdx.x*256 + threadIdx.x;
    if (gid < MTOT*3) outz[gid] = 0.f;
    int warp = threadIdx.x / 32, lane = threadIdx.x % 32;
    int m = blockIdx.x * 8 + warp;
    int b = m / QQ; int q = m % QQ;
    float cy = coord[((size_t)b*QQ + q)*2 + 0];
    float cx = coord[((size_t)b*QQ + q)*2 + 1];
    int ix = (int)rintf(((cx + 1.f)*(float)H2 - 1.f)*0.5f);
    int iy = (int)rintf(((cy + 1.f)*(float)H2 - 1.f)*0.5f);
    bool ok = (ix >= 0 && ix < H2 && iy >= 0 && iy < H2);
    __half* xh = g_X0h + (size_t)m*HID;
    if (!ok) {
        __half z = __float2half(0.f);
        #pragma unroll
        for (int kk = 0; kk < 4; kk++) {
            int k = lane + kk*32;
            xh[k] = z; xh[128+k] = z;
        }
        return;
    }
    float fcy = -1.f + 1.f/(float)H2 + (2.f/(float)H2)*(float)iy;
    float fcx = -1.f + 1.f/(float)H2 + (2.f/(float)H2)*(float)ix;
    float rely = (cy - fcy)*(float)H2;
    float relx = (cx - fcx)*(float)H2;
    float rc0 = cell[((size_t)b*QQ + q)*2 + 0]*(float)H2;
    float rc1 = cell[((size_t)b*QQ + q)*2 + 1]*(float)H2;
    size_t base = (((size_t)b*H2 + iy)*H2 + ix)*HID;
    const float*  cf = g_coef + base;
    const float2* fq = (const float2*)(g_freq + base);
    const float2* pw = (const float2*)phase_w;
    const float PI = 3.14159265358979f;
    #pragma unroll
    for (int kk = 0; kk < 4; kk++) {
        int k = lane + kk*32;
        float2 f = fq[k];
        float2 p = pw[k];
        float s = (f.x*rely + f.y*relx + rc0*p.x + rc1*p.y) * PI;
        xh[k]     = __float2half(cf[k]       * __cosf(s));
        xh[128+k] = __float2half(cf[128 + k] * __sinf(s));
    }
}

// ---------------- mma.sync fp16 GEMM (1-pass + ldmatrix) ----------------------
// layer 0: X0 -> X1 (fp16). layer 1: X1 -> fused final 256->3 via atomics.
#define GM_BB 0
#define GM_AB 65536
#define GM_SMEM (65536 + 2*16384)   // 98304

__global__ void __launch_bounds__(256, 1) gemm_mma(const float* __restrict__ bias, int layer,
                                                   const float* __restrict__ w3,
                                                   const float* __restrict__ b3,
                                                   float* __restrict__ out) {
    extern __shared__ __align__(16) char smc[];
    __shared__ float sbias[128];
    __shared__ float w3s[3*128];
    uint32_t sb;
    asm("{ .reg .u64 t; cvta.to.shared.u64 t, %1; cvt.u32.u64 %0, t; }" : "=r"(sb) : "l"(smc));
    int tid = threadIdx.x, wid = tid >> 5, lane = tid & 31;
    int m0 = blockIdx.x * 128;
    int n0 = blockIdx.y * 128;
    int wm = wid >> 1, wn = wid & 1;
    int mb = wm * 32, nb = wn * 64;

    int lr8  = lane & 7;
    int a_mh = (lane >> 3) & 1;
    int a_jh = (lane >> 4) & 1;
    int b_jh = (lane >> 3) & 1;
    int b_nh = (lane >> 4) & 1;

    const __half* Ah = layer ? g_X1h : g_X0h;
    const __half* Wh = g_Wh[layer];

    for (int i = tid; i < 4096; i += 256) {
        int n = i >> 5; int j = i & 31;
        const __half* src = Wh + (size_t)(n0 + n)*256 + j*8;
        cpa16(smc + GM_BB + n*512 + ((j*16) ^ ((n&7)<<4)), src);
    }
    for (int i = tid; i < 1024; i += 256) {
        int m = i >> 3; int j = i & 7;
        const __half* src = Ah + (size_t)(m0 + m)*256 + j*8;
        cpa16(smc + GM_AB + m*128 + ((j*16) ^ ((m&7)<<4)), src);
    }
    asm volatile("cp.async.commit_group;" ::: "memory");
    if (tid < 128) {
        sbias[tid] = bias[n0 + tid];
        if (layer) {
            w3s[tid]       = w3[0*256 + n0 + tid];
            w3s[128 + tid] = w3[1*256 + n0 + tid];
            w3s[256 + tid] = w3[2*256 + n0 + tid];
        }
    }

    float acc[2][8][4];
    #pragma unroll
    for (int t = 0; t < 2; t++)
        #pragma unroll
        for (int u = 0; u < 8; u++)
            #pragma unroll
            for (int j = 0; j < 4; j++) acc[t][u][j] = 0.f;

    // per-lane ldmatrix bases
    uint32_t aRowOff = (uint32_t)((a_mh*8 + lr8)*128);
    uint32_t swA = (uint32_t)(lr8 << 4);
    uint32_t bRowOff = (uint32_t)((nb + b_nh*8 + lr8)*512);
    uint32_t swB = swA;
    uint32_t bB = sb + GM_BB + bRowOff;

    for (int c = 0; c < 4; c++) {
        if (c < 3) {
            int cn = c + 1;
            char* dstb = smc + GM_AB + (cn & 1)*16384;
            for (int i = tid; i < 1024; i += 256) {
                int m = i >> 3; int j = i & 7;
                const __half* src = Ah + (size_t)(m0 + m)*256 + cn*64 + j*8;
                cpa16(dstb + m*128 + ((j*16) ^ ((m&7)<<4)), src);
            }
            asm volatile("cp.async.commit_group;" ::: "memory");
            asm volatile("cp.async.wait_group 1;" ::: "memory");
        } else {
            asm volatile("cp.async.wait_group 0;" ::: "memory");
        }
        __syncthreads();

        uint32_t bA = sb + GM_AB + (c & 1)*16384 + aRowOff;
        #pragma unroll
        for (int ks = 0; ks < 4; ks++) {
            uint32_t ka = (uint32_t)(((ks*2 + a_jh)*16)) ^ swA;
            uint32_t a0[4], a1[4];
            ldsm4(a0[0], a0[1], a0[2], a0[3], bA + (uint32_t)(mb*128) + ka);
            ldsm4(a1[0], a1[1], a1[2], a1[3], bA + (uint32_t)((mb+16)*128) + ka);
            uint32_t kb = (uint32_t)(((c*8 + ks*2 + b_jh)*16)) ^ swB;
            #pragma unroll
            for (int up = 0; up < 4; up++) {
                uint32_t br[4];
                ldsm4(br[0], br[1], br[2], br[3], bB + (uint32_t)(up*8192) + kb);
                mma16816(acc[0][2*up],   a0[0], a0[1], a0[2], a0[3], br[0], br[1]);
                mma16816(acc[0][2*up+1], a0[0], a0[1], a0[2], a0[3], br[2], br[3]);
                mma16816(acc[1][2*up],   a1[0], a1[1], a1[2], a1[3], br[0], br[1]);
                mma16816(acc[1][2*up+1], a1[0], a1[1], a1[2], a1[3], br[2], br[3]);
            }
        }
        __syncthreads();
    }

    int grp = lane >> 2, t4 = lane & 3;
    if (layer == 0) {
        #pragma unroll
        for (int t = 0; t < 2; t++) {
            int r0 = m0 + mb + t*16 + grp;
            int r1 = r0 + 8;
            #pragma unroll
            for (int u = 0; u < 8; u++) {
                int cb = nb + u*8 + t4*2;
                float b0v = sbias[cb], b1v = sbias[cb+1];
                float v00 = fmaxf(acc[t][u][0] + b0v, 0.f);
                float v01 = fmaxf(acc[t][u][1] + b1v, 0.f);
                float v10 = fmaxf(acc[t][u][2] + b0v, 0.f);
                float v11 = fmaxf(acc[t][u][3] + b1v, 0.f);
                int gcol = n0 + cb;
                *(__half2*)&g_X1h[(size_t)r0*256 + gcol] = __floats2half2_rn(v00, v01);
                *(__half2*)&g_X1h[(size_t)r1*256 + gcol] = __floats2half2_rn(v10, v11);
            }
        }
    } else {
        #pragma unroll
        for (int t = 0; t < 2; t++) {
            int r0 = m0 + mb + t*16 + grp;
            int r1 = r0 + 8;
            float p0[3] = {0.f, 0.f, 0.f};
            float p1[3] = {0.f, 0.f, 0.f};
            #pragma unroll
            for (int u = 0; u < 8; u++) {
                int cb = nb + u*8 + t4*2;
                float b0v = sbias[cb], b1v = sbias[cb+1];
                float v00 = fmaxf(acc[t][u][0] + b0v, 0.f);
                float v01 = fmaxf(acc[t][u][1] + b1v, 0.f);
                float v10 = fmaxf(acc[t][u][2] + b0v, 0.f);
                float v11 = fmaxf(acc[t][u][3] + b1v, 0.f);
                #pragma unroll
                for (int cc = 0; cc < 3; cc++) {
                    float w0 = w3s[cc*128 + cb], w1 = w3s[cc*128 + cb + 1];
                    p0[cc] += v00*w0 + v01*w1;
                    p1[cc] += v10*w0 + v11*w1;
                }
            }
            #pragma unroll
            for (int cc = 0; cc < 3; cc++) {
                p0[cc] += __shfl_xor_sync(0xffffffffu, p0[cc], 1);
                p0[cc] += __shfl_xor_sync(0xffffffffu, p0[cc], 2);
                p1[cc] += __shfl_xor_sync(0xffffffffu, p1[cc], 1);
                p1[cc] += __shfl_xor_sync(0xffffffffu, p1[cc], 2);
            }
            if (t4 == 0) {
                #pragma unroll
                for (int cc = 0; cc < 3; cc++) {
                    float bb = (n0 == 0) ? b3[cc] : 0.f;
                    atomicAdd(&out[(size_t)r0*3 + cc], p0[cc] + bb);
                    atomicAdd(&out[(size_t)r1*3 + cc], p1[cc] + bb);
                }
            }
        }
    }
}

// ---------------- launch -------------------------------------------------------
extern "C" void kernel_launch(void* const* d_in, const int* in_sizes, int n_in,
                              void* d_out, int out_size) {
    const float* feat    = (const float*)d_in[0];
    const float* coord   = (const float*)d_in[1];
    const float* cell    = (const float*)d_in[2];
    const float* cls_w1  = (const float*)d_in[3];
    const float* cls_b1  = (const float*)d_in[4];
    const float* cls_w2  = (const float*)d_in[5];
    const float* cls_b2  = (const float*)d_in[6];
    const float* sigma_x = (const float*)d_in[7];
    const float* sigma_y = (const float*)d_in[8];
    const float* opacity = (const float*)d_in[9];
    const float* rho     = (const float*)d_in[10];
    const float* coef_w  = (const float*)d_in[11];
    const float* coef_b  = (const float*)d_in[12];
    const float* freq_w  = (const float*)d_in[13];
    const float* freq_b  = (const float*)d_in[14];
    const float* phase_w = (const float*)d_in[15];
    const float* mlp_w1  = (const float*)d_in[16];
    const float* mlp_b1  = (const float*)d_in[17];
    const float* mlp_w2  = (const float*)d_in[18];
    const float* mlp_b2  = (const float*)d_in[19];
    const float* mlp_w3  = (const float*)d_in[20];
    const float* mlp_b3  = (const float*)d_in[21];
    float* out = (float*)d_out;

    cudaFuncSetAttribute(conv112p, cudaFuncAttributeMaxDynamicSharedMemorySize, CONVP_SMEM);
    cudaFuncSetAttribute(splat,    cudaFuncAttributeMaxDynamicSharedMemorySize, SPLAT_SMEM);
    cudaFuncSetAttribute(conv224m, cudaFuncAttributeMaxDynamicSharedMemorySize, CM_SMEM);
    cudaFuncSetAttribute(gemm_mma, cudaFuncAttributeMaxDynamicSharedMemorySize, GM_SMEM);

    conv112p<<<dim3(49, 4, BB), 256, CONVP_SMEM>>>(feat, cls_w1, cls_b1);          // #1
    logits_stats<<<196, 256>>>(cls_w2, cls_b2, sigma_x, sigma_y, opacity, rho);    // #2
    splat<<<1024, 196, SPLAT_SMEM>>>(feat, coef_w, freq_w);                        // #3
    conv224m<<<dim3(196, 2, BB*2), 512, CM_SMEM>>>(coef_b, freq_b);                // #4 (profiled)
    pack_mlp<<<512, 256>>>(mlp_w1, mlp_w2);                                        // #5
    gather_basis<<<MTOT/8, 256>>>(coord, cell, phase_w, out);                      // #6
    gemm_mma<<<dim3(MTOT/128, 2), 256, GM_SMEM>>>(mlp_b1, 0, mlp_w3, mlp_b3, out); // #7
    gemm_mma<<<dim3(MTOT/128, 2), 256, GM_SMEM>>>(mlp_b2, 1, mlp_w3, mlp_b3, out); // #8
}

// round 13
// speedup vs baseline: 12.6839x; 1.2111x over previous
#include <cuda_runtime.h>
#include <cuda_fp16.h>
#include <math.h>
#include <stdint.h>

#define CIN 64
#define NGRP 100
#define HID 256
#define BB 4
#define HH 112
#define H2 224
#define QQ 50176
#define MTOT (BB*QQ)   // 200704

typedef unsigned long long ull;

__device__ __forceinline__ void cpa16(void* dst, const void* src) {
    unsigned d = (unsigned)__cvta_generic_to_shared(dst);
    asm volatile("cp.async.cg.shared.global [%0], [%1], 16;" :: "r"(d), "l"(src));
}
__device__ __forceinline__ void cpa16z(void* dst, const void* src, int sz) {
    unsigned d = (unsigned)__cvta_generic_to_shared(dst);
    asm volatile("cp.async.cg.shared.global [%0], [%1], 16, %2;" :: "r"(d), "l"(src), "r"(sz));
}
__device__ __forceinline__ void ldsm4(uint32_t& r0, uint32_t& r1, uint32_t& r2, uint32_t& r3, uint32_t a) {
    asm volatile("ldmatrix.sync.aligned.m8n8.x4.shared.b16 {%0,%1,%2,%3}, [%4];"
        : "=r"(r0), "=r"(r1), "=r"(r2), "=r"(r3) : "r"(a));
}
__device__ __forceinline__ void mma16816(float* c, uint32_t a0, uint32_t a1, uint32_t a2, uint32_t a3,
                                         uint32_t b0, uint32_t b1) {
    asm volatile("mma.sync.aligned.m16n8k16.row.col.f32.f16.f16.f32 "
        "{%0,%1,%2,%3},{%4,%5,%6,%7},{%8,%9},{%0,%1,%2,%3};"
        : "+f"(c[0]), "+f"(c[1]), "+f"(c[2]), "+f"(c[3])
        : "r"(a0), "r"(a1), "r"(a2), "r"(a3), "r"(b0), "r"(b1));
}

// ---------------- scratch -----------------------------------------------------
__device__ __align__(16) __half g_f16[(size_t)BB*HH*HH*64];   // feat NHWC fp16
__device__ __align__(16) __half g_h16[(size_t)BB*HH*HH*64];   // conv112 out NHWC fp16
__device__ float g_wstat[49*4];
__device__ int   g_ctr;
__device__ float g_ktw[49*196];
__device__ __align__(16) __half g_gfh[(size_t)BB*H2*H2*64];   // gfeat NHWC fp16
__device__ __align__(16) __half g_coefh[(size_t)BB*H2*H2*HID]; // coef fp16
__device__ float g_freq[(size_t)BB*H2*H2*HID];                 // freq fp32
__device__ __align__(16) __half g_X0h[(size_t)MTOT*HID];
__device__ __align__(16) __half g_X1h[(size_t)MTOT*HID];
__device__ __align__(16) unsigned char g_cw[(size_t)2*2*9*16384];  // conv224 weights
__device__ __align__(16) unsigned char g_cw1[(size_t)9*8192];      // conv112 weights
__device__ __align__(16) __half g_Wh[2][65536];

// ------- prep: feat NCHW->NHWC fp16, pack conv112 + MLP weights, zero stats ---
__global__ void feat_prep(const float* __restrict__ feat,
                          const float* __restrict__ cls_w1,
                          const float* __restrict__ w1, const float* __restrict__ w2) {
    int gid = blockIdx.x*256 + threadIdx.x;
    if (blockIdx.x == 0 && threadIdx.x < 196) g_wstat[threadIdx.x] = 0.f;
    // feat transpose: gid -> (b, y, x, c) output-major
    if (gid < BB*HH*HH*64) {
        int c = gid & 63; int e = gid >> 6;
        int x = e % HH; e /= HH; int y = e % HH; int b = e / HH;
        g_f16[gid] = __float2half(feat[(((size_t)b*64 + c)*HH + y)*HH + x]);
    }
    // conv112 weights: 9 taps x [co64][ci64] swizzled
    if (gid < 36864) {
        int ci = gid & 63; int t = gid >> 6;
        int co = t & 63; int tap = t >> 6;
        float v = cls_w1[(size_t)co*576 + ci*9 + tap];
        uint32_t off = (uint32_t)co*128 + (((uint32_t)(ci>>3)*16) ^ (((uint32_t)co&7)<<4)) + (ci&7)*2;
        *(__half*)(g_cw1 + (size_t)tap*8192 + off) = __float2half(v);
    }
    // MLP weights
    if (gid < 131072) {
        int l = gid >> 16; int e = gid & 65535;
        const float* W = l ? w2 : w1;
        g_Wh[l][e] = __float2half(W[e]);
    }
}

// ---------------- conv3x3 64->64 @112 via mma.sync (fp16) ---------------------
#define C1_WBASE 41472
#define C1_WBUF  8192
#define C1_SMEM  (41472 + 2*8192)   // 57856

__global__ void __launch_bounds__(512, 1) conv112t(const float* __restrict__ bias) {
    extern __shared__ __align__(16) char smc[];
    __shared__ float sbias[64];
    uint32_t sb;
    asm("{ .reg .u64 t; cvta.to.shared.u64 t, %1; cvt.u32.u64 %0, t; }" : "=r"(sb) : "l"(smc));
    int tid = threadIdx.x, wid = tid >> 5, lane = tid & 31;
    int bt = blockIdx.x, b = blockIdx.z;
    int row0 = (bt/7)*16, col0 = (bt%7)*16;
    int wm = wid >> 1, wn = wid & 1;
    int nb = wn*32;

    int lr8  = lane & 7;
    int a_mh = (lane >> 3) & 1;
    int a_jh = (lane >> 4) & 1;
    int b_jh = (lane >> 3) & 1;
    int b_nh = (lane >> 4) & 1;

    const __half* gh = g_f16 + (size_t)b*HH*HH*64;

    for (int i = tid; i < 512; i += 512)
        cpa16(smc + C1_WBASE + i*16, g_cw1 + i*16);
    for (int i = tid; i < 2592; i += 512) {
        int pos = i >> 3, j = i & 7;
        int r = pos / 18, c = pos - r*18;
        int gy = row0 + r - 1, gx = col0 + c - 1;
        int ok = (gy >= 0 && gy < HH && gx >= 0 && gx < HH);
        const __half* src = gh + ((size_t)(ok ? gy : 0)*HH + (ok ? gx : 0))*64 + j*8;
        cpa16z(smc + (r*18 + c)*128 + (((uint32_t)j*16) ^ (((uint32_t)c&7)<<4)), src, ok ? 16 : 0);
    }
    asm volatile("cp.async.commit_group;" ::: "memory");
    if (tid < 64) sbias[tid] = bias[tid];

    float acc[2][4][4];
    #pragma unroll
    for (int t = 0; t < 2; t++)
        #pragma unroll
        for (int u = 0; u < 4; u++)
            #pragma unroll
            for (int j = 0; j < 4; j++) acc[t][u][j] = 0.f;

    uint32_t bRowOff = (uint32_t)((nb + b_nh*8 + lr8)*128);
    uint32_t swB = (uint32_t)(lr8 << 4);

    for (int dydx = 0; dydx < 9; dydx++) {
        if (dydx < 8) {
            const unsigned char* src = g_cw1 + (size_t)(dydx+1)*8192;
            char* dst = smc + C1_WBASE + ((dydx+1)&1)*C1_WBUF;
            for (int i = tid; i < 512; i += 512)
                cpa16(dst + i*16, src + i*16);
            asm volatile("cp.async.commit_group;" ::: "memory");
            asm volatile("cp.async.wait_group 1;" ::: "memory");
        } else {
            asm volatile("cp.async.wait_group 0;" ::: "memory");
        }
        __syncthreads();

        int dy = dydx/3, dx = dydx - dy*3;
        uint32_t wb = sb + C1_WBASE + (uint32_t)((dydx&1)*C1_WBUF) + bRowOff;

        int cA = dx + lr8 + a_mh*8;
        uint32_t swA = (uint32_t)(((dx + lr8) & 7) << 4);
        uint32_t aBase0 = sb + (uint32_t)((((wm*2 + dy)*18 + cA))*128);
        uint32_t aBase1 = aBase0 + 18*128;

        #pragma unroll
        for (int ks = 0; ks < 4; ks++) {
            uint32_t ka = (uint32_t)(((ks*2 + a_jh)*16)) ^ swA;
            uint32_t a0[4], a1[4];
            ldsm4(a0[0], a0[1], a0[2], a0[3], aBase0 + ka);
            ldsm4(a1[0], a1[1], a1[2], a1[3], aBase1 + ka);
            uint32_t kb = (uint32_t)(((ks*2 + b_jh)*16)) ^ swB;
            #pragma unroll
            for (int up = 0; up < 2; up++) {
                uint32_t br[4];
                ldsm4(br[0], br[1], br[2], br[3], wb + (uint32_t)(up*2048) + kb);
                mma16816(acc[0][2*up],   a0[0], a0[1], a0[2], a0[3], br[0], br[1]);
                mma16816(acc[0][2*up+1], a0[0], a0[1], a0[2], a0[3], br[2], br[3]);
                mma16816(acc[1][2*up],   a1[0], a1[1], a1[2], a1[3], br[0], br[1]);
                mma16816(acc[1][2*up+1], a1[0], a1[1], a1[2], a1[3], br[2], br[3]);
            }
        }
        __syncthreads();
    }

    int egrp = lane >> 2, et4 = lane & 3;
    __half* outp = g_h16 + (size_t)b*HH*HH*64;
    #pragma unroll
    for (int t = 0; t < 2; t++) {
        int gy = row0 + wm*2 + t;
        #pragma unroll
        for (int u = 0; u < 4; u++) {
            int cidx = nb + u*8 + et4*2;
            float b0 = sbias[cidx], b1 = sbias[cidx+1];
            size_t o0 = ((size_t)gy*HH + col0 + egrp)*64 + cidx;
            size_t o1 = o0 + (size_t)8*64;
            *(__half2*)&outp[o0] = __floats2half2_rn(fmaxf(acc[t][u][0] + b0, 0.f),
                                                     fmaxf(acc[t][u][1] + b1, 0.f));
            *(__half2*)&outp[o1] = __floats2half2_rn(fmaxf(acc[t][u][2] + b0, 0.f),
                                                     fmaxf(acc[t][u][3] + b1, 0.f));
        }
    }
}

// ------- fused 1x1 conv -> online softmax -> stats -> (last block) ktw --------
__global__ void logits_stats(const float* __restrict__ w2, const float* __restrict__ b2,
                             const float* __restrict__ sx, const float* __restrict__ sy,
                             const float* __restrict__ op, const float* __restrict__ rh) {
    __shared__ float buf[49*196];
    __shared__ float sv[4*NGRP];
    __shared__ float b2s[NGRP];
    __shared__ float accs[196];
    __shared__ float wops[49];
    __shared__ int lastb;
    int tid = threadIdx.x;
    float* ws = buf;
    for (int i = tid; i < NGRP; i += 256) {
        sv[i] = sx[i]; sv[NGRP+i] = sy[i]; sv[2*NGRP+i] = op[i]; sv[3*NGRP+i] = rh[i];
        b2s[i] = b2[i];
    }
    for (int i = tid; i < NGRP*64; i += 256) ws[i] = w2[i];
    for (int i = tid; i < 196; i += 256) accs[i] = 0.f;
    __syncthreads();

    int t = blockIdx.x * 256 + tid;
    int b = t / (HH*HH); int pix = t % (HH*HH);
    int y = pix / HH, x = pix % HH;
    const __half2* hp = (const __half2*)(g_h16 + ((size_t)b*HH*HH + pix)*64);
    float hv[64];
    #pragma unroll
    for (int ci = 0; ci < 32; ci++) {
        float2 v = __half22float2(hp[ci]);
        hv[2*ci] = v.x; hv[2*ci+1] = v.y;
    }

    float m = -1e30f, s = 0.f, a0 = 0.f, a1 = 0.f, a2 = 0.f, a3 = 0.f;
    for (int g = 0; g < NGRP; g++) {
        float l = b2s[g];
        const float* wg = ws + g*64;
        #pragma unroll
        for (int ci = 0; ci < 64; ci += 4) {
            float4 wv = *(const float4*)(wg + ci);
            l += hv[ci]*wv.x + hv[ci+1]*wv.y + hv[ci+2]*wv.z + hv[ci+3]*wv.w;
        }
        float mn = fmaxf(m, l);
        float sc = __expf(m - mn);
        float e  = __expf(l - mn);
        s  = s*sc + e;
        a0 = a0*sc + e*sv[g];
        a1 = a1*sc + e*sv[NGRP+g];
        a2 = a2*sc + e*sv[2*NGRP+g];
        a3 = a3*sc + e*sv[3*NGRP+g];
        m = mn;
    }
    float inv = 1.f / s;
    int p = (y % 7)*7 + (x % 7);
    atomicAdd(&accs[p*4+0], a0*inv);
    atomicAdd(&accs[p*4+1], a1*inv);
    atomicAdd(&accs[p*4+2], a2*inv);
    atomicAdd(&accs[p*4+3], a3*inv);
    __syncthreads();
    for (int i = tid; i < 196; i += 256) atomicAdd(&g_wstat[i], accs[i]);

    __threadfence();
    if (tid == 0) lastb = (atomicAdd(&g_ctr, 1) == (int)gridDim.x - 1);
    __syncthreads();
    if (!lastb) return;
    if (tid == 0) g_ctr = 0;

    float* kpad = buf;
    for (int i = tid; i < 49*196; i += 256) kpad[i] = 0.f;
    __syncthreads();
    if (tid < 49) {
        int p2 = tid;
        const float inv1024 = 1.f/1024.f;
        float wsx = g_wstat[p2*4+0]*inv1024;
        float wsy = g_wstat[p2*4+1]*inv1024;
        float wop = g_wstat[p2*4+2]*inv1024;
        float wr  = g_wstat[p2*4+3]*inv1024;
        wops[p2] = wop;
        float c00 = wsx*wsx + 1e-5f;
        float c11 = wsy*wsy + 1e-5f;
        float c01 = wr*wsx*wsy;
        float det = c00*c11 - c01*c01;
        float i00 = c11/det, i11 = c00/det, i01 = -c01/det;
        float norm = 1.f/(2.f*3.14159265358979f*sqrtf(det));
        float kv[25]; float kmx = 0.f;
        #pragma unroll
        for (int i = 0; i < 5; i++)
            #pragma unroll
            for (int j = 0; j < 5; j++) {
                float yv = -5.f + 2.5f*i;
                float xv = -5.f + 2.5f*j;
                float z = -0.5f*(i00*xv*xv + 2.f*i01*xv*yv + i11*yv*yv);
                float k = expf(z)*norm;
                kv[i*5+j] = k; kmx = fmaxf(kmx, k);
            }
        float im = 1.f/kmx;
        #pragma unroll
        for (int i = 0; i < 5; i++)
            #pragma unroll
            for (int j = 0; j < 5; j++)
                kpad[p2*196 + (i+4)*14 + (j+4)] = kv[i*5+j]*im;
    }
    __syncthreads();
    for (int idx = tid; idx < 49*196; idx += 256) {
        int p2 = idx/196, hw = idx%196, h = hw/14, w = hw%14;
        float txo = (0.5f - (float)(p2/7)*(1.f/7.f))*2.f;
        float tyo = (0.5f - (float)(p2%7)*(1.f/7.f))*2.f;
        float gxv = -1.f + (2.f/13.f)*w + txo;
        float gyv = -1.f + (2.f/13.f)*h + tyo;
        float px = (gxv + 1.f)*0.5f*13.f;
        float py = (gyv + 1.f)*0.5f*13.f;
        float x0f = floorf(px), y0f = floorf(py);
        int x0 = (int)x0f, y0 = (int)y0f;
        float wx = px - x0f, wy = py - y0f;
        float s00 = (y0   >= 0 && y0   < 14 && x0   >= 0 && x0   < 14) ? kpad[p2*196 + y0*14 + x0]       : 0.f;
        float s01 = (y0   >= 0 && y0   < 14 && x0+1 >= 0 && x0+1 < 14) ? kpad[p2*196 + y0*14 + x0+1]     : 0.f;
        float s10 = (y0+1 >= 0 && y0+1 < 14 && x0   >= 0 && x0   < 14) ? kpad[p2*196 + (y0+1)*14 + x0]   : 0.f;
        float s11 = (y0+1 >= 0 && y0+1 < 14 && x0+1 >= 0 && x0+1 < 14) ? kpad[p2*196 + (y0+1)*14 + x0+1] : 0.f;
        float kt = s00*(1.f-wy)*(1.f-wx) + s01*(1.f-wy)*wx + s10*wy*(1.f-wx) + s11*wy*wx;
        g_ktw[idx] = kt * wops[p2];
    }
}

// ------- splat -> NHWC fp16  (+ side job: pack conv224 weights fp16) ----------
#define SPLAT_SMEM ((49*196 + 49*64)*4)
__global__ void splat(const float* __restrict__ feat,
                      const float* __restrict__ wc, const float* __restrict__ wf) {
    extern __shared__ float sm[];
    float* kts = sm;
    float* fp  = sm + 49*196;
    int bl = blockIdx.x;
    int b = bl / 256; int l = bl % 256; int pr = l / 16, pc = l % 16;
    int tid = threadIdx.x;

    for (int i = bl*196 + tid; i < 294912; i += 1024*196) {
        int ci = i & 63; int t = i >> 6;
        int co = t & 127; t >>= 7;
        int dydx = t % 9; t /= 9;
        int half = t & 1; int sel = t >> 1;
        const float* W = sel ? wf : wc;
        float v = W[(size_t)(half*128 + co)*576 + ci*9 + dydx];
        size_t base = ((size_t)((sel*2 + half)*9 + dydx))*16384;
        uint32_t off = (uint32_t)co*128 + (((uint32_t)(ci>>3)*16) ^ (((uint32_t)co&7)<<4)) + (ci&7)*2;
        *(__half*)(g_cw + base + off) = __float2half(v);
    }

    for (int i = tid; i < 49*196; i += 196) kts[i] = g_ktw[i];
    const float* fb = feat + (size_t)b*64*HH*HH;
    for (int i = tid; i < 49*64; i += 196) {
        int p = i >> 6, c = i & 63;
        fp[i] = fb[((size_t)c*HH + pr*7 + p/7)*HH + pc*7 + p%7];
    }
    __syncthreads();
    int h = tid/14, w = tid%14;
    int oy = pr*14 + h, ox = pc*14 + w;
    size_t pixb = ((size_t)b*H2 + oy)*H2 + ox;
    __half* gh = g_gfh + pixb*64;
    #pragma unroll
    for (int half = 0; half < 2; half++) {
        float a[32];
        #pragma unroll
        for (int j = 0; j < 32; j++) a[j] = 0.f;
        for (int p = 0; p < 49; p++) {
            float k = kts[p*196 + tid];
            const float4* f4 = (const float4*)(fp + p*64 + half*32);
            #pragma unroll
            for (int j = 0; j < 8; j++) {
                float4 v = f4[j];
                a[j*4+0] += k*v.x; a[j*4+1] += k*v.y;
                a[j*4+2] += k*v.z; a[j*4+3] += k*v.w;
            }
        }
        #pragma unroll
        for (int j = 0; j < 32; j += 4) {
            int c0 = half*32 + j;
            *(__half2*)(gh + c0)     = __floats2half2_rn(__saturatef(a[j]),   __saturatef(a[j+1]));
            *(__half2*)(gh + c0 + 2) = __floats2half2_rn(__saturatef(a[j+2]), __saturatef(a[j+3]));
        }
    }
}

// ---------------- conv3x3 64->256 @224 via mma.sync (1-pass fp16 + ldmatrix) --
#define CM_WBASE 41472
#define CM_WBUF  16384
#define CM_SMEM  (41472 + 2*16384)

__global__ void __launch_bounds__(512, 1) conv224m(const float* __restrict__ bias_c,
                                                   const float* __restrict__ bias_f) {
    extern __shared__ __align__(16) char smc[];
    __shared__ float sbias[128];
    uint32_t sb;
    asm("{ .reg .u64 t; cvta.to.shared.u64 t, %1; cvt.u32.u64 %0, t; }" : "=r"(sb) : "l"(smc));
    int tid = threadIdx.x, wid = tid >> 5, lane = tid & 31;
    int bt = blockIdx.x, cohalf = blockIdx.y;
    int sel = blockIdx.z & 1, b = blockIdx.z >> 1;
    int row0 = (bt/14)*16, col0 = (bt%14)*16;
    int wm = wid >> 1, wn = wid & 1;
    int nb = wn*64;

    int lr8  = lane & 7;
    int a_mh = (lane >> 3) & 1;
    int a_jh = (lane >> 4) & 1;
    int b_jh = (lane >> 3) & 1;
    int b_nh = (lane >> 4) & 1;

    const __half* gh = g_gfh + (size_t)b*H2*H2*64;
    const unsigned char* wsrc = g_cw + (size_t)(sel*2 + cohalf)*9*16384;
    const float* bias = sel ? bias_f : bias_c;

    for (int i = tid; i < 1024; i += 512)
        cpa16(smc + CM_WBASE + i*16, wsrc + i*16);
    for (int i = tid; i < 2592; i += 512) {
        int pos = i >> 3, j = i & 7;
        int r = pos / 18, c = pos - r*18;
        int gy = row0 + r - 1, gx = col0 + c - 1;
        int ok = (gy >= 0 && gy < H2 && gx >= 0 && gx < H2);
        const __half* src = gh + ((size_t)(ok ? gy : 0)*H2 + (ok ? gx : 0))*64 + j*8;
        cpa16z(smc + (r*18 + c)*128 + (((uint32_t)j*16) ^ (((uint32_t)c&7)<<4)), src, ok ? 16 : 0);
    }
    asm volatile("cp.async.commit_group;" ::: "memory");
    if (tid < 128) sbias[tid] = bias[cohalf*128 + tid];

    float acc[2][8][4];
    #pragma unroll
    for (int t = 0; t < 2; t++)
        #pragma unroll
        for (int u = 0; u < 8; u++)
            #pragma unroll
            for (int j = 0; j < 4; j++) acc[t][u][j] = 0.f;

    uint32_t bRowOff = (uint32_t)((nb + b_nh*8 + lr8)*128);
    uint32_t swB = (uint32_t)(lr8 << 4);

    for (int dydx = 0; dydx < 9; dydx++) {
        if (dydx < 8) {
            const unsigned char* src = wsrc + (size_t)(dydx+1)*16384;
            char* dst = smc + CM_WBASE + ((dydx+1)&1)*CM_WBUF;
            for (int i = tid; i < 1024; i += 512)
                cpa16(dst + i*16, src + i*16);
            asm volatile("cp.async.commit_group;" ::: "memory");
            asm volatile("cp.async.wait_group 1;" ::: "memory");
        } else {
            asm volatile("cp.async.wait_group 0;" ::: "memory");
        }
        __syncthreads();

        int dy = dydx/3, dx = dydx - dy*3;
        uint32_t wb = sb + CM_WBASE + (uint32_t)((dydx&1)*CM_WBUF) + bRowOff;

        int cA = dx + lr8 + a_mh*8;
        uint32_t swA = (uint32_t)(((dx + lr8) & 7) << 4);
        uint32_t aBase0 = sb + (uint32_t)((((wm*2 + dy)*18 + cA))*128);
        uint32_t aBase1 = aBase0 + 18*128;

        #pragma unroll
        for (int ks = 0; ks < 4; ks++) {
            uint32_t ka = (uint32_t)(((ks*2 + a_jh)*16)) ^ swA;
            uint32_t a0[4], a1[4];
            ldsm4(a0[0], a0[1], a0[2], a0[3], aBase0 + ka);
            ldsm4(a1[0], a1[1], a1[2], a1[3], aBase1 + ka);
            uint32_t kb = (uint32_t)(((ks*2 + b_jh)*16)) ^ swB;
            #pragma unroll
            for (int up = 0; up < 4; up++) {
                uint32_t br[4];
                ldsm4(br[0], br[1], br[2], br[3], wb + (uint32_t)(up*2048) + kb);
                mma16816(acc[0][2*up],   a0[0], a0[1], a0[2], a0[3], br[0], br[1]);
                mma16816(acc[0][2*up+1], a0[0], a0[1], a0[2], a0[3], br[2], br[3]);
                mma16816(acc[1][2*up],   a1[0], a1[1], a1[2], a1[3], br[0], br[1]);
                mma16816(acc[1][2*up+1], a1[0], a1[1], a1[2], a1[3], br[2], br[3]);
            }
        }
        __syncthreads();
    }

    int egrp = lane >> 2, et4 = lane & 3;
    if (sel) {
        float* outp = g_freq;
        #pragma unroll
        for (int t = 0; t < 2; t++) {
            int gy = row0 + wm*2 + t;
            #pragma unroll
            for (int u = 0; u < 8; u++) {
                int cidx = nb + u*8 + et4*2;
                float b0 = sbias[cidx], b1 = sbias[cidx+1];
                size_t o0 = (((size_t)b*H2 + gy)*H2 + col0 + egrp)*256 + cohalf*128 + cidx;
                size_t o1 = o0 + (size_t)8*256;
                *(float2*)&outp[o0] = make_float2(acc[t][u][0] + b0, acc[t][u][1] + b1);
                *(float2*)&outp[o1] = make_float2(acc[t][u][2] + b0, acc[t][u][3] + b1);
            }
        }
    } else {
        __half* outp = g_coefh;
        #pragma unroll
        for (int t = 0; t < 2; t++) {
            int gy = row0 + wm*2 + t;
            #pragma unroll
            for (int u = 0; u < 8; u++) {
                int cidx = nb + u*8 + et4*2;
                float b0 = sbias[cidx], b1 = sbias[cidx+1];
                size_t o0 = (((size_t)b*H2 + gy)*H2 + col0 + egrp)*256 + cohalf*128 + cidx;
                size_t o1 = o0 + (size_t)8*256;
                *(__half2*)&outp[o0] = __floats2half2_rn(acc[t][u][0] + b0, acc[t][u][1] + b1);
                *(__half2*)&outp[o1] = __floats2half2_rn(acc[t][u][2] + b0, acc[t][u][3] + b1);
            }
        }
    }
}

// ---------------- gather + fourier basis -> X0 fp16 (+ zero out) --------------
__global__ void gather_basis(const float* __restrict__ coord,
                             const float* __restrict__ cell,
                             const float* __restrict__ phase_w,
                             float* __restrict__ outz) {
    int gid = blockIdx.x*256 + threadIdx.x;
    if (gid < MTOT*3) outz[gid] = 0.f;
    int warp = threadIdx.x / 32, lane = threadIdx.x % 32;
    int m = blockIdx.x * 8 + warp;
    int b = m / QQ; int q = m % QQ;
    float cy = coord[((size_t)b*QQ + q)*2 + 0];
    float cx = coord[((size_t)b*QQ + q)*2 + 1];
    int ix = (int)rintf(((cx + 1.f)*(float)H2 - 1.f)*0.5f);
    int iy = (int)rintf(((cy + 1.f)*(float)H2 - 1.f)*0.5f);
    bool ok = (ix >= 0 && ix < H2 && iy >= 0 && iy < H2);
    __half* xh = g_X0h + (size_t)m*HID;
    if (!ok) {
        __half z = __float2half(0.f);
        #pragma unroll
        for (int kk = 0; kk < 4; kk++) {
            int k = lane + kk*32;
            xh[k] = z; xh[128+k] = z;
        }
        return;
    }
    float fcy = -1.f + 1.f/(float)H2 + (2.f/(float)H2)*(float)iy;
    float fcx = -1.f + 1.f/(float)H2 + (2.f/(float)H2)*(float)ix;
    float rely = (cy - fcy)*(float)H2;
    float relx = (cx - fcx)*(float)H2;
    float rc0 = cell[((size_t)b*QQ + q)*2 + 0]*(float)H2;
    float rc1 = cell[((size_t)b*QQ + q)*2 + 1]*(float)H2;
    size_t base = (((size_t)b*H2 + iy)*H2 + ix)*HID;
    const __half*  cf = g_coefh + base;
    const float2* fq = (const float2*)(g_freq + base);
    const float2* pw = (const float2*)phase_w;
    const float PI = 3.14159265358979f;
    #pragma unroll
    for (int kk = 0; kk < 4; kk++) {
        int k = lane + kk*32;
        float2 f = fq[k];
        float2 p = pw[k];
        float s = (f.x*rely + f.y*relx + rc0*p.x + rc1*p.y) * PI;
        xh[k]     = __float2half(__half2float(cf[k])       * __cosf(s));
        xh[128+k] = __float2half(__half2float(cf[128 + k]) * __sinf(s));
    }
}

// ---------------- mma.sync fp16 GEMM (1-pass + ldmatrix) ----------------------
#define GM_BB 0
#define GM_AB 65536
#define GM_SMEM (65536 + 2*16384)

__global__ void __launch_bounds__(256, 1) gemm_mma(const float* __restrict__ bias, int layer,
                                                   const float* __restrict__ w3,
                                                   const float* __restrict__ b3,
                                                   float* __restrict__ out) {
    extern __shared__ __align__(16) char smc[];
    __shared__ float sbias[128];
    __shared__ float w3s[3*128];
    uint32_t sb;
    asm("{ .reg .u64 t; cvta.to.shared.u64 t, %1; cvt.u32.u64 %0, t; }" : "=r"(sb) : "l"(smc));
    int tid = threadIdx.x, wid = tid >> 5, lane = tid & 31;
    int m0 = blockIdx.x * 128;
    int n0 = blockIdx.y * 128;
    int wm = wid >> 1, wn = wid & 1;
    int mb = wm * 32, nb = wn * 64;

    int lr8  = lane & 7;
    int a_mh = (lane >> 3) & 1;
    int a_jh = (lane >> 4) & 1;
    int b_jh = (lane >> 3) & 1;
    int b_nh = (lane >> 4) & 1;

    const __half* Ah = layer ? g_X1h : g_X0h;
    const __half* Wh = g_Wh[layer];

    for (int i = tid; i < 4096; i += 256) {
        int n = i >> 5; int j = i & 31;
        const __half* src = Wh + (size_t)(n0 + n)*256 + j*8;
        cpa16(smc + GM_BB + n*512 + ((j*16) ^ ((n&7)<<4)), src);
    }
    for (int i = tid; i < 1024; i += 256) {
        int m = i >> 3; int j = i & 7;
        const __half* src = Ah + (size_t)(m0 + m)*256 + j*8;
        cpa16(smc + GM_AB + m*128 + ((j*16) ^ ((m&7)<<4)), src);
    }
    asm volatile("cp.async.commit_group;" ::: "memory");
    if (tid < 128) {
        sbias[tid] = bias[n0 + tid];
        if (layer) {
            w3s[tid]       = w3[0*256 + n0 + tid];
            w3s[128 + tid] = w3[1*256 + n0 + tid];
            w3s[256 + tid] = w3[2*256 + n0 + tid];
        }
    }

    float acc[2][8][4];
    #pragma unroll
    for (int t = 0; t < 2; t++)
        #pragma unroll
        for (int u = 0; u < 8; u++)
            #pragma unroll
            for (int j = 0; j < 4; j++) acc[t][u][j] = 0.f;

    uint32_t aRowOff = (uint32_t)((a_mh*8 + lr8)*128);
    uint32_t swA = (uint32_t)(lr8 << 4);
    uint32_t bRowOff = (uint32_t)((nb + b_nh*8 + lr8)*512);
    uint32_t swB = swA;
    uint32_t bB = sb + GM_BB + bRowOff;

    for (int c = 0; c < 4; c++) {
        if (c < 3) {
            int cn = c + 1;
            char* dstb = smc + GM_AB + (cn & 1)*16384;
            for (int i = tid; i < 1024; i += 256) {
                int m = i >> 3; int j = i & 7;
                const __half* src = Ah + (size_t)(m0 + m)*256 + cn*64 + j*8;
                cpa16(dstb + m*128 + ((j*16) ^ ((m&7)<<4)), src);
            }
            asm volatile("cp.async.commit_group;" ::: "memory");
            asm volatile("cp.async.wait_group 1;" ::: "memory");
        } else {
            asm volatile("cp.async.wait_group 0;" ::: "memory");
        }
        __syncthreads();

        uint32_t bA = sb + GM_AB + (c & 1)*16384 + aRowOff;
        #pragma unroll
        for (int ks = 0; ks < 4; ks++) {
            uint32_t ka = (uint32_t)(((ks*2 + a_jh)*16)) ^ swA;
            uint32_t a0[4], a1[4];
            ldsm4(a0[0], a0[1], a0[2], a0[3], bA + (uint32_t)(mb*128) + ka);
            ldsm4(a1[0], a1[1], a1[2], a1[3], bA + (uint32_t)((mb+16)*128) + ka);
            uint32_t kb = (uint32_t)(((c*8 + ks*2 + b_jh)*16)) ^ swB;
            #pragma unroll
            for (int up = 0; up < 4; up++) {
                uint32_t br[4];
                ldsm4(br[0], br[1], br[2], br[3], bB + (uint32_t)(up*8192) + kb);
                mma16816(acc[0][2*up],   a0[0], a0[1], a0[2], a0[3], br[0], br[1]);
                mma16816(acc[0][2*up+1], a0[0], a0[1], a0[2], a0[3], br[2], br[3]);
                mma16816(acc[1][2*up],   a1[0], a1[1], a1[2], a1[3], br[0], br[1]);
                mma16816(acc[1][2*up+1], a1[0], a1[1], a1[2], a1[3], br[2], br[3]);
            }
        }
        __syncthreads();
    }

    int grp = lane >> 2, t4 = lane & 3;
    if (layer == 0) {
        #pragma unroll
        for (int t = 0; t < 2; t++) {
            int r0 = m0 + mb + t*16 + grp;
            int r1 = r0 + 8;
            #pragma unroll
            for (int u = 0; u < 8; u++) {
                int cb = nb + u*8 + t4*2;
                float b0v = sbias[cb], b1v = sbias[cb+1];
                float v00 = fmaxf(acc[t][u][0] + b0v, 0.f);
                float v01 = fmaxf(acc[t][u][1] + b1v, 0.f);
                float v10 = fmaxf(acc[t][u][2] + b0v, 0.f);
                float v11 = fmaxf(acc[t][u][3] + b1v, 0.f);
                int gcol = n0 + cb;
                *(__half2*)&g_X1h[(size_t)r0*256 + gcol] = __floats2half2_rn(v00, v01);
                *(__half2*)&g_X1h[(size_t)r1*256 + gcol] = __floats2half2_rn(v10, v11);
            }
        }
    } else {
        #pragma unroll
        for (int t = 0; t < 2; t++) {
            int r0 = m0 + mb + t*16 + grp;
            int r1 = r0 + 8;
            float p0[3] = {0.f, 0.f, 0.f};
            float p1[3] = {0.f, 0.f, 0.f};
            #pragma unroll
            for (int u = 0; u < 8; u++) {
                int cb = nb + u*8 + t4*2;
                float b0v = sbias[cb], b1v = sbias[cb+1];
                float v00 = fmaxf(acc[t][u][0] + b0v, 0.f);
                float v01 = fmaxf(acc[t][u][1] + b1v, 0.f);
                float v10 = fmaxf(acc[t][u][2] + b0v, 0.f);
                float v11 = fmaxf(acc[t][u][3] + b1v, 0.f);
                #pragma unroll
                for (int cc = 0; cc < 3; cc++) {
                    float w0 = w3s[cc*128 + cb], w1 = w3s[cc*128 + cb + 1];
                    p0[cc] += v00*w0 + v01*w1;
                    p1[cc] += v10*w0 + v11*w1;
                }
            }
            #pragma unroll
            for (int cc = 0; cc < 3; cc++) {
                p0[cc] += __shfl_xor_sync(0xffffffffu, p0[cc], 1);
                p0[cc] += __shfl_xor_sync(0xffffffffu, p0[cc], 2);
                p1[cc] += __shfl_xor_sync(0xffffffffu, p1[cc], 1);
                p1[cc] += __shfl_xor_sync(0xffffffffu, p1[cc], 2);
            }
            if (t4 == 0) {
                #pragma unroll
                for (int cc = 0; cc < 3; cc++) {
                    float bb = (n0 == 0) ? b3[cc] : 0.f;
                    atomicAdd(&out[(size_t)r0*3 + cc], p0[cc] + bb);
                    atomicAdd(&out[(size_t)r1*3 + cc], p1[cc] + bb);
                }
            }
        }
    }
}

// ---------------- launch -------------------------------------------------------
extern "C" void kernel_launch(void* const* d_in, const int* in_sizes, int n_in,
                              void* d_out, int out_size) {
    const float* feat    = (const float*)d_in[0];
    const float* coord   = (const float*)d_in[1];
    const float* cell    = (const float*)d_in[2];
    const float* cls_w1  = (const float*)d_in[3];
    const float* cls_b1  = (const float*)d_in[4];
    const float* cls_w2  = (const float*)d_in[5];
    const float* cls_b2  = (const float*)d_in[6];
    const float* sigma_x = (const float*)d_in[7];
    const float* sigma_y = (const float*)d_in[8];
    const float* opacity = (const float*)d_in[9];
    const float* rho     = (const float*)d_in[10];
    const float* coef_w  = (const float*)d_in[11];
    const float* coef_b  = (const float*)d_in[12];
    const float* freq_w  = (const float*)d_in[13];
    const float* freq_b  = (const float*)d_in[14];
    const float* phase_w = (const float*)d_in[15];
    const float* mlp_w1  = (const float*)d_in[16];
    const float* mlp_b1  = (const float*)d_in[17];
    const float* mlp_w2  = (const float*)d_in[18];
    const float* mlp_b2  = (const float*)d_in[19];
    const float* mlp_w3  = (const float*)d_in[20];
    const float* mlp_b3  = (const float*)d_in[21];
    float* out = (float*)d_out;

    cudaFuncSetAttribute(conv112t, cudaFuncAttributeMaxDynamicSharedMemorySize, C1_SMEM);
    cudaFuncSetAttribute(splat,    cudaFuncAttributeMaxDynamicSharedMemorySize, SPLAT_SMEM);
    cudaFuncSetAttribute(conv224m, cudaFuncAttributeMaxDynamicSharedMemorySize, CM_SMEM);
    cudaFuncSetAttribute(gemm_mma, cudaFuncAttributeMaxDynamicSharedMemorySize, GM_SMEM);

    feat_prep<<<12544, 256>>>(feat, cls_w1, mlp_w1, mlp_w2);                       // #1
    conv112t<<<dim3(49, 1, BB), 512, C1_SMEM>>>(cls_b1);                           // #2
    logits_stats<<<196, 256>>>(cls_w2, cls_b2, sigma_x, sigma_y, opacity, rho);    // #3
    splat<<<1024, 196, SPLAT_SMEM>>>(feat, coef_w, freq_w);                        // #4
    conv224m<<<dim3(196, 2, BB*2), 512, CM_SMEM>>>(coef_b, freq_b);                // #5
    gather_basis<<<MTOT/8, 256>>>(coord, cell, phase_w, out);                      // #6
    gemm_mma<<<dim3(MTOT/128, 2), 256, GM_SMEM>>>(mlp_b1, 0, mlp_w3, mlp_b3, out); // #7
    gemm_mma<<<dim3(MTOT/128, 2), 256, GM_SMEM>>>(mlp_b2, 1, mlp_w3, mlp_b3, out); // #8
}